// round 6
// baseline (speedup 1.0000x reference)
#include <cuda_runtime.h>
#include <stdint.h>

#define NN 100000
#define EE 800000
#define NBLK_SCAN 98            // ceil(100000/1024)

typedef unsigned long long ull;

// ---------------- scratch (device globals; no allocation) ----------------
__device__ float    g_g[(size_t)NN * 128];    // mlp_inv(feat) per node
__device__ float    g_sum[(size_t)NN * 128];  // aggregated 128-wide sums
__device__ unsigned g_packed[EE];             // CSR edge payload: src | (r<<31)
__device__ int      g_deg[NN];
__device__ int      g_start[NN];
__device__ int      g_cursor[NN];
__device__ int      g_bsum[NBLK_SCAN];
__device__ int      g_boff[NBLK_SCAN];
__device__ int      g_list[NN];
__device__ int      g_cnt[1];

__device__ __forceinline__ float lrelu(float v) { return v >= 0.0f ? v : 0.01f * v; }

__device__ __forceinline__ void fma2(ull &d, ull a, ull b) {
    asm("fma.rn.f32x2 %0, %1, %2, %0;" : "+l"(d) : "l"(a), "l"(b));
}
__device__ __forceinline__ ull pack2(float lo, float hi) {
    ull r; asm("mov.b64 %0, {%1, %2};" : "=l"(r) : "f"(lo), "f"(hi)); return r;
}
__device__ __forceinline__ void unpack2(ull v, float &lo, float &hi) {
    asm("mov.b64 {%0, %1}, %2;" : "=f"(lo), "=f"(hi) : "l"(v));
}

// ---------------- smem layout (floats) ----------------
// W1d: 64 outs x 256 (dup K=128), W2d: 64 x 128 (dup 64), W3d: 128 x 128 (dup 64)
// x: 64 row-slots x 132 (ev rows at slot p, od rows at 32+p)  [u (64x68) reuses this]
// t: 64 row-slots x 68
#define OFF_W1 0
#define OFF_W2 16384
#define OFF_W3 24576
#define OFF_B1 40960
#define OFF_B2 41024
#define OFF_B3 41088
#define OFF_X  41216
#define OFF_T  49664
#define SMEM_FLOATS 54016        // 216064 bytes

// stage weights duplicated per k2: (w[2k2], w[2k2], w[2k2+1], w[2k2+1])
__device__ __forceinline__ void stage_wdup(float* s, const float* __restrict__ w,
                                           int OUT, int K, int tid) {
    int WS = 2 * K;
    for (int i = tid; i < OUT * K; i += 256) {
        int o = i / K, k = i - o * K;
        float v = w[i];
        int b = o * WS + (k >> 1) * 4 + (k & 1) * 2;
        s[b] = v; s[b + 1] = v;
    }
}

// fused 3-layer MLP on the staged 64-row tile; lane owns row pair (ev/od), warp owns outs
__device__ __forceinline__ void mlp3_tile(float* s, int warp, int lane,
                                          int r0, int r1, float* __restrict__ outp)
{
    const int o0 = warp * 8;
    // ---- L1: K=128 -> 64 ----
    ull acc[8];
    #pragma unroll
    for (int j = 0; j < 8; j++) { float b = s[OFF_B1 + o0 + j]; acc[j] = pack2(b, b); }
    {
        const float* evp = s + OFF_X + lane * 132;
        const float* odp = s + OFF_X + (32 + lane) * 132;
        #pragma unroll 4
        for (int kq = 0; kq < 32; kq++) {
            float4 ev = *(const float4*)(evp + 4 * kq);
            float4 od = *(const float4*)(odp + 4 * kq);
            ull x0 = pack2(ev.x, od.x), x1 = pack2(ev.y, od.y);
            ull x2 = pack2(ev.z, od.z), x3 = pack2(ev.w, od.w);
            #pragma unroll
            for (int j = 0; j < 8; j++) {
                const float* wp = s + OFF_W1 + (o0 + j) * 256 + kq * 8;
                ulonglong2 wa = *(const ulonglong2*)(wp);
                ulonglong2 wb = *(const ulonglong2*)(wp + 4);
                fma2(acc[j], x0, wa.x); fma2(acc[j], x1, wa.y);
                fma2(acc[j], x2, wb.x); fma2(acc[j], x3, wb.y);
            }
        }
    }
    {
        float e[8], o[8];
        #pragma unroll
        for (int j = 0; j < 8; j++) { float lo, hi; unpack2(acc[j], lo, hi); e[j] = lrelu(lo); o[j] = lrelu(hi); }
        float* tev = s + OFF_T + lane * 68 + o0;
        float* tod = s + OFF_T + (32 + lane) * 68 + o0;
        *(float4*)(tev)     = make_float4(e[0], e[1], e[2], e[3]);
        *(float4*)(tev + 4) = make_float4(e[4], e[5], e[6], e[7]);
        *(float4*)(tod)     = make_float4(o[0], o[1], o[2], o[3]);
        *(float4*)(tod + 4) = make_float4(o[4], o[5], o[6], o[7]);
    }
    __syncthreads();
    // ---- L2: 64 -> 64 ----
    ull acc2[8];
    #pragma unroll
    for (int j = 0; j < 8; j++) { float b = s[OFF_B2 + o0 + j]; acc2[j] = pack2(b, b); }
    {
        const float* evp = s + OFF_T + lane * 68;
        const float* odp = s + OFF_T + (32 + lane) * 68;
        #pragma unroll 4
        for (int kq = 0; kq < 16; kq++) {
            float4 ev = *(const float4*)(evp + 4 * kq);
            float4 od = *(const float4*)(odp + 4 * kq);
            ull x0 = pack2(ev.x, od.x), x1 = pack2(ev.y, od.y);
            ull x2 = pack2(ev.z, od.z), x3 = pack2(ev.w, od.w);
            #pragma unroll
            for (int j = 0; j < 8; j++) {
                const float* wp = s + OFF_W2 + (o0 + j) * 128 + kq * 8;
                ulonglong2 wa = *(const ulonglong2*)(wp);
                ulonglong2 wb = *(const ulonglong2*)(wp + 4);
                fma2(acc2[j], x0, wa.x); fma2(acc2[j], x1, wa.y);
                fma2(acc2[j], x2, wb.x); fma2(acc2[j], x3, wb.y);
            }
        }
    }
    {
        float e[8], o[8];
        #pragma unroll
        for (int j = 0; j < 8; j++) { float lo, hi; unpack2(acc2[j], lo, hi); e[j] = lrelu(lo); o[j] = lrelu(hi); }
        float* uev = s + OFF_X + lane * 68 + o0;       // u overwrites x region (x dead)
        float* uod = s + OFF_X + (32 + lane) * 68 + o0;
        *(float4*)(uev)     = make_float4(e[0], e[1], e[2], e[3]);
        *(float4*)(uev + 4) = make_float4(e[4], e[5], e[6], e[7]);
        *(float4*)(uod)     = make_float4(o[0], o[1], o[2], o[3]);
        *(float4*)(uod + 4) = make_float4(o[4], o[5], o[6], o[7]);
    }
    __syncthreads();
    // ---- L3: 64 -> 128 ----
    const int o1 = warp * 16;
    ull acc3[16];
    #pragma unroll
    for (int j = 0; j < 16; j++) { float b = s[OFF_B3 + o1 + j]; acc3[j] = pack2(b, b); }
    {
        const float* evp = s + OFF_X + lane * 68;
        const float* odp = s + OFF_X + (32 + lane) * 68;
        #pragma unroll 2
        for (int kq = 0; kq < 16; kq++) {
            float4 ev = *(const float4*)(evp + 4 * kq);
            float4 od = *(const float4*)(odp + 4 * kq);
            ull x0 = pack2(ev.x, od.x), x1 = pack2(ev.y, od.y);
            ull x2 = pack2(ev.z, od.z), x3 = pack2(ev.w, od.w);
            #pragma unroll
            for (int j = 0; j < 16; j++) {
                const float* wp = s + OFF_W3 + (o1 + j) * 128 + kq * 8;
                ulonglong2 wa = *(const ulonglong2*)(wp);
                ulonglong2 wb = *(const ulonglong2*)(wp + 4);
                fma2(acc3[j], x0, wa.x); fma2(acc3[j], x1, wa.y);
                fma2(acc3[j], x2, wb.x); fma2(acc3[j], x3, wb.y);
            }
        }
    }
    if (r0 >= 0) {
        float e[16];
        #pragma unroll
        for (int j = 0; j < 16; j++) { float lo, hi; unpack2(acc3[j], lo, hi); e[j] = lo; }
        float* op = outp + (size_t)r0 * 128 + o1;
        *(float4*)(op)      = make_float4(e[0], e[1], e[2], e[3]);
        *(float4*)(op + 4)  = make_float4(e[4], e[5], e[6], e[7]);
        *(float4*)(op + 8)  = make_float4(e[8], e[9], e[10], e[11]);
        *(float4*)(op + 12) = make_float4(e[12], e[13], e[14], e[15]);
    }
    if (r1 >= 0) {
        float o_[16];
        #pragma unroll
        for (int j = 0; j < 16; j++) { float lo, hi; unpack2(acc3[j], lo, hi); o_[j] = hi; }
        float* op = outp + (size_t)r1 * 128 + o1;
        *(float4*)(op)      = make_float4(o_[0], o_[1], o_[2], o_[3]);
        *(float4*)(op + 4)  = make_float4(o_[4], o_[5], o_[6], o_[7]);
        *(float4*)(op + 8)  = make_float4(o_[8], o_[9], o_[10], o_[11]);
        *(float4*)(op + 12) = make_float4(o_[12], o_[13], o_[14], o_[15]);
    }
    __syncthreads();   // X (u) and T reusable next tile
}

// ================= k_g: g = mlp_inv(feat) =================
__global__ void __launch_bounds__(256, 1) k_g(
    const float* __restrict__ feat,
    const float* __restrict__ iw1, const float* __restrict__ ib1,
    const float* __restrict__ iw2, const float* __restrict__ ib2,
    const float* __restrict__ iw3, const float* __restrict__ ib3,
    float* __restrict__ g)
{
    extern __shared__ float s[];
    const int tid = threadIdx.x;
    stage_wdup(s + OFF_W1, iw1, 64, 128, tid);
    stage_wdup(s + OFF_W2, iw2, 64, 64, tid);
    stage_wdup(s + OFF_W3, iw3, 128, 64, tid);
    for (int i = tid; i < 64;  i += 256) { s[OFF_B1 + i] = ib1[i]; s[OFF_B2 + i] = ib2[i]; }
    for (int i = tid; i < 128; i += 256) s[OFF_B3 + i] = ib3[i];
    __syncthreads();

    const int warp = tid >> 5, lane = tid & 31;
    const int ntiles = (NN + 63) / 64;
    for (int tile = blockIdx.x; tile < ntiles; tile += gridDim.x) {
        int base = tile * 64;
        for (int idx = tid; idx < 64 * 32; idx += 256) {
            int j = idx >> 5, q = idx & 31;
            int row = base + j; if (row >= NN) row = NN - 1;
            float4 v = *(const float4*)(feat + (size_t)row * 128 + 4 * q);
            int slot = (j & 1) ? 32 + (j >> 1) : (j >> 1);
            *(float4*)(s + OFF_X + slot * 132 + 4 * q) = v;
        }
        __syncthreads();
        int r0 = base + 2 * lane;     if (r0 >= NN) r0 = -1;
        int r1 = base + 2 * lane + 1; if (r1 >= NN) r1 = -1;
        mlp3_tile(s, warp, lane, r0, r1, g);
    }
}

// ================= CSR build =================
__global__ void k_hist(const int* __restrict__ dst, int* __restrict__ deg) {
    int i = blockIdx.x * 1024 + threadIdx.x;
    if (i < EE) atomicAdd(&deg[dst[i]], 1);
}

__global__ void k_scanA(const int* __restrict__ deg, int* __restrict__ bsum) {
    __shared__ int ws[32];
    int i = blockIdx.x * 1024 + threadIdx.x;
    int v = (i < NN) ? deg[i] : 0;
    #pragma unroll
    for (int d = 16; d > 0; d >>= 1) v += __shfl_down_sync(~0u, v, d);
    int lane = threadIdx.x & 31, wid = threadIdx.x >> 5;
    if (lane == 0) ws[wid] = v;
    __syncthreads();
    if (wid == 0) {
        int t = ws[lane];
        #pragma unroll
        for (int d = 16; d > 0; d >>= 1) t += __shfl_down_sync(~0u, t, d);
        if (lane == 0) bsum[blockIdx.x] = t;
    }
}

__global__ void k_scanB(const int* __restrict__ bsum, int* __restrict__ boff) {
    __shared__ int s[128];
    int t = threadIdx.x;
    int v = (t < NBLK_SCAN) ? bsum[t] : 0;
    s[t] = v;
    __syncthreads();
    for (int d = 1; d < 128; d <<= 1) {
        int x = (t >= d) ? s[t - d] : 0;
        __syncthreads();
        s[t] += x;
        __syncthreads();
    }
    if (t < NBLK_SCAN) boff[t] = s[t] - v;   // exclusive
}

__global__ void k_scanC(const int* __restrict__ deg, const int* __restrict__ boff,
                        int* __restrict__ start, int* __restrict__ cursor) {
    __shared__ int ws[32];
    int i = blockIdx.x * 1024 + threadIdx.x;
    int lane = threadIdx.x & 31, wid = threadIdx.x >> 5;
    int v = (i < NN) ? deg[i] : 0;
    int incl = v;
    #pragma unroll
    for (int d = 1; d < 32; d <<= 1) {
        int n = __shfl_up_sync(~0u, incl, d);
        if (lane >= d) incl += n;
    }
    if (lane == 31) ws[wid] = incl;
    __syncthreads();
    if (wid == 0) {
        int wv = ws[lane];
        int wi = wv;
        #pragma unroll
        for (int d = 1; d < 32; d <<= 1) {
            int n = __shfl_up_sync(~0u, wi, d);
            if (lane >= d) wi += n;
        }
        ws[lane] = wi - wv;
    }
    __syncthreads();
    int excl = incl - v + ws[wid] + boff[blockIdx.x];
    if (i < NN) { start[i] = excl; cursor[i] = excl; }
}

__global__ void k_fill(const int* __restrict__ src, const int* __restrict__ dst,
                       const int* __restrict__ r, int* __restrict__ cursor,
                       unsigned* __restrict__ packed) {
    int i = blockIdx.x * 1024 + threadIdx.x;
    if (i >= EE) return;
    int d = dst[i];
    int pos = atomicAdd(&cursor[d], 1);
    packed[pos] = (unsigned)src[i] | ((unsigned)r[i] << 31);
}

__global__ void k_compact(const int* __restrict__ inv, int* __restrict__ list,
                          int* __restrict__ cnt) {
    int i = blockIdx.x * 1024 + threadIdx.x;
    if (i < NN && inv[i] == 1) {
        int pos = atomicAdd(cnt, 1);
        list[pos] = i;
    }
}

// ================= k_gather: warp per node, 128-wide sums =================
__global__ void k_gather(const float* __restrict__ feat, const float* __restrict__ g,
                         const unsigned* __restrict__ packed,
                         const int* __restrict__ start, const int* __restrict__ deg,
                         float* __restrict__ sum) {
    int w = (blockIdx.x * blockDim.x + threadIdx.x) >> 5;
    int lane = threadIdx.x & 31;
    if (w >= NN) return;
    int s0 = start[w];
    int e = s0 + deg[w];
    float4 acc = make_float4(0.f, 0.f, 0.f, 0.f);
    for (int j = s0; j < e; j++) {
        unsigned v = __ldg(&packed[j]);
        const float* rp = ((v >> 31) ? g : feat) + (size_t)(v & 0x7FFFFFFFu) * 128;
        float4 x = *(const float4*)(rp + 4 * lane);
        acc.x += x.x; acc.y += x.y; acc.z += x.z; acc.w += x.w;
    }
    *(float4*)(sum + (size_t)w * 128 + 4 * lane) = acc;
}

// ================= k_node: mean -> and-mlp -> out =================
__global__ void __launch_bounds__(256, 1) k_node(
    const float* __restrict__ sum, const int* __restrict__ deg,
    const float* __restrict__ aw1, const float* __restrict__ ab1,
    const float* __restrict__ aw2, const float* __restrict__ ab2,
    const float* __restrict__ aw3, const float* __restrict__ ab3,
    float* __restrict__ out)
{
    extern __shared__ float s[];
    const int tid = threadIdx.x;
    stage_wdup(s + OFF_W1, aw1, 64, 128, tid);
    stage_wdup(s + OFF_W2, aw2, 64, 64, tid);
    stage_wdup(s + OFF_W3, aw3, 128, 64, tid);
    for (int i = tid; i < 64;  i += 256) { s[OFF_B1 + i] = ab1[i]; s[OFF_B2 + i] = ab2[i]; }
    for (int i = tid; i < 128; i += 256) s[OFF_B3 + i] = ab3[i];
    __syncthreads();

    const int warp = tid >> 5, lane = tid & 31;
    const int ntiles = (NN + 63) / 64;
    for (int tile = blockIdx.x; tile < ntiles; tile += gridDim.x) {
        int base = tile * 64;
        for (int idx = tid; idx < 64 * 32; idx += 256) {
            int j = idx >> 5, q = idx & 31;
            int row = base + j; if (row >= NN) row = NN - 1;
            int dg = deg[row];
            float sc = 1.0f / (float)(dg < 1 ? 1 : dg);
            float4 v = *(const float4*)(sum + (size_t)row * 128 + 4 * q);
            v.x *= sc; v.y *= sc; v.z *= sc; v.w *= sc;
            int slot = (j & 1) ? 32 + (j >> 1) : (j >> 1);
            *(float4*)(s + OFF_X + slot * 132 + 4 * q) = v;
        }
        __syncthreads();
        int r0 = base + 2 * lane;     if (r0 >= NN) r0 = -1;
        int r1 = base + 2 * lane + 1; if (r1 >= NN) r1 = -1;
        mlp3_tile(s, warp, lane, r0, r1, out);
    }
}

// ================= k_inv: mlp_inv on compacted rows (in-place on out) =================
__global__ void __launch_bounds__(256, 1) k_inv(
    const float* __restrict__ iw1, const float* __restrict__ ib1,
    const float* __restrict__ iw2, const float* __restrict__ ib2,
    const float* __restrict__ iw3, const float* __restrict__ ib3,
    const int* __restrict__ list, const int* __restrict__ cnt,
    float* __restrict__ out)
{
    extern __shared__ float s[];
    const int tid = threadIdx.x;
    stage_wdup(s + OFF_W1, iw1, 64, 128, tid);
    stage_wdup(s + OFF_W2, iw2, 64, 64, tid);
    stage_wdup(s + OFF_W3, iw3, 128, 64, tid);
    for (int i = tid; i < 64;  i += 256) { s[OFF_B1 + i] = ib1[i]; s[OFF_B2 + i] = ib2[i]; }
    for (int i = tid; i < 128; i += 256) s[OFF_B3 + i] = ib3[i];
    __syncthreads();
    const int total = *cnt;

    const int warp = tid >> 5, lane = tid & 31;
    const int ntiles = (total + 63) / 64;
    for (int tile = blockIdx.x; tile < ntiles; tile += gridDim.x) {
        int base = tile * 64;
        for (int idx = tid; idx < 64 * 32; idx += 256) {
            int j = idx >> 5, q = idx & 31;
            int li = base + j;
            int row = (li < total) ? list[li] : list[total - 1];
            float4 v = *(const float4*)(out + (size_t)row * 128 + 4 * q);
            int slot = (j & 1) ? 32 + (j >> 1) : (j >> 1);
            *(float4*)(s + OFF_X + slot * 132 + 4 * q) = v;
        }
        __syncthreads();
        int i0 = base + 2 * lane, i1 = i0 + 1;
        int r0 = (i0 < total) ? list[i0] : -1;
        int r1 = (i1 < total) ? list[i1] : -1;
        mlp3_tile(s, warp, lane, r0, r1, out);
    }
}

// ================= host =================
extern "C" void kernel_launch(void* const* d_in, const int* in_sizes, int n_in,
                              void* d_out, int out_size)
{
    const float* feat = (const float*)d_in[0];
    const int*   src  = (const int*)d_in[1];
    const int*   dst  = (const int*)d_in[2];
    const int*   r    = (const int*)d_in[3];
    const int*   inv  = (const int*)d_in[4];
    const float* iw1 = (const float*)d_in[5];
    const float* ib1 = (const float*)d_in[6];
    const float* iw2 = (const float*)d_in[7];
    const float* ib2 = (const float*)d_in[8];
    const float* iw3 = (const float*)d_in[9];
    const float* ib3 = (const float*)d_in[10];
    const float* aw1 = (const float*)d_in[11];
    const float* ab1 = (const float*)d_in[12];
    const float* aw2 = (const float*)d_in[13];
    const float* ab2 = (const float*)d_in[14];
    const float* aw3 = (const float*)d_in[15];
    const float* ab3 = (const float*)d_in[16];
    float* out = (float*)d_out;

    float *g, *sum;
    unsigned* packed;
    int *deg, *start, *cursor, *bsum, *boff, *list, *cnt;
    cudaGetSymbolAddress((void**)&g, g_g);
    cudaGetSymbolAddress((void**)&sum, g_sum);
    cudaGetSymbolAddress((void**)&packed, g_packed);
    cudaGetSymbolAddress((void**)&deg, g_deg);
    cudaGetSymbolAddress((void**)&start, g_start);
    cudaGetSymbolAddress((void**)&cursor, g_cursor);
    cudaGetSymbolAddress((void**)&bsum, g_bsum);
    cudaGetSymbolAddress((void**)&boff, g_boff);
    cudaGetSymbolAddress((void**)&list, g_list);
    cudaGetSymbolAddress((void**)&cnt, g_cnt);

    const size_t smem = SMEM_FLOATS * sizeof(float);
    cudaFuncSetAttribute(k_g,    cudaFuncAttributeMaxDynamicSharedMemorySize, (int)smem);
    cudaFuncSetAttribute(k_node, cudaFuncAttributeMaxDynamicSharedMemorySize, (int)smem);
    cudaFuncSetAttribute(k_inv,  cudaFuncAttributeMaxDynamicSharedMemorySize, (int)smem);

    cudaMemsetAsync(deg, 0, NN * sizeof(int));                        // launch 0
    cudaMemsetAsync(cnt, 0, sizeof(int));                             // launch 1

    k_hist<<<(EE + 1023) / 1024, 1024>>>(dst, deg);                   // 2
    k_scanA<<<NBLK_SCAN, 1024>>>(deg, bsum);                          // 3
    k_scanB<<<1, 128>>>(bsum, boff);                                  // 4
    k_g<<<148, 256, smem>>>(feat, iw1, ib1, iw2, ib2, iw3, ib3, g);   // 5  <- ncu -s 5 lands here
    k_scanC<<<NBLK_SCAN, 1024>>>(deg, boff, start, cursor);           // 6
    k_fill<<<(EE + 1023) / 1024, 1024>>>(src, dst, r, cursor, packed);// 7
    k_compact<<<NBLK_SCAN, 1024>>>(inv, list, cnt);                   // 8
    k_gather<<<(NN * 32 + 255) / 256, 256>>>(feat, g, packed, start, deg, sum); // 9
    k_node<<<148, 256, smem>>>(sum, deg, aw1, ab1, aw2, ab2, aw3, ab3, out);    // 10
    k_inv<<<148, 256, smem>>>(iw1, ib1, iw2, ib2, iw3, ib3, list, cnt, out);    // 11
}

// round 7
// speedup vs baseline: 1.4642x; 1.4642x over previous
#include <cuda_runtime.h>
#include <stdint.h>

#define NN 100000
#define EE 800000
#define NBLK_SCAN 98            // ceil(100000/1024)

typedef unsigned long long ull;

// ---------------- scratch (device globals; no allocation) ----------------
__device__ float    g_g[(size_t)NN * 128];    // mlp_inv(feat) per node
__device__ float    g_sum[(size_t)NN * 128];  // aggregated 128-wide sums
__device__ unsigned g_packed[EE];             // CSR edge payload: src | (r<<31)
__device__ int      g_deg[NN];
__device__ int      g_start[NN];
__device__ int      g_cursor[NN];
__device__ int      g_bsum[NBLK_SCAN];
__device__ int      g_boff[NBLK_SCAN];
__device__ int      g_list[NN];
__device__ int      g_cnt[1];

__device__ __forceinline__ float lrelu(float v) { return v >= 0.0f ? v : 0.01f * v; }

__device__ __forceinline__ void fma2(ull &d, ull a, ull b) {
    asm("fma.rn.f32x2 %0, %1, %2, %0;" : "+l"(d) : "l"(a), "l"(b));
}
__device__ __forceinline__ ull pack2(float lo, float hi) {
    ull r; asm("mov.b64 %0, {%1, %2};" : "=l"(r) : "f"(lo), "f"(hi)); return r;
}
__device__ __forceinline__ void unpack2(ull v, float &lo, float &hi) {
    asm("mov.b64 {%0, %1}, %2;" : "=f"(lo), "=f"(hi) : "l"(v));
}
__device__ __forceinline__ float hadd2(ull v) {
    float lo, hi; unpack2(v, lo, hi); return lo + hi;
}

// ---------------- smem layout (floats) — no weight duplication ----------------
// W1: 64 x 132 (K=128 pad 4), W2: 64 x 68, W3: 128 x 68
#define OFF_W1 0
#define OFF_W2 8448
#define OFF_W3 12800
#define OFF_B1 21504
#define OFF_B2 21568
#define OFF_B3 21632
#define OFF_X  21760            // 12 warps x 2048 floats (16 rows x 128)
#define OFF_RID 46336           // 192 ints
#define SMEM_FLOATS 46528       // 186112 bytes
#define NWARP 12
#define NTHR  384
#define ROWS_PER_WARP 16
#define TILE_ROWS (NWARP * ROWS_PER_WARP)   // 192

__device__ __forceinline__ void stage_weights(float* s,
    const float* __restrict__ w1, const float* __restrict__ b1,
    const float* __restrict__ w2, const float* __restrict__ b2,
    const float* __restrict__ w3, const float* __restrict__ b3, int tid)
{
    for (int i = tid; i < 64 * 128; i += NTHR) s[OFF_W1 + (i >> 7) * 132 + (i & 127)] = w1[i];
    for (int i = tid; i < 64 * 64;  i += NTHR) s[OFF_W2 + (i >> 6) * 68 + (i & 63)] = w2[i];
    for (int i = tid; i < 128 * 64; i += NTHR) s[OFF_W3 + (i >> 6) * 68 + (i & 63)] = w3[i];
    for (int i = tid; i < 64;  i += NTHR) { s[OFF_B1 + i] = b1[i]; s[OFF_B2 + i] = b2[i]; }
    for (int i = tid; i < 128; i += NTHR) s[OFF_B3 + i] = b3[i];
}

// fused 3-layer MLP for one warp's private 16-row tile (dual-K packed f32x2).
// xs: 16 rows x 128 floats (contiguous). rid: 16 row ids (-1 = skip store).
__device__ __forceinline__ void mlp3_warp(const float* __restrict__ s, float* __restrict__ xs,
                                          const int* __restrict__ rid, int lane,
                                          float* __restrict__ outp)
{
    // ---- L1: K=128 -> 64 (lane owns outs lane, lane+32) ----
    ull a1[ROWS_PER_WARP][2];
    {
        ull b0 = pack2(s[OFF_B1 + lane], 0.0f);
        ull b1v = pack2(s[OFF_B1 + lane + 32], 0.0f);
        #pragma unroll
        for (int j = 0; j < ROWS_PER_WARP; j++) { a1[j][0] = b0; a1[j][1] = b1v; }
        const float* w0p = s + OFF_W1 + lane * 132;
        const float* w1p = s + OFF_W1 + (lane + 32) * 132;
        #pragma unroll 2
        for (int kq = 0; kq < 32; kq++) {
            ulonglong2 w0 = *(const ulonglong2*)(w0p + 4 * kq);
            ulonglong2 w1 = *(const ulonglong2*)(w1p + 4 * kq);
            #pragma unroll
            for (int j = 0; j < ROWS_PER_WARP; j++) {
                ulonglong2 xv = *(const ulonglong2*)(xs + j * 128 + 4 * kq);  // broadcast
                fma2(a1[j][0], xv.x, w0.x); fma2(a1[j][0], xv.y, w0.y);
                fma2(a1[j][1], xv.x, w1.x); fma2(a1[j][1], xv.y, w1.y);
            }
        }
    }
    __syncwarp();   // all lanes done reading xs
    #pragma unroll
    for (int j = 0; j < ROWS_PER_WARP; j++) {
        xs[j * 64 + lane]      = lrelu(hadd2(a1[j][0]));   // t overlays xs[0:1024]
        xs[j * 64 + lane + 32] = lrelu(hadd2(a1[j][1]));
    }
    __syncwarp();

    // ---- L2: 64 -> 64 ----
    ull a2[ROWS_PER_WARP][2];
    {
        ull b0 = pack2(s[OFF_B2 + lane], 0.0f);
        ull b1v = pack2(s[OFF_B2 + lane + 32], 0.0f);
        #pragma unroll
        for (int j = 0; j < ROWS_PER_WARP; j++) { a2[j][0] = b0; a2[j][1] = b1v; }
        const float* w0p = s + OFF_W2 + lane * 68;
        const float* w1p = s + OFF_W2 + (lane + 32) * 68;
        #pragma unroll 2
        for (int kq = 0; kq < 16; kq++) {
            ulonglong2 w0 = *(const ulonglong2*)(w0p + 4 * kq);
            ulonglong2 w1 = *(const ulonglong2*)(w1p + 4 * kq);
            #pragma unroll
            for (int j = 0; j < ROWS_PER_WARP; j++) {
                ulonglong2 xv = *(const ulonglong2*)(xs + j * 64 + 4 * kq);
                fma2(a2[j][0], xv.x, w0.x); fma2(a2[j][0], xv.y, w0.y);
                fma2(a2[j][1], xv.x, w1.x); fma2(a2[j][1], xv.y, w1.y);
            }
        }
    }
    __syncwarp();
    float* us = xs + 1024;      // u in xs[1024:2048] (x dead, t still live in [0:1024])
    #pragma unroll
    for (int j = 0; j < ROWS_PER_WARP; j++) {
        us[j * 64 + lane]      = lrelu(hadd2(a2[j][0]));
        us[j * 64 + lane + 32] = lrelu(hadd2(a2[j][1]));
    }
    __syncwarp();

    // ---- L3: 64 -> 128, two half-passes of 8 rows (reg pressure) ----
    #pragma unroll
    for (int h = 0; h < 2; h++) {
        ull a3[8][4];
        {
            ull b0 = pack2(s[OFF_B3 + lane], 0.0f);
            ull b1v = pack2(s[OFF_B3 + lane + 32], 0.0f);
            ull b2v = pack2(s[OFF_B3 + lane + 64], 0.0f);
            ull b3v = pack2(s[OFF_B3 + lane + 96], 0.0f);
            #pragma unroll
            for (int j = 0; j < 8; j++) { a3[j][0] = b0; a3[j][1] = b1v; a3[j][2] = b2v; a3[j][3] = b3v; }
            const float* w0p = s + OFF_W3 + lane * 68;
            const float* w1p = s + OFF_W3 + (lane + 32) * 68;
            const float* w2p = s + OFF_W3 + (lane + 64) * 68;
            const float* w3p = s + OFF_W3 + (lane + 96) * 68;
            #pragma unroll 2
            for (int kq = 0; kq < 16; kq++) {
                ulonglong2 w0 = *(const ulonglong2*)(w0p + 4 * kq);
                ulonglong2 w1 = *(const ulonglong2*)(w1p + 4 * kq);
                ulonglong2 w2 = *(const ulonglong2*)(w2p + 4 * kq);
                ulonglong2 w3 = *(const ulonglong2*)(w3p + 4 * kq);
                #pragma unroll
                for (int j = 0; j < 8; j++) {
                    ulonglong2 xv = *(const ulonglong2*)(us + (h * 8 + j) * 64 + 4 * kq);
                    fma2(a3[j][0], xv.x, w0.x); fma2(a3[j][0], xv.y, w0.y);
                    fma2(a3[j][1], xv.x, w1.x); fma2(a3[j][1], xv.y, w1.y);
                    fma2(a3[j][2], xv.x, w2.x); fma2(a3[j][2], xv.y, w2.y);
                    fma2(a3[j][3], xv.x, w3.x); fma2(a3[j][3], xv.y, w3.y);
                }
            }
        }
        #pragma unroll
        for (int j = 0; j < 8; j++) {
            int rowid = rid[h * 8 + j];
            if (rowid >= 0) {
                float* op = outp + (size_t)rowid * 128;
                op[lane]      = hadd2(a3[j][0]);
                op[lane + 32] = hadd2(a3[j][1]);
                op[lane + 64] = hadd2(a3[j][2]);
                op[lane + 96] = hadd2(a3[j][3]);
            }
        }
    }
}

// ================= k_g: g = mlp_inv(feat) =================
__global__ void __launch_bounds__(NTHR, 1) k_g(
    const float* __restrict__ feat,
    const float* __restrict__ iw1, const float* __restrict__ ib1,
    const float* __restrict__ iw2, const float* __restrict__ ib2,
    const float* __restrict__ iw3, const float* __restrict__ ib3,
    float* __restrict__ g)
{
    extern __shared__ float s[];
    const int tid = threadIdx.x;
    stage_weights(s, iw1, ib1, iw2, ib2, iw3, ib3, tid);
    int* rid = (int*)(s + OFF_RID);
    const int warp = tid >> 5, lane = tid & 31;
    const int nt = (NN + TILE_ROWS - 1) / TILE_ROWS;
    for (int tile = blockIdx.x; tile < nt; tile += gridDim.x) {
        int base = tile * TILE_ROWS;
        __syncthreads();                       // prev tile fully consumed
        for (int idx = tid; idx < TILE_ROWS * 32; idx += NTHR) {
            int j = idx >> 5, q = idx & 31;
            int row = base + j;
            int rowc = row < NN ? row : NN - 1;
            float4 v = *(const float4*)(feat + (size_t)rowc * 128 + 4 * q);
            *(float4*)(s + OFF_X + j * 128 + 4 * q) = v;
            if (q == 0) rid[j] = (row < NN) ? row : -1;
        }
        __syncthreads();
        mlp3_warp(s, s + OFF_X + warp * 2048, rid + warp * ROWS_PER_WARP, lane, g);
    }
}

// ================= CSR build =================
__global__ void k_hist(const int* __restrict__ dst, int* __restrict__ deg) {
    int i = blockIdx.x * 1024 + threadIdx.x;
    if (i < EE) atomicAdd(&deg[dst[i]], 1);
}

__global__ void k_scanA(const int* __restrict__ deg, int* __restrict__ bsum) {
    __shared__ int ws[32];
    int i = blockIdx.x * 1024 + threadIdx.x;
    int v = (i < NN) ? deg[i] : 0;
    #pragma unroll
    for (int d = 16; d > 0; d >>= 1) v += __shfl_down_sync(~0u, v, d);
    int lane = threadIdx.x & 31, wid = threadIdx.x >> 5;
    if (lane == 0) ws[wid] = v;
    __syncthreads();
    if (wid == 0) {
        int t = ws[lane];
        #pragma unroll
        for (int d = 16; d > 0; d >>= 1) t += __shfl_down_sync(~0u, t, d);
        if (lane == 0) bsum[blockIdx.x] = t;
    }
}

__global__ void k_scanB(const int* __restrict__ bsum, int* __restrict__ boff) {
    __shared__ int s[128];
    int t = threadIdx.x;
    int v = (t < NBLK_SCAN) ? bsum[t] : 0;
    s[t] = v;
    __syncthreads();
    for (int d = 1; d < 128; d <<= 1) {
        int x = (t >= d) ? s[t - d] : 0;
        __syncthreads();
        s[t] += x;
        __syncthreads();
    }
    if (t < NBLK_SCAN) boff[t] = s[t] - v;   // exclusive
}

__global__ void k_scanC(const int* __restrict__ deg, const int* __restrict__ boff,
                        int* __restrict__ start, int* __restrict__ cursor) {
    __shared__ int ws[32];
    int i = blockIdx.x * 1024 + threadIdx.x;
    int lane = threadIdx.x & 31, wid = threadIdx.x >> 5;
    int v = (i < NN) ? deg[i] : 0;
    int incl = v;
    #pragma unroll
    for (int d = 1; d < 32; d <<= 1) {
        int n = __shfl_up_sync(~0u, incl, d);
        if (lane >= d) incl += n;
    }
    if (lane == 31) ws[wid] = incl;
    __syncthreads();
    if (wid == 0) {
        int wv = ws[lane];
        int wi = wv;
        #pragma unroll
        for (int d = 1; d < 32; d <<= 1) {
            int n = __shfl_up_sync(~0u, wi, d);
            if (lane >= d) wi += n;
        }
        ws[lane] = wi - wv;
    }
    __syncthreads();
    int excl = incl - v + ws[wid] + boff[blockIdx.x];
    if (i < NN) { start[i] = excl; cursor[i] = excl; }
}

__global__ void k_fill(const int* __restrict__ src, const int* __restrict__ dst,
                       const int* __restrict__ r, int* __restrict__ cursor,
                       unsigned* __restrict__ packed) {
    int i = blockIdx.x * 1024 + threadIdx.x;
    if (i >= EE) return;
    int d = dst[i];
    int pos = atomicAdd(&cursor[d], 1);
    packed[pos] = (unsigned)src[i] | ((unsigned)r[i] << 31);
}

__global__ void k_compact(const int* __restrict__ inv, int* __restrict__ list,
                          int* __restrict__ cnt) {
    int i = blockIdx.x * 1024 + threadIdx.x;
    if (i < NN && inv[i] == 1) {
        int pos = atomicAdd(cnt, 1);
        list[pos] = i;
    }
}

// ================= k_gather: warp per node, 128-wide sums =================
__global__ void k_gather(const float* __restrict__ feat, const float* __restrict__ g,
                         const unsigned* __restrict__ packed,
                         const int* __restrict__ start, const int* __restrict__ deg,
                         float* __restrict__ sum) {
    int w = (blockIdx.x * blockDim.x + threadIdx.x) >> 5;
    int lane = threadIdx.x & 31;
    if (w >= NN) return;
    int s0 = start[w];
    int e = s0 + deg[w];
    float4 acc = make_float4(0.f, 0.f, 0.f, 0.f);
    for (int j = s0; j < e; j++) {
        unsigned v = __ldg(&packed[j]);
        const float* rp = ((v >> 31) ? g : feat) + (size_t)(v & 0x7FFFFFFFu) * 128;
        float4 x = *(const float4*)(rp + 4 * lane);
        acc.x += x.x; acc.y += x.y; acc.z += x.z; acc.w += x.w;
    }
    *(float4*)(sum + (size_t)w * 128 + 4 * lane) = acc;
}

// ================= k_node: mean -> and-mlp -> out =================
__global__ void __launch_bounds__(NTHR, 1) k_node(
    const float* __restrict__ sum, const int* __restrict__ deg,
    const float* __restrict__ aw1, const float* __restrict__ ab1,
    const float* __restrict__ aw2, const float* __restrict__ ab2,
    const float* __restrict__ aw3, const float* __restrict__ ab3,
    float* __restrict__ out)
{
    extern __shared__ float s[];
    const int tid = threadIdx.x;
    stage_weights(s, aw1, ab1, aw2, ab2, aw3, ab3, tid);
    int* rid = (int*)(s + OFF_RID);
    const int warp = tid >> 5, lane = tid & 31;
    const int nt = (NN + TILE_ROWS - 1) / TILE_ROWS;
    for (int tile = blockIdx.x; tile < nt; tile += gridDim.x) {
        int base = tile * TILE_ROWS;
        __syncthreads();
        for (int idx = tid; idx < TILE_ROWS * 32; idx += NTHR) {
            int j = idx >> 5, q = idx & 31;
            int row = base + j;
            int rowc = row < NN ? row : NN - 1;
            int dg = deg[rowc];
            float sc = 1.0f / (float)(dg < 1 ? 1 : dg);
            float4 v = *(const float4*)(sum + (size_t)rowc * 128 + 4 * q);
            v.x *= sc; v.y *= sc; v.z *= sc; v.w *= sc;
            *(float4*)(s + OFF_X + j * 128 + 4 * q) = v;
            if (q == 0) rid[j] = (row < NN) ? row : -1;
        }
        __syncthreads();
        mlp3_warp(s, s + OFF_X + warp * 2048, rid + warp * ROWS_PER_WARP, lane, out);
    }
}

// ================= k_inv: mlp_inv on compacted rows (in-place on out) =================
__global__ void __launch_bounds__(NTHR, 1) k_inv(
    const float* __restrict__ iw1, const float* __restrict__ ib1,
    const float* __restrict__ iw2, const float* __restrict__ ib2,
    const float* __restrict__ iw3, const float* __restrict__ ib3,
    const int* __restrict__ list, const int* __restrict__ cnt,
    float* __restrict__ out)
{
    extern __shared__ float s[];
    const int tid = threadIdx.x;
    stage_weights(s, iw1, ib1, iw2, ib2, iw3, ib3, tid);
    int* rid = (int*)(s + OFF_RID);
    __syncthreads();
    const int total = *cnt;
    const int warp = tid >> 5, lane = tid & 31;
    const int nt = (total + TILE_ROWS - 1) / TILE_ROWS;
    for (int tile = blockIdx.x; tile < nt; tile += gridDim.x) {
        int base = tile * TILE_ROWS;
        __syncthreads();
        for (int idx = tid; idx < TILE_ROWS * 32; idx += NTHR) {
            int j = idx >> 5, q = idx & 31;
            int li = base + j;
            int row = (li < total) ? list[li] : -1;
            int rowc = (row >= 0) ? row : list[0];
            float4 v = *(const float4*)(out + (size_t)rowc * 128 + 4 * q);
            *(float4*)(s + OFF_X + j * 128 + 4 * q) = v;
            if (q == 0) rid[j] = row;
        }
        __syncthreads();
        mlp3_warp(s, s + OFF_X + warp * 2048, rid + warp * ROWS_PER_WARP, lane, out);
    }
}

// ================= host =================
extern "C" void kernel_launch(void* const* d_in, const int* in_sizes, int n_in,
                              void* d_out, int out_size)
{
    const float* feat = (const float*)d_in[0];
    const int*   src  = (const int*)d_in[1];
    const int*   dst  = (const int*)d_in[2];
    const int*   r    = (const int*)d_in[3];
    const int*   inv  = (const int*)d_in[4];
    const float* iw1 = (const float*)d_in[5];
    const float* ib1 = (const float*)d_in[6];
    const float* iw2 = (const float*)d_in[7];
    const float* ib2 = (const float*)d_in[8];
    const float* iw3 = (const float*)d_in[9];
    const float* ib3 = (const float*)d_in[10];
    const float* aw1 = (const float*)d_in[11];
    const float* ab1 = (const float*)d_in[12];
    const float* aw2 = (const float*)d_in[13];
    const float* ab2 = (const float*)d_in[14];
    const float* aw3 = (const float*)d_in[15];
    const float* ab3 = (const float*)d_in[16];
    float* out = (float*)d_out;

    float *g, *sum;
    unsigned* packed;
    int *deg, *start, *cursor, *bsum, *boff, *list, *cnt;
    cudaGetSymbolAddress((void**)&g, g_g);
    cudaGetSymbolAddress((void**)&sum, g_sum);
    cudaGetSymbolAddress((void**)&packed, g_packed);
    cudaGetSymbolAddress((void**)&deg, g_deg);
    cudaGetSymbolAddress((void**)&start, g_start);
    cudaGetSymbolAddress((void**)&cursor, g_cursor);
    cudaGetSymbolAddress((void**)&bsum, g_bsum);
    cudaGetSymbolAddress((void**)&boff, g_boff);
    cudaGetSymbolAddress((void**)&list, g_list);
    cudaGetSymbolAddress((void**)&cnt, g_cnt);

    const size_t smem = SMEM_FLOATS * sizeof(float);   // 186112 B
    cudaFuncSetAttribute(k_g,    cudaFuncAttributeMaxDynamicSharedMemorySize, (int)smem);
    cudaFuncSetAttribute(k_node, cudaFuncAttributeMaxDynamicSharedMemorySize, (int)smem);
    cudaFuncSetAttribute(k_inv,  cudaFuncAttributeMaxDynamicSharedMemorySize, (int)smem);

    cudaMemsetAsync(deg, 0, NN * sizeof(int));                        // launch 0
    cudaMemsetAsync(cnt, 0, sizeof(int));                             // launch 1

    k_hist<<<(EE + 1023) / 1024, 1024>>>(dst, deg);                   // 2
    k_scanA<<<NBLK_SCAN, 1024>>>(deg, bsum);                          // 3
    k_scanB<<<1, 128>>>(bsum, boff);                                  // 4
    k_g<<<148, NTHR, smem>>>(feat, iw1, ib1, iw2, ib2, iw3, ib3, g);  // 5  <- ncu -s 5
    k_scanC<<<NBLK_SCAN, 1024>>>(deg, boff, start, cursor);           // 6
    k_fill<<<(EE + 1023) / 1024, 1024>>>(src, dst, r, cursor, packed);// 7
    k_compact<<<NBLK_SCAN, 1024>>>(inv, list, cnt);                   // 8
    k_gather<<<(NN * 32 + 255) / 256, 256>>>(feat, g, packed, start, deg, sum); // 9
    k_node<<<148, NTHR, smem>>>(sum, deg, aw1, ab1, aw2, ab2, aw3, ab3, out);   // 10
    k_inv<<<148, NTHR, smem>>>(iw1, ib1, iw2, ib2, iw3, ib3, list, cnt, out);   // 11
}

// round 9
// speedup vs baseline: 1.8880x; 1.2894x over previous
#include <cuda_runtime.h>
#include <cuda_bf16.h>
#include <stdint.h>

#define NN 100000
#define EE 800000
#define NBLK_SCAN 98            // ceil(100000/1024)

// ---------------- scratch (device globals; no allocation) ----------------
__device__ float    g_g[(size_t)NN * 128];    // mlp_inv(feat) per node
__device__ float    g_sum[(size_t)NN * 128];  // aggregated 128-wide sums
__device__ unsigned g_packed[EE];             // CSR edge payload: src | (r<<31)
__device__ int      g_deg[NN];
__device__ int      g_start[NN];
__device__ int      g_cursor[NN];
__device__ int      g_bsum[NBLK_SCAN];
__device__ int      g_boff[NBLK_SCAN];
__device__ int      g_list[NN];
__device__ int      g_cnt[1];

__device__ __forceinline__ float lrelu(float v) { return v >= 0.0f ? v : 0.01f * v; }

__device__ __forceinline__ uint32_t smem_u32(const void* p) {
    uint32_t a;
    asm("{ .reg .u64 t; cvta.to.shared.u64 t, %1; cvt.u32.u64 %0, t; }" : "=r"(a) : "l"(p));
    return a;
}

// packed bf16x2: low 16 bits = bf16(vlo), high 16 bits = bf16(vhi)
__device__ __forceinline__ uint32_t bfpair(float vlo, float vhi) {
    uint32_t r;
    asm("cvt.rn.bf16x2.f32 %0, %1, %2;" : "=r"(r) : "f"(vhi), "f"(vlo));
    return r;
}

__device__ __forceinline__ void ldsm4(uint32_t &r0, uint32_t &r1, uint32_t &r2, uint32_t &r3,
                                      uint32_t a) {
    asm volatile("ldmatrix.sync.aligned.m8n8.x4.shared.b16 {%0,%1,%2,%3}, [%4];"
                 : "=r"(r0), "=r"(r1), "=r"(r2), "=r"(r3) : "r"(a));
}

__device__ __forceinline__ void mma_bf16(float d[4],
                                         uint32_t a0, uint32_t a1, uint32_t a2, uint32_t a3,
                                         uint32_t b0, uint32_t b1) {
    asm volatile("mma.sync.aligned.m16n8k16.row.col.f32.bf16.bf16.f32 "
                 "{%0,%1,%2,%3}, {%4,%5,%6,%7}, {%8,%9}, {%0,%1,%2,%3};"
                 : "+f"(d[0]), "+f"(d[1]), "+f"(d[2]), "+f"(d[3])
                 : "r"(a0), "r"(a1), "r"(a2), "r"(a3), "r"(b0), "r"(b1));
}

// ---------------- smem byte offsets ----------------
// pitches: X/W1 = 272 B (17x16B, odd -> conflict-free ldmatrix); 64-col tiles = 144 B (9x16B)
#define SM_RID  0          // 128 ints
#define SM_SRC  512
#define SM_SCL  1024
#define SM_B1   1536       // 64 f32
#define SM_B2   1792
#define SM_B3   2048       // 128 f32
#define SM_W1H  2560       // 64 x 272
#define SM_W1L  19968
#define SM_W2H  37376      // 64 x 144
#define SM_W2L  46592
#define SM_W3H  55808      // 128 x 144
#define SM_W3L  74240
#define SM_TH   92672      // 128 x 144
#define SM_TL   111104
#define SM_XH   129536     // 128 x 272 (U hi overlays @144 pitch)
#define SM_XL   164352
#define SMEM_BYTES 199168

// stage fp32 weights [OUT][K] -> hi/lo bf16 pitched tiles
__device__ void stage_w(char* hi, char* lo, const float* __restrict__ w,
                        int OUT, int K, int pitch, int tid) {
    for (int i = tid; i < OUT * K; i += 256) {
        int o = i / K, k = i - o * K;
        float v = w[i];
        __nv_bfloat16 hb = __float2bfloat16(v);
        __nv_bfloat16 lb = __float2bfloat16(v - __bfloat162float(hb));
        *(__nv_bfloat16*)(hi + o * pitch + k * 2) = hb;
        *(__nv_bfloat16*)(lo + o * pitch + k * 2) = lb;
    }
}

// warp GEMM: A (16 rows) x B (64 cols, 8 n-tiles), hi/lo 3-pass, KSTEPS k16-steps
template<int KSTEPS>
__device__ __forceinline__ void gemm8(uint32_t aH, uint32_t aL,
                                      uint32_t bH, uint32_t bL, int bstep16,
                                      float acc[8][4]) {
    #pragma unroll
    for (int k = 0; k < KSTEPS; k++) {
        uint32_t ah0, ah1, ah2, ah3, al0, al1, al2, al3;
        ldsm4(ah0, ah1, ah2, ah3, aH + k * 32);
        ldsm4(al0, al1, al2, al3, aL + k * 32);
        #pragma unroll
        for (int np = 0; np < 4; np++) {
            uint32_t bh0, bh1, bh2, bh3, bl0, bl1, bl2, bl3;
            ldsm4(bh0, bh1, bh2, bh3, bH + np * bstep16 + k * 32);
            ldsm4(bl0, bl1, bl2, bl3, bL + np * bstep16 + k * 32);
            mma_bf16(acc[2*np],   ah0, ah1, ah2, ah3, bh0, bh1);
            mma_bf16(acc[2*np+1], ah0, ah1, ah2, ah3, bh2, bh3);
            mma_bf16(acc[2*np],   al0, al1, al2, al3, bh0, bh1);
            mma_bf16(acc[2*np+1], al0, al1, al2, al3, bh2, bh3);
            mma_bf16(acc[2*np],   ah0, ah1, ah2, ah3, bl0, bl1);
            mma_bf16(acc[2*np+1], ah0, ah1, ah2, ah3, bl2, bl3);
        }
    }
}

// 64-col epilogue: bias + lrelu + hi/lo bf16 store to pitched tiles
__device__ __forceinline__ void epi64(const float acc[8][4], const float* __restrict__ bias,
                                      char* tH, char* tL, int pitch, int m0, int g, int t) {
    #pragma unroll
    for (int nt2 = 0; nt2 < 8; nt2++) {
        int c = nt2 * 8 + 2 * t;
        float v0 = lrelu(acc[nt2][0] + bias[c]);
        float v1 = lrelu(acc[nt2][1] + bias[c + 1]);
        float v2 = lrelu(acc[nt2][2] + bias[c]);
        float v3 = lrelu(acc[nt2][3] + bias[c + 1]);
        uint32_t h0 = bfpair(v0, v1);
        uint32_t l0 = bfpair(v0 - __uint_as_float(h0 << 16),
                             v1 - __uint_as_float(h0 & 0xFFFF0000u));
        uint32_t h1 = bfpair(v2, v3);
        uint32_t l1 = bfpair(v2 - __uint_as_float(h1 << 16),
                             v3 - __uint_as_float(h1 & 0xFFFF0000u));
        *(uint32_t*)(tH + (m0 + g) * pitch + c * 2)     = h0;
        *(uint32_t*)(tL + (m0 + g) * pitch + c * 2)     = l0;
        *(uint32_t*)(tH + (m0 + 8 + g) * pitch + c * 2) = h1;
        *(uint32_t*)(tL + (m0 + 8 + g) * pitch + c * 2) = l1;
    }
}

// ================= fused 3-layer MLP via mma.sync bf16 hi/lo =================
// MODE 0: rows 0..NN-1. MODE 1: in scaled by 1/max(deg,1). MODE 2: rows from list.
template <int MODE>
__global__ void __launch_bounds__(256, 1) mlp_mma(
    const float* __restrict__ in, float* __restrict__ outp,
    const float* __restrict__ w1, const float* __restrict__ b1,
    const float* __restrict__ w2, const float* __restrict__ b2,
    const float* __restrict__ w3, const float* __restrict__ b3,
    const int* __restrict__ deg, const int* __restrict__ list,
    const int* __restrict__ cnt)
{
    extern __shared__ char smc[];
    const uint32_t sb = smem_u32(smc);
    const int tid = threadIdx.x, wid = tid >> 5, lane = tid & 31;

    stage_w(smc + SM_W1H, smc + SM_W1L, w1, 64, 128, 272, tid);
    stage_w(smc + SM_W2H, smc + SM_W2L, w2, 64, 64, 144, tid);
    stage_w(smc + SM_W3H, smc + SM_W3L, w3, 128, 64, 144, tid);
    float* b1s = (float*)(smc + SM_B1);
    float* b2s = (float*)(smc + SM_B2);
    float* b3s = (float*)(smc + SM_B3);
    for (int i = tid; i < 64; i += 256) { b1s[i] = b1[i]; b2s[i] = b2[i]; }
    for (int i = tid; i < 128; i += 256) b3s[i] = b3[i];

    int* rid_s = (int*)(smc + SM_RID);
    int* src_s = (int*)(smc + SM_SRC);
    float* scl_s = (float*)(smc + SM_SCL);
    __syncthreads();

    const int nrows = (MODE == 2) ? *cnt : NN;
    const int ntile = (nrows + 127) >> 7;

    const int arow = (lane & 7) + ((lane >> 3) & 1) * 8;
    const int akoff = (lane >> 4) * 16;
    const int brow = (lane & 7) + ((lane >> 4) & 1) * 8;
    const int bkoff = ((lane >> 3) & 1) * 16;
    const int m0 = wid * 16;
    const int g = lane >> 2, t = lane & 3;

    for (int tile = blockIdx.x; tile < ntile; tile += gridDim.x) {
        int base = tile << 7;
        __syncthreads();                   // prev tile's U region fully consumed
        if (tid < 128) {
            int row = base + tid;
            int rowid, srow; float sc = 1.0f;
            if (MODE == 2) {
                rowid = (row < nrows) ? list[row] : -1;
                srow = (rowid >= 0) ? rowid : list[base];
            } else {
                rowid = (row < NN) ? row : -1;
                srow = (rowid >= 0) ? rowid : (NN - 1);
            }
            if (MODE == 1) { int dg = deg[srow]; sc = 1.0f / (float)(dg < 1 ? 1 : dg); }
            rid_s[tid] = rowid; src_s[tid] = srow; scl_s[tid] = sc;
        }
        __syncthreads();
        // ---- stage X: fp32 -> hi/lo bf16 pitched tiles ----
        for (int idx = tid; idx < 128 * 32; idx += 256) {
            int j = idx >> 5, q = idx & 31;
            float4 v = *(const float4*)(in + (size_t)src_s[j] * 128 + 4 * q);
            if (MODE == 1) { float sc = scl_s[j]; v.x *= sc; v.y *= sc; v.z *= sc; v.w *= sc; }
            uint32_t h0 = bfpair(v.x, v.y);
            uint32_t h1 = bfpair(v.z, v.w);
            uint32_t l0 = bfpair(v.x - __uint_as_float(h0 << 16),
                                 v.y - __uint_as_float(h0 & 0xFFFF0000u));
            uint32_t l1 = bfpair(v.z - __uint_as_float(h1 << 16),
                                 v.w - __uint_as_float(h1 & 0xFFFF0000u));
            *(uint2*)(smc + SM_XH + j * 272 + 8 * q) = make_uint2(h0, h1);
            *(uint2*)(smc + SM_XL + j * 272 + 8 * q) = make_uint2(l0, l1);
        }
        __syncthreads();

        // ---- layer 1: [16x128] @ W1^T[128x64] ----
        float acc[8][4];
        #pragma unroll
        for (int i = 0; i < 8; i++) { acc[i][0]=0.f; acc[i][1]=0.f; acc[i][2]=0.f; acc[i][3]=0.f; }
        gemm8<8>(sb + SM_XH + (m0 + arow) * 272 + akoff,
                 sb + SM_XL + (m0 + arow) * 272 + akoff,
                 sb + SM_W1H + brow * 272 + bkoff,
                 sb + SM_W1L + brow * 272 + bkoff, 16 * 272, acc);
        epi64(acc, b1s, smc + SM_TH, smc + SM_TL, 144, m0, g, t);
        __syncwarp();

        // ---- layer 2: [16x64] @ W2^T ----
        float acc2[8][4];
        #pragma unroll
        for (int i = 0; i < 8; i++) { acc2[i][0]=0.f; acc2[i][1]=0.f; acc2[i][2]=0.f; acc2[i][3]=0.f; }
        gemm8<4>(sb + SM_TH + (m0 + arow) * 144 + akoff,
                 sb + SM_TL + (m0 + arow) * 144 + akoff,
                 sb + SM_W2H + brow * 144 + bkoff,
                 sb + SM_W2L + brow * 144 + bkoff, 16 * 144, acc2);
        // U tiles overlay X region at pitch 144
        epi64(acc2, b2s, smc + SM_XH, smc + SM_XL, 144, m0, g, t);
        __syncwarp();

        // ---- layer 3: [16x64] @ W3^T[64x128], two 64-col halves ----
        int r0g = rid_s[m0 + g], r1g = rid_s[m0 + 8 + g];
        #pragma unroll
        for (int h = 0; h < 2; h++) {
            float acc3[8][4];
            #pragma unroll
            for (int i = 0; i < 8; i++) { acc3[i][0]=0.f; acc3[i][1]=0.f; acc3[i][2]=0.f; acc3[i][3]=0.f; }
            gemm8<4>(sb + SM_XH + (m0 + arow) * 144 + akoff,
                     sb + SM_XL + (m0 + arow) * 144 + akoff,
                     sb + SM_W3H + (h * 64 + brow) * 144 + bkoff,
                     sb + SM_W3L + (h * 64 + brow) * 144 + bkoff, 16 * 144, acc3);
            #pragma unroll
            for (int nt2 = 0; nt2 < 8; nt2++) {
                int c = h * 64 + nt2 * 8 + 2 * t;
                if (r0g >= 0) {
                    float2 o; o.x = acc3[nt2][0] + b3s[c]; o.y = acc3[nt2][1] + b3s[c + 1];
                    *(float2*)(outp + (size_t)r0g * 128 + c) = o;
                }
                if (r1g >= 0) {
                    float2 o; o.x = acc3[nt2][2] + b3s[c]; o.y = acc3[nt2][3] + b3s[c + 1];
                    *(float2*)(outp + (size_t)r1g * 128 + c) = o;
                }
            }
        }
    }
}

// ================= CSR build =================
__global__ void k_hist(const int* __restrict__ dst, int* __restrict__ deg) {
    int i = blockIdx.x * 1024 + threadIdx.x;
    if (i < EE) atomicAdd(&deg[dst[i]], 1);
}

__global__ void k_scanA(const int* __restrict__ deg, int* __restrict__ bsum) {
    __shared__ int ws[32];
    int i = blockIdx.x * 1024 + threadIdx.x;
    int v = (i < NN) ? deg[i] : 0;
    #pragma unroll
    for (int d = 16; d > 0; d >>= 1) v += __shfl_down_sync(~0u, v, d);
    int lane = threadIdx.x & 31, wid = threadIdx.x >> 5;
    if (lane == 0) ws[wid] = v;
    __syncthreads();
    if (wid == 0) {
        int t = ws[lane];
        #pragma unroll
        for (int d = 16; d > 0; d >>= 1) t += __shfl_down_sync(~0u, t, d);
        if (lane == 0) bsum[blockIdx.x] = t;
    }
}

__global__ void k_scanB(const int* __restrict__ bsum, int* __restrict__ boff) {
    __shared__ int s[128];
    int t = threadIdx.x;
    int v = (t < NBLK_SCAN) ? bsum[t] : 0;
    s[t] = v;
    __syncthreads();
    for (int d = 1; d < 128; d <<= 1) {
        int x = (t >= d) ? s[t - d] : 0;
        __syncthreads();
        s[t] += x;
        __syncthreads();
    }
    if (t < NBLK_SCAN) boff[t] = s[t] - v;   // exclusive
}

__global__ void k_scanC(const int* __restrict__ deg, const int* __restrict__ boff,
                        int* __restrict__ start, int* __restrict__ cursor) {
    __shared__ int ws[32];
    int i = blockIdx.x * 1024 + threadIdx.x;
    int lane = threadIdx.x & 31, wid = threadIdx.x >> 5;
    int v = (i < NN) ? deg[i] : 0;
    int incl = v;
    #pragma unroll
    for (int d = 1; d < 32; d <<= 1) {
        int n = __shfl_up_sync(~0u, incl, d);
        if (lane >= d) incl += n;
    }
    if (lane == 31) ws[wid] = incl;
    __syncthreads();
    if (wid == 0) {
        int wv = ws[lane];
        int wi = wv;
        #pragma unroll
        for (int d = 1; d < 32; d <<= 1) {
            int n = __shfl_up_sync(~0u, wi, d);
            if (lane >= d) wi += n;
        }
        ws[lane] = wi - wv;
    }
    __syncthreads();
    int excl = incl - v + ws[wid] + boff[blockIdx.x];
    if (i < NN) { start[i] = excl; cursor[i] = excl; }
}

__global__ void k_fill(const int* __restrict__ src, const int* __restrict__ dst,
                       const int* __restrict__ r, int* __restrict__ cursor,
                       unsigned* __restrict__ packed) {
    int i = blockIdx.x * 1024 + threadIdx.x;
    if (i >= EE) return;
    int d = dst[i];
    int pos = atomicAdd(&cursor[d], 1);
    packed[pos] = (unsigned)src[i] | ((unsigned)r[i] << 31);
}

__global__ void k_compact(const int* __restrict__ inv, int* __restrict__ list,
                          int* __restrict__ cnt) {
    int i = blockIdx.x * 1024 + threadIdx.x;
    if (i < NN && inv[i] == 1) {
        int pos = atomicAdd(cnt, 1);
        list[pos] = i;
    }
}

// ================= k_gather: warp per node, 128-wide sums =================
__global__ void k_gather(const float* __restrict__ feat, const float* __restrict__ g,
                         const unsigned* __restrict__ packed,
                         const int* __restrict__ start, const int* __restrict__ deg,
                         float* __restrict__ sum) {
    int w = (blockIdx.x * blockDim.x + threadIdx.x) >> 5;
    int lane = threadIdx.x & 31;
    if (w >= NN) return;
    int s0 = start[w];
    int e = s0 + deg[w];
    float4 acc = make_float4(0.f, 0.f, 0.f, 0.f);
    for (int j = s0; j < e; j++) {
        unsigned v = __ldg(&packed[j]);
        const float* rp = ((v >> 31) ? g : feat) + (size_t)(v & 0x7FFFFFFFu) * 128;
        float4 x = *(const float4*)(rp + 4 * lane);
        acc.x += x.x; acc.y += x.y; acc.z += x.z; acc.w += x.w;
    }
    *(float4*)(sum + (size_t)w * 128 + 4 * lane) = acc;
}

// ================= host =================
extern "C" void kernel_launch(void* const* d_in, const int* in_sizes, int n_in,
                              void* d_out, int out_size)
{
    const float* feat = (const float*)d_in[0];
    const int*   src  = (const int*)d_in[1];
    const int*   dst  = (const int*)d_in[2];
    const int*   r    = (const int*)d_in[3];
    const int*   inv  = (const int*)d_in[4];
    const float* iw1 = (const float*)d_in[5];
    const float* ib1 = (const float*)d_in[6];
    const float* iw2 = (const float*)d_in[7];
    const float* ib2 = (const float*)d_in[8];
    const float* iw3 = (const float*)d_in[9];
    const float* ib3 = (const float*)d_in[10];
    const float* aw1 = (const float*)d_in[11];
    const float* ab1 = (const float*)d_in[12];
    const float* aw2 = (const float*)d_in[13];
    const float* ab2 = (const float*)d_in[14];
    const float* aw3 = (const float*)d_in[15];
    const float* ab3 = (const float*)d_in[16];
    float* out = (float*)d_out;

    float *g, *sum;
    unsigned* packed;
    int *deg, *start, *cursor, *bsum, *boff, *list, *cnt;
    cudaGetSymbolAddress((void**)&g, g_g);
    cudaGetSymbolAddress((void**)&sum, g_sum);
    cudaGetSymbolAddress((void**)&packed, g_packed);
    cudaGetSymbolAddress((void**)&deg, g_deg);
    cudaGetSymbolAddress((void**)&start, g_start);
    cudaGetSymbolAddress((void**)&cursor, g_cursor);
    cudaGetSymbolAddress((void**)&bsum, g_bsum);
    cudaGetSymbolAddress((void**)&boff, g_boff);
    cudaGetSymbolAddress((void**)&list, g_list);
    cudaGetSymbolAddress((void**)&cnt, g_cnt);

    cudaFuncSetAttribute(mlp_mma<0>, cudaFuncAttributeMaxDynamicSharedMemorySize, SMEM_BYTES);
    cudaFuncSetAttribute(mlp_mma<1>, cudaFuncAttributeMaxDynamicSharedMemorySize, SMEM_BYTES);
    cudaFuncSetAttribute(mlp_mma<2>, cudaFuncAttributeMaxDynamicSharedMemorySize, SMEM_BYTES);

    cudaMemsetAsync(deg, 0, NN * sizeof(int));                        // launch 0
    cudaMemsetAsync(cnt, 0, sizeof(int));                             // launch 1

    k_hist<<<(EE + 1023) / 1024, 1024>>>(dst, deg);                   // 2
    k_scanA<<<NBLK_SCAN, 1024>>>(deg, bsum);                          // 3
    k_scanB<<<1, 128>>>(bsum, boff);                                  // 4
    mlp_mma<0><<<148, 256, SMEM_BYTES>>>(feat, g, iw1, ib1, iw2, ib2, iw3, ib3,
                                         nullptr, nullptr, nullptr);  // 5  <- ncu -s 5
    k_scanC<<<NBLK_SCAN, 1024>>>(deg, boff, start, cursor);           // 6
    k_fill<<<(EE + 1023) / 1024, 1024>>>(src, dst, r, cursor, packed);// 7
    k_compact<<<NBLK_SCAN, 1024>>>(inv, list, cnt);                   // 8
    k_gather<<<(NN * 32 + 255) / 256, 256>>>(feat, g, packed, start, deg, sum); // 9
    mlp_mma<1><<<148, 256, SMEM_BYTES>>>(sum, out, aw1, ab1, aw2, ab2, aw3, ab3,
                                         deg, nullptr, nullptr);      // 10
    mlp_mma<2><<<148, 256, SMEM_BYTES>>>(out, out, iw1, ib1, iw2, ib2, iw3, ib3,
                                         nullptr, list, cnt);         // 11
}

// round 10
// speedup vs baseline: 2.1270x; 1.1266x over previous
#include <cuda_runtime.h>
#include <cuda_bf16.h>
#include <stdint.h>

#define NN 100000
#define EE 800000
#define NBLK_SCAN 98            // ceil(100000/1024)

// ---------------- scratch (device globals; no allocation) ----------------
__device__ float    g_g[(size_t)NN * 128];    // mlp_inv(feat) per node
__device__ float    g_sum[(size_t)NN * 128];  // aggregated 128-wide sums
__device__ unsigned g_packed[EE];             // CSR edge payload: src | (r<<31)
__device__ int      g_deg[NN];
__device__ int      g_start[NN];
__device__ int      g_cursor[NN];
__device__ int      g_bsum[NBLK_SCAN];
__device__ int      g_boff[NBLK_SCAN];
__device__ int      g_list[NN];
__device__ int      g_cnt[1];

__device__ __forceinline__ float lrelu(float v) { return v >= 0.0f ? v : 0.01f * v; }

__device__ __forceinline__ uint32_t smem_u32(const void* p) {
    uint32_t a;
    asm("{ .reg .u64 t; cvta.to.shared.u64 t, %1; cvt.u32.u64 %0, t; }" : "=r"(a) : "l"(p));
    return a;
}

// packed bf16x2: low 16 bits = bf16(vlo), high 16 bits = bf16(vhi)
__device__ __forceinline__ uint32_t bfpair(float vlo, float vhi) {
    uint32_t r;
    asm("cvt.rn.bf16x2.f32 %0, %1, %2;" : "=r"(r) : "f"(vhi), "f"(vlo));
    return r;
}

__device__ __forceinline__ void ldsm4(uint32_t &r0, uint32_t &r1, uint32_t &r2, uint32_t &r3,
                                      uint32_t a) {
    asm volatile("ldmatrix.sync.aligned.m8n8.x4.shared.b16 {%0,%1,%2,%3}, [%4];"
                 : "=r"(r0), "=r"(r1), "=r"(r2), "=r"(r3) : "r"(a));
}

__device__ __forceinline__ void mma_bf16(float d[4],
                                         uint32_t a0, uint32_t a1, uint32_t a2, uint32_t a3,
                                         uint32_t b0, uint32_t b1) {
    asm volatile("mma.sync.aligned.m16n8k16.row.col.f32.bf16.bf16.f32 "
                 "{%0,%1,%2,%3}, {%4,%5,%6,%7}, {%8,%9}, {%0,%1,%2,%3};"
                 : "+f"(d[0]), "+f"(d[1]), "+f"(d[2]), "+f"(d[3])
                 : "r"(a0), "r"(a1), "r"(a2), "r"(a3), "r"(b0), "r"(b1));
}

// ---------------- smem byte offsets ----------------
// pitches: X/W1 = 272 B (17x16B, odd -> conflict-free ldmatrix); 64-col tiles = 144 B (9x16B)
#define SM_RID  0          // 128 ints
#define SM_SRC  512
#define SM_SCL  1024
#define SM_B1   1536       // 64 f32
#define SM_B2   1792
#define SM_B3   2048       // 128 f32
#define SM_W1H  2560       // 64 x 272
#define SM_W1L  19968
#define SM_W2H  37376      // 64 x 144
#define SM_W2L  46592
#define SM_W3H  55808      // 128 x 144
#define SM_W3L  74240
#define SM_TH   92672      // 128 x 144
#define SM_TL   111104
#define SM_XH   129536     // 128 x 272 (U hi overlays @144 pitch)
#define SM_XL   164352
#define SMEM_BYTES 199168

#define NTHR 512

// stage fp32 weights [OUT][K] -> hi/lo bf16 pitched tiles
__device__ void stage_w(char* hi, char* lo, const float* __restrict__ w,
                        int OUT, int K, int pitch, int tid) {
    for (int i = tid; i < OUT * K; i += NTHR) {
        int o = i / K, k = i - o * K;
        float v = w[i];
        __nv_bfloat16 hb = __float2bfloat16(v);
        __nv_bfloat16 lb = __float2bfloat16(v - __bfloat162float(hb));
        *(__nv_bfloat16*)(hi + o * pitch + k * 2) = hb;
        *(__nv_bfloat16*)(lo + o * pitch + k * 2) = lb;
    }
}

// warp GEMM: A (16 rows) x B (NTILES*16 cols), hi/lo 3-pass, KSTEPS k16-steps
template<int KSTEPS, int NTILES>
__device__ __forceinline__ void gemmN(uint32_t aH, uint32_t aL,
                                      uint32_t bH, uint32_t bL, int bstep16,
                                      float acc[][4]) {
    #pragma unroll
    for (int k = 0; k < KSTEPS; k++) {
        uint32_t ah0, ah1, ah2, ah3, al0, al1, al2, al3;
        ldsm4(ah0, ah1, ah2, ah3, aH + k * 32);
        ldsm4(al0, al1, al2, al3, aL + k * 32);
        #pragma unroll
        for (int np = 0; np < NTILES; np++) {
            uint32_t bh0, bh1, bh2, bh3, bl0, bl1, bl2, bl3;
            ldsm4(bh0, bh1, bh2, bh3, bH + np * bstep16 + k * 32);
            ldsm4(bl0, bl1, bl2, bl3, bL + np * bstep16 + k * 32);
            mma_bf16(acc[2*np],   ah0, ah1, ah2, ah3, bh0, bh1);
            mma_bf16(acc[2*np+1], ah0, ah1, ah2, ah3, bh2, bh3);
            mma_bf16(acc[2*np],   al0, al1, al2, al3, bh0, bh1);
            mma_bf16(acc[2*np+1], al0, al1, al2, al3, bh2, bh3);
            mma_bf16(acc[2*np],   ah0, ah1, ah2, ah3, bl0, bl1);
            mma_bf16(acc[2*np+1], ah0, ah1, ah2, ah3, bl2, bl3);
        }
    }
}

// 32-col epilogue: bias + lrelu + hi/lo bf16 store to pitched tiles at column offset ncol0
__device__ __forceinline__ void epi32(const float acc[4][4], const float* __restrict__ bias,
                                      char* tH, char* tL, int pitch, int m0, int ncol0,
                                      int g, int t) {
    #pragma unroll
    for (int nt2 = 0; nt2 < 4; nt2++) {
        int c = ncol0 + nt2 * 8 + 2 * t;
        float v0 = lrelu(acc[nt2][0] + bias[c]);
        float v1 = lrelu(acc[nt2][1] + bias[c + 1]);
        float v2 = lrelu(acc[nt2][2] + bias[c]);
        float v3 = lrelu(acc[nt2][3] + bias[c + 1]);
        uint32_t h0 = bfpair(v0, v1);
        uint32_t l0 = bfpair(v0 - __uint_as_float(h0 << 16),
                             v1 - __uint_as_float(h0 & 0xFFFF0000u));
        uint32_t h1 = bfpair(v2, v3);
        uint32_t l1 = bfpair(v2 - __uint_as_float(h1 << 16),
                             v3 - __uint_as_float(h1 & 0xFFFF0000u));
        *(uint32_t*)(tH + (m0 + g) * pitch + c * 2)     = h0;
        *(uint32_t*)(tL + (m0 + g) * pitch + c * 2)     = l0;
        *(uint32_t*)(tH + (m0 + 8 + g) * pitch + c * 2) = h1;
        *(uint32_t*)(tL + (m0 + 8 + g) * pitch + c * 2) = l1;
    }
}

// ================= fused 3-layer MLP via mma.sync bf16 hi/lo, 16 warps N-split ======
// MODE 0: rows 0..NN-1. MODE 1: in scaled by 1/max(deg,1). MODE 2: rows from list.
template <int MODE>
__global__ void __launch_bounds__(NTHR, 1) mlp_mma(
    const float* __restrict__ in, float* __restrict__ outp,
    const float* __restrict__ w1, const float* __restrict__ b1,
    const float* __restrict__ w2, const float* __restrict__ b2,
    const float* __restrict__ w3, const float* __restrict__ b3,
    const int* __restrict__ deg, const int* __restrict__ list,
    const int* __restrict__ cnt)
{
    extern __shared__ char smc[];
    const uint32_t sb = smem_u32(smc);
    const int tid = threadIdx.x, wid = tid >> 5, lane = tid & 31;

    stage_w(smc + SM_W1H, smc + SM_W1L, w1, 64, 128, 272, tid);
    stage_w(smc + SM_W2H, smc + SM_W2L, w2, 64, 64, 144, tid);
    stage_w(smc + SM_W3H, smc + SM_W3L, w3, 128, 64, 144, tid);
    float* b1s = (float*)(smc + SM_B1);
    float* b2s = (float*)(smc + SM_B2);
    float* b3s = (float*)(smc + SM_B3);
    for (int i = tid; i < 64; i += NTHR) { b1s[i] = b1[i]; b2s[i] = b2[i]; }
    for (int i = tid; i < 128; i += NTHR) b3s[i] = b3[i];

    int* rid_s = (int*)(smc + SM_RID);
    int* src_s = (int*)(smc + SM_SRC);
    float* scl_s = (float*)(smc + SM_SCL);
    __syncthreads();

    const int nrows = (MODE == 2) ? *cnt : NN;
    const int ntile = (nrows + 127) >> 7;

    const int arow = (lane & 7) + ((lane >> 3) & 1) * 8;
    const int akoff = (lane >> 4) * 16;
    const int brow = (lane & 7) + ((lane >> 4) & 1) * 8;
    const int bkoff = ((lane >> 3) & 1) * 16;
    const int mwarp = wid & 7, nhalf = wid >> 3;
    const int m0 = mwarp * 16;
    const int g = lane >> 2, t = lane & 3;

    for (int tile = blockIdx.x; tile < ntile; tile += gridDim.x) {
        int base = tile << 7;
        __syncthreads();                   // prev tile fully consumed
        if (tid < 128) {
            int row = base + tid;
            int rowid, srow; float sc = 1.0f;
            if (MODE == 2) {
                rowid = (row < nrows) ? list[row] : -1;
                srow = (rowid >= 0) ? rowid : list[base];
            } else {
                rowid = (row < NN) ? row : -1;
                srow = (rowid >= 0) ? rowid : (NN - 1);
            }
            if (MODE == 1) { int dg = deg[srow]; sc = 1.0f / (float)(dg < 1 ? 1 : dg); }
            rid_s[tid] = rowid; src_s[tid] = srow; scl_s[tid] = sc;
        }
        __syncthreads();
        // ---- stage X: fp32 -> hi/lo bf16 pitched tiles ----
        for (int idx = tid; idx < 128 * 32; idx += NTHR) {
            int j = idx >> 5, q = idx & 31;
            float4 v = *(const float4*)(in + (size_t)src_s[j] * 128 + 4 * q);
            if (MODE == 1) { float sc = scl_s[j]; v.x *= sc; v.y *= sc; v.z *= sc; v.w *= sc; }
            uint32_t h0 = bfpair(v.x, v.y);
            uint32_t h1 = bfpair(v.z, v.w);
            uint32_t l0 = bfpair(v.x - __uint_as_float(h0 << 16),
                                 v.y - __uint_as_float(h0 & 0xFFFF0000u));
            uint32_t l1 = bfpair(v.z - __uint_as_float(h1 << 16),
                                 v.w - __uint_as_float(h1 & 0xFFFF0000u));
            *(uint2*)(smc + SM_XH + j * 272 + 8 * q) = make_uint2(h0, h1);
            *(uint2*)(smc + SM_XL + j * 272 + 8 * q) = make_uint2(l0, l1);
        }
        __syncthreads();

        // ---- layer 1: [16x128] @ W1^T cols [nhalf*32, +32) ----
        float acc1[4][4];
        #pragma unroll
        for (int i = 0; i < 4; i++) { acc1[i][0]=0.f; acc1[i][1]=0.f; acc1[i][2]=0.f; acc1[i][3]=0.f; }
        gemmN<8, 2>(sb + SM_XH + (m0 + arow) * 272 + akoff,
                    sb + SM_XL + (m0 + arow) * 272 + akoff,
                    sb + SM_W1H + (nhalf * 32 + brow) * 272 + bkoff,
                    sb + SM_W1L + (nhalf * 32 + brow) * 272 + bkoff, 16 * 272, acc1);
        epi32(acc1, b1s, smc + SM_TH, smc + SM_TL, 144, m0, nhalf * 32, g, t);
        __syncthreads();                   // T complete across n-halves

        // ---- layer 2: [16x64] @ W2^T cols [nhalf*32, +32) ----
        float acc2[4][4];
        #pragma unroll
        for (int i = 0; i < 4; i++) { acc2[i][0]=0.f; acc2[i][1]=0.f; acc2[i][2]=0.f; acc2[i][3]=0.f; }
        gemmN<4, 2>(sb + SM_TH + (m0 + arow) * 144 + akoff,
                    sb + SM_TL + (m0 + arow) * 144 + akoff,
                    sb + SM_W2H + (nhalf * 32 + brow) * 144 + bkoff,
                    sb + SM_W2L + (nhalf * 32 + brow) * 144 + bkoff, 16 * 144, acc2);
        __syncthreads();                   // all layer-2 reads of T done; X region dead
        // U tiles overlay X region at pitch 144
        epi32(acc2, b2s, smc + SM_XH, smc + SM_XL, 144, m0, nhalf * 32, g, t);
        __syncthreads();                   // U complete across n-halves

        // ---- layer 3: [16x64] @ W3^T cols [nhalf*64, +64) -> gmem ----
        float acc3[8][4];
        #pragma unroll
        for (int i = 0; i < 8; i++) { acc3[i][0]=0.f; acc3[i][1]=0.f; acc3[i][2]=0.f; acc3[i][3]=0.f; }
        gemmN<4, 4>(sb + SM_XH + (m0 + arow) * 144 + akoff,
                    sb + SM_XL + (m0 + arow) * 144 + akoff,
                    sb + SM_W3H + (nhalf * 64 + brow) * 144 + bkoff,
                    sb + SM_W3L + (nhalf * 64 + brow) * 144 + bkoff, 16 * 144, acc3);
        int r0g = rid_s[m0 + g], r1g = rid_s[m0 + 8 + g];
        #pragma unroll
        for (int nt2 = 0; nt2 < 8; nt2++) {
            int c = nhalf * 64 + nt2 * 8 + 2 * t;
            if (r0g >= 0) {
                float2 o; o.x = acc3[nt2][0] + b3s[c]; o.y = acc3[nt2][1] + b3s[c + 1];
                *(float2*)(outp + (size_t)r0g * 128 + c) = o;
            }
            if (r1g >= 0) {
                float2 o; o.x = acc3[nt2][2] + b3s[c]; o.y = acc3[nt2][3] + b3s[c + 1];
                *(float2*)(outp + (size_t)r1g * 128 + c) = o;
            }
        }
    }
}

// ================= CSR build =================
__global__ void k_hist(const int* __restrict__ dst, int* __restrict__ deg) {
    int i = blockIdx.x * 1024 + threadIdx.x;
    if (i < EE) atomicAdd(&deg[dst[i]], 1);
}

__global__ void k_scanA(const int* __restrict__ deg, int* __restrict__ bsum) {
    __shared__ int ws[32];
    int i = blockIdx.x * 1024 + threadIdx.x;
    int v = (i < NN) ? deg[i] : 0;
    #pragma unroll
    for (int d = 16; d > 0; d >>= 1) v += __shfl_down_sync(~0u, v, d);
    int lane = threadIdx.x & 31, wid = threadIdx.x >> 5;
    if (lane == 0) ws[wid] = v;
    __syncthreads();
    if (wid == 0) {
        int t = ws[lane];
        #pragma unroll
        for (int d = 16; d > 0; d >>= 1) t += __shfl_down_sync(~0u, t, d);
        if (lane == 0) bsum[blockIdx.x] = t;
    }
}

__global__ void k_scanB(const int* __restrict__ bsum, int* __restrict__ boff) {
    __shared__ int s[128];
    int t = threadIdx.x;
    int v = (t < NBLK_SCAN) ? bsum[t] : 0;
    s[t] = v;
    __syncthreads();
    for (int d = 1; d < 128; d <<= 1) {
        int x = (t >= d) ? s[t - d] : 0;
        __syncthreads();
        s[t] += x;
        __syncthreads();
    }
    if (t < NBLK_SCAN) boff[t] = s[t] - v;   // exclusive
}

__global__ void k_scanC(const int* __restrict__ deg, const int* __restrict__ boff,
                        int* __restrict__ start, int* __restrict__ cursor) {
    __shared__ int ws[32];
    int i = blockIdx.x * 1024 + threadIdx.x;
    int lane = threadIdx.x & 31, wid = threadIdx.x >> 5;
    int v = (i < NN) ? deg[i] : 0;
    int incl = v;
    #pragma unroll
    for (int d = 1; d < 32; d <<= 1) {
        int n = __shfl_up_sync(~0u, incl, d);
        if (lane >= d) incl += n;
    }
    if (lane == 31) ws[wid] = incl;
    __syncthreads();
    if (wid == 0) {
        int wv = ws[lane];
        int wi = wv;
        #pragma unroll
        for (int d = 1; d < 32; d <<= 1) {
            int n = __shfl_up_sync(~0u, wi, d);
            if (lane >= d) wi += n;
        }
        ws[lane] = wi - wv;
    }
    __syncthreads();
    int excl = incl - v + ws[wid] + boff[blockIdx.x];
    if (i < NN) { start[i] = excl; cursor[i] = excl; }
}

__global__ void k_fill(const int* __restrict__ src, const int* __restrict__ dst,
                       const int* __restrict__ r, int* __restrict__ cursor,
                       unsigned* __restrict__ packed) {
    int i = blockIdx.x * 1024 + threadIdx.x;
    if (i >= EE) return;
    int d = dst[i];
    int pos = atomicAdd(&cursor[d], 1);
    packed[pos] = (unsigned)src[i] | ((unsigned)r[i] << 31);
}

__global__ void k_compact(const int* __restrict__ inv, int* __restrict__ list,
                          int* __restrict__ cnt) {
    int i = blockIdx.x * 1024 + threadIdx.x;
    if (i < NN && inv[i] == 1) {
        int pos = atomicAdd(cnt, 1);
        list[pos] = i;
    }
}

// ================= k_gather: warp per node, 128-wide sums =================
__global__ void k_gather(const float* __restrict__ feat, const float* __restrict__ g,
                         const unsigned* __restrict__ packed,
                         const int* __restrict__ start, const int* __restrict__ deg,
                         float* __restrict__ sum) {
    int w = (blockIdx.x * blockDim.x + threadIdx.x) >> 5;
    int lane = threadIdx.x & 31;
    if (w >= NN) return;
    int s0 = start[w];
    int e = s0 + deg[w];
    float4 acc = make_float4(0.f, 0.f, 0.f, 0.f);
    for (int j = s0; j < e; j++) {
        unsigned v = __ldg(&packed[j]);
        const float* rp = ((v >> 31) ? g : feat) + (size_t)(v & 0x7FFFFFFFu) * 128;
        float4 x = *(const float4*)(rp + 4 * lane);
        acc.x += x.x; acc.y += x.y; acc.z += x.z; acc.w += x.w;
    }
    *(float4*)(sum + (size_t)w * 128 + 4 * lane) = acc;
}

// ================= host =================
extern "C" void kernel_launch(void* const* d_in, const int* in_sizes, int n_in,
                              void* d_out, int out_size)
{
    const float* feat = (const float*)d_in[0];
    const int*   src  = (const int*)d_in[1];
    const int*   dst  = (const int*)d_in[2];
    const int*   r    = (const int*)d_in[3];
    const int*   inv  = (const int*)d_in[4];
    const float* iw1 = (const float*)d_in[5];
    const float* ib1 = (const float*)d_in[6];
    const float* iw2 = (const float*)d_in[7];
    const float* ib2 = (const float*)d_in[8];
    const float* iw3 = (const float*)d_in[9];
    const float* ib3 = (const float*)d_in[10];
    const float* aw1 = (const float*)d_in[11];
    const float* ab1 = (const float*)d_in[12];
    const float* aw2 = (const float*)d_in[13];
    const float* ab2 = (const float*)d_in[14];
    const float* aw3 = (const float*)d_in[15];
    const float* ab3 = (const float*)d_in[16];
    float* out = (float*)d_out;

    float *g, *sum;
    unsigned* packed;
    int *deg, *start, *cursor, *bsum, *boff, *list, *cnt;
    cudaGetSymbolAddress((void**)&g, g_g);
    cudaGetSymbolAddress((void**)&sum, g_sum);
    cudaGetSymbolAddress((void**)&packed, g_packed);
    cudaGetSymbolAddress((void**)&deg, g_deg);
    cudaGetSymbolAddress((void**)&start, g_start);
    cudaGetSymbolAddress((void**)&cursor, g_cursor);
    cudaGetSymbolAddress((void**)&bsum, g_bsum);
    cudaGetSymbolAddress((void**)&boff, g_boff);
    cudaGetSymbolAddress((void**)&list, g_list);
    cudaGetSymbolAddress((void**)&cnt, g_cnt);

    cudaFuncSetAttribute(mlp_mma<0>, cudaFuncAttributeMaxDynamicSharedMemorySize, SMEM_BYTES);
    cudaFuncSetAttribute(mlp_mma<1>, cudaFuncAttributeMaxDynamicSharedMemorySize, SMEM_BYTES);
    cudaFuncSetAttribute(mlp_mma<2>, cudaFuncAttributeMaxDynamicSharedMemorySize, SMEM_BYTES);

    cudaMemsetAsync(deg, 0, NN * sizeof(int));                        // launch 0
    cudaMemsetAsync(cnt, 0, sizeof(int));                             // launch 1

    k_hist<<<(EE + 1023) / 1024, 1024>>>(dst, deg);                   // 2
    k_scanA<<<NBLK_SCAN, 1024>>>(deg, bsum);                          // 3
    k_scanB<<<1, 128>>>(bsum, boff);                                  // 4
    mlp_mma<0><<<148, NTHR, SMEM_BYTES>>>(feat, g, iw1, ib1, iw2, ib2, iw3, ib3,
                                          nullptr, nullptr, nullptr); // 5  <- ncu -s 5
    k_scanC<<<NBLK_SCAN, 1024>>>(deg, boff, start, cursor);           // 6
    k_fill<<<(EE + 1023) / 1024, 1024>>>(src, dst, r, cursor, packed);// 7
    k_compact<<<NBLK_SCAN, 1024>>>(inv, list, cnt);                   // 8
    k_gather<<<(NN * 32 + 255) / 256, 256>>>(feat, g, packed, start, deg, sum); // 9
    mlp_mma<1><<<148, NTHR, SMEM_BYTES>>>(sum, out, aw1, ab1, aw2, ab2, aw3, ab3,
                                          deg, nullptr, nullptr);     // 10
    mlp_mma<2><<<148, NTHR, SMEM_BYTES>>>(out, out, iw1, ib1, iw2, ib2, iw3, ib3,
                                          nullptr, list, cnt);        // 11
}

// round 12
// speedup vs baseline: 2.1325x; 1.0026x over previous
#include <cuda_runtime.h>
#include <cuda_bf16.h>
#include <stdint.h>

#define NN 100000
#define EE 800000
#define NBLK_SCAN 98            // ceil(100000/1024)

// ---------------- scratch (device globals; no allocation) ----------------
__device__ float    g_g[(size_t)NN * 128];    // mlp_inv(feat) per node
__device__ float    g_sum[(size_t)NN * 128];  // aggregated 128-wide sums
__device__ unsigned g_packed[EE];             // CSR edge payload: src | (r<<31)
__device__ int      g_deg[NN];
__device__ int      g_start[NN];
__device__ int      g_cursor[NN];
__device__ int      g_bsum[NBLK_SCAN];
__device__ int      g_boff[NBLK_SCAN];
__device__ int      g_list[NN];
__device__ int      g_cnt[1];

__device__ __forceinline__ float lrelu(float v) { return v >= 0.0f ? v : 0.01f * v; }

__device__ __forceinline__ uint32_t smem_u32(const void* p) {
    uint32_t a;
    asm("{ .reg .u64 t; cvta.to.shared.u64 t, %1; cvt.u32.u64 %0, t; }" : "=r"(a) : "l"(p));
    return a;
}

// packed bf16x2: low 16 bits = bf16(vlo), high 16 bits = bf16(vhi)
__device__ __forceinline__ uint32_t bfpair(float vlo, float vhi) {
    uint32_t r;
    asm("cvt.rn.bf16x2.f32 %0, %1, %2;" : "=r"(r) : "f"(vhi), "f"(vlo));
    return r;
}

__device__ __forceinline__ void ldsm4(uint32_t &r0, uint32_t &r1, uint32_t &r2, uint32_t &r3,
                                      uint32_t a) {
    asm volatile("ldmatrix.sync.aligned.m8n8.x4.shared.b16 {%0,%1,%2,%3}, [%4];"
                 : "=r"(r0), "=r"(r1), "=r"(r2), "=r"(r3) : "r"(a));
}

__device__ __forceinline__ void mma_bf16(float d[4],
                                         uint32_t a0, uint32_t a1, uint32_t a2, uint32_t a3,
                                         uint32_t b0, uint32_t b1) {
    asm volatile("mma.sync.aligned.m16n8k16.row.col.f32.bf16.bf16.f32 "
                 "{%0,%1,%2,%3}, {%4,%5,%6,%7}, {%8,%9}, {%0,%1,%2,%3};"
                 : "+f"(d[0]), "+f"(d[1]), "+f"(d[2]), "+f"(d[3])
                 : "r"(a0), "r"(a1), "r"(a2), "r"(a3), "r"(b0), "r"(b1));
}

// ---------------- smem byte offsets ----------------
// pitches: X/W1 = 272 B (17x16B, odd -> conflict-free ldmatrix); 64-col tiles = 144 B (9x16B)
#define SM_RID  0          // 128 ints
#define SM_SRC  512
#define SM_SCL  1024
#define SM_B1   1536       // 64 f32
#define SM_B2   1792
#define SM_B3   2048       // 128 f32
#define SM_W1H  2560       // 64 x 272
#define SM_W1L  19968
#define SM_W2H  37376      // 64 x 144
#define SM_W2L  46592
#define SM_W3H  55808      // 128 x 144
#define SM_W3L  74240
#define SM_TH   92672      // 128 x 144
#define SM_TL   111104
#define SM_XH   129536     // 128 x 272 (U hi overlays @144 pitch)
#define SM_XL   164352
#define SMEM_BYTES 199168

#define NTHR 512

// stage fp32 weights [OUT][K] -> hi/lo bf16 pitched tiles
__device__ void stage_w(char* hi, char* lo, const float* __restrict__ w,
                        int OUT, int K, int pitch, int tid) {
    for (int i = tid; i < OUT * K; i += NTHR) {
        int o = i / K, k = i - o * K;
        float v = w[i];
        __nv_bfloat16 hb = __float2bfloat16(v);
        __nv_bfloat16 lb = __float2bfloat16(v - __bfloat162float(hb));
        *(__nv_bfloat16*)(hi + o * pitch + k * 2) = hb;
        *(__nv_bfloat16*)(lo + o * pitch + k * 2) = lb;
    }
}

// warp GEMM: A (16 rows) x B (NTILES*16 cols), hi/lo 3-pass into TWO acc banks
// (bank h: hh products; bank l: lh + hl products) -> independent HMMA chains
template<int KSTEPS, int NTILES>
__device__ __forceinline__ void gemmN(uint32_t aH, uint32_t aL,
                                      uint32_t bH, uint32_t bL, int bstep16,
                                      float acch[][4], float accl[][4]) {
    #pragma unroll
    for (int k = 0; k < KSTEPS; k++) {
        uint32_t ah0, ah1, ah2, ah3, al0, al1, al2, al3;
        ldsm4(ah0, ah1, ah2, ah3, aH + k * 32);
        ldsm4(al0, al1, al2, al3, aL + k * 32);
        #pragma unroll
        for (int np = 0; np < NTILES; np++) {
            uint32_t bh0, bh1, bh2, bh3, bl0, bl1, bl2, bl3;
            ldsm4(bh0, bh1, bh2, bh3, bH + np * bstep16 + k * 32);
            ldsm4(bl0, bl1, bl2, bl3, bL + np * bstep16 + k * 32);
            mma_bf16(acch[2*np],   ah0, ah1, ah2, ah3, bh0, bh1);
            mma_bf16(acch[2*np+1], ah0, ah1, ah2, ah3, bh2, bh3);
            mma_bf16(accl[2*np],   al0, al1, al2, al3, bh0, bh1);
            mma_bf16(accl[2*np+1], al0, al1, al2, al3, bh2, bh3);
            mma_bf16(accl[2*np],   ah0, ah1, ah2, ah3, bl0, bl1);
            mma_bf16(accl[2*np+1], ah0, ah1, ah2, ah3, bl2, bl3);
        }
    }
}

// 32-col epilogue: (acch+accl) + bias + lrelu + hi/lo bf16 store at column offset ncol0
__device__ __forceinline__ void epi32(const float acch[4][4], const float accl[4][4],
                                      const float* __restrict__ bias,
                                      char* tH, char* tL, int pitch, int m0, int ncol0,
                                      int g, int t) {
    #pragma unroll
    for (int nt2 = 0; nt2 < 4; nt2++) {
        int c = ncol0 + nt2 * 8 + 2 * t;
        float v0 = lrelu(acch[nt2][0] + accl[nt2][0] + bias[c]);
        float v1 = lrelu(acch[nt2][1] + accl[nt2][1] + bias[c + 1]);
        float v2 = lrelu(acch[nt2][2] + accl[nt2][2] + bias[c]);
        float v3 = lrelu(acch[nt2][3] + accl[nt2][3] + bias[c + 1]);
        uint32_t h0 = bfpair(v0, v1);
        uint32_t l0 = bfpair(v0 - __uint_as_float(h0 << 16),
                             v1 - __uint_as_float(h0 & 0xFFFF0000u));
        uint32_t h1 = bfpair(v2, v3);
        uint32_t l1 = bfpair(v2 - __uint_as_float(h1 << 16),
                             v3 - __uint_as_float(h1 & 0xFFFF0000u));
        *(uint32_t*)(tH + (m0 + g) * pitch + c * 2)     = h0;
        *(uint32_t*)(tL + (m0 + g) * pitch + c * 2)     = l0;
        *(uint32_t*)(tH + (m0 + 8 + g) * pitch + c * 2) = h1;
        *(uint32_t*)(tL + (m0 + 8 + g) * pitch + c * 2) = l1;
    }
}

#define ZERO4(a, n) { _Pragma("unroll") for (int i = 0; i < n; i++) { (a)[i][0]=0.f; (a)[i][1]=0.f; (a)[i][2]=0.f; (a)[i][3]=0.f; } }

// ================= fused 3-layer MLP via mma.sync bf16 hi/lo, 16 warps N-split ======
// MODE 0: rows 0..NN-1. MODE 1: in scaled by 1/max(deg,1). MODE 2: rows from list.
template <int MODE>
__global__ void __launch_bounds__(NTHR, 1) mlp_mma(
    const float* __restrict__ in, float* __restrict__ outp,
    const float* __restrict__ w1, const float* __restrict__ b1,
    const float* __restrict__ w2, const float* __restrict__ b2,
    const float* __restrict__ w3, const float* __restrict__ b3,
    const int* __restrict__ deg, const int* __restrict__ list,
    const int* __restrict__ cnt)
{
    extern __shared__ char smc[];
    const uint32_t sb = smem_u32(smc);
    const int tid = threadIdx.x, wid = tid >> 5, lane = tid & 31;

    stage_w(smc + SM_W1H, smc + SM_W1L, w1, 64, 128, 272, tid);
    stage_w(smc + SM_W2H, smc + SM_W2L, w2, 64, 64, 144, tid);
    stage_w(smc + SM_W3H, smc + SM_W3L, w3, 128, 64, 144, tid);
    float* b1s = (float*)(smc + SM_B1);
    float* b2s = (float*)(smc + SM_B2);
    float* b3s = (float*)(smc + SM_B3);
    for (int i = tid; i < 64; i += NTHR) { b1s[i] = b1[i]; b2s[i] = b2[i]; }
    for (int i = tid; i < 128; i += NTHR) b3s[i] = b3[i];

    int* rid_s = (int*)(smc + SM_RID);
    int* src_s = (int*)(smc + SM_SRC);
    float* scl_s = (float*)(smc + SM_SCL);
    __syncthreads();

    const int nrows = (MODE == 2) ? *cnt : NN;
    const int ntile = (nrows + 127) >> 7;

    const int arow = (lane & 7) + ((lane >> 3) & 1) * 8;
    const int akoff = (lane >> 4) * 16;
    const int brow = (lane & 7) + ((lane >> 4) & 1) * 8;
    const int bkoff = ((lane >> 3) & 1) * 16;
    const int mwarp = wid & 7, nhalf = wid >> 3;
    const int m0 = mwarp * 16;
    const int g = lane >> 2, t = lane & 3;

    for (int tile = blockIdx.x; tile < ntile; tile += gridDim.x) {
        int base = tile << 7;
        __syncthreads();                   // prev tile fully consumed
        if (tid < 128) {
            int row = base + tid;
            int rowid, srow; float sc = 1.0f;
            if (MODE == 2) {
                rowid = (row < nrows) ? list[row] : -1;
                srow = (rowid >= 0) ? rowid : list[base];
            } else {
                rowid = (row < NN) ? row : -1;
                srow = (rowid >= 0) ? rowid : (NN - 1);
            }
            if (MODE == 1) { int dg = deg[srow]; sc = 1.0f / (float)(dg < 1 ? 1 : dg); }
            rid_s[tid] = rowid; src_s[tid] = srow; scl_s[tid] = sc;
        }
        __syncthreads();
        // ---- stage X: fp32 -> hi/lo bf16 pitched tiles ----
        for (int idx = tid; idx < 128 * 32; idx += NTHR) {
            int j = idx >> 5, q = idx & 31;
            float4 v = *(const float4*)(in + (size_t)src_s[j] * 128 + 4 * q);
            if (MODE == 1) { float sc = scl_s[j]; v.x *= sc; v.y *= sc; v.z *= sc; v.w *= sc; }
            uint32_t h0 = bfpair(v.x, v.y);
            uint32_t h1 = bfpair(v.z, v.w);
            uint32_t l0 = bfpair(v.x - __uint_as_float(h0 << 16),
                                 v.y - __uint_as_float(h0 & 0xFFFF0000u));
            uint32_t l1 = bfpair(v.z - __uint_as_float(h1 << 16),
                                 v.w - __uint_as_float(h1 & 0xFFFF0000u));
            *(uint2*)(smc + SM_XH + j * 272 + 8 * q) = make_uint2(h0, h1);
            *(uint2*)(smc + SM_XL + j * 272 + 8 * q) = make_uint2(l0, l1);
        }
        __syncthreads();

        // ---- layer 1: [16x128] @ W1^T cols [nhalf*32, +32) ----
        float a1h[4][4], a1l[4][4];
        ZERO4(a1h, 4); ZERO4(a1l, 4);
        gemmN<8, 2>(sb + SM_XH + (m0 + arow) * 272 + akoff,
                    sb + SM_XL + (m0 + arow) * 272 + akoff,
                    sb + SM_W1H + (nhalf * 32 + brow) * 272 + bkoff,
                    sb + SM_W1L + (nhalf * 32 + brow) * 272 + bkoff, 16 * 272, a1h, a1l);
        epi32(a1h, a1l, b1s, smc + SM_TH, smc + SM_TL, 144, m0, nhalf * 32, g, t);
        __syncthreads();   // T complete across n-halves AND all X reads done (U overlay safe)

        // ---- layer 2: [16x64] @ W2^T cols [nhalf*32, +32) ----
        float a2h[4][4], a2l[4][4];
        ZERO4(a2h, 4); ZERO4(a2l, 4);
        gemmN<4, 2>(sb + SM_TH + (m0 + arow) * 144 + akoff,
                    sb + SM_TL + (m0 + arow) * 144 + akoff,
                    sb + SM_W2H + (nhalf * 32 + brow) * 144 + bkoff,
                    sb + SM_W2L + (nhalf * 32 + brow) * 144 + bkoff, 16 * 144, a2h, a2l);
        // U tiles overlay X region at pitch 144 (X dead for all warps since last barrier)
        epi32(a2h, a2l, b2s, smc + SM_XH, smc + SM_XL, 144, m0, nhalf * 32, g, t);
        // U rows m0..m0+16 produced/consumed only by warp pair {mwarp, mwarp+8}
        asm volatile("bar.sync %0, 64;" :: "r"(mwarp + 1) : "memory");

        // ---- layer 3: [16x64] @ W3^T cols [nhalf*64, +64) -> gmem ----
        float a3h[8][4], a3l[8][4];
        ZERO4(a3h, 8); ZERO4(a3l, 8);
        gemmN<4, 4>(sb + SM_XH + (m0 + arow) * 144 + akoff,
                    sb + SM_XL + (m0 + arow) * 144 + akoff,
                    sb + SM_W3H + (nhalf * 64 + brow) * 144 + bkoff,
                    sb + SM_W3L + (nhalf * 64 + brow) * 144 + bkoff, 16 * 144, a3h, a3l);
        int r0g = rid_s[m0 + g], r1g = rid_s[m0 + 8 + g];
        #pragma unroll
        for (int nt2 = 0; nt2 < 8; nt2++) {
            int c = nhalf * 64 + nt2 * 8 + 2 * t;
            if (r0g >= 0) {
                float2 o;
                o.x = a3h[nt2][0] + a3l[nt2][0] + b3s[c];
                o.y = a3h[nt2][1] + a3l[nt2][1] + b3s[c + 1];
                *(float2*)(outp + (size_t)r0g * 128 + c) = o;
            }
            if (r1g >= 0) {
                float2 o;
                o.x = a3h[nt2][2] + a3l[nt2][2] + b3s[c];
                o.y = a3h[nt2][3] + a3l[nt2][3] + b3s[c + 1];
                *(float2*)(outp + (size_t)r1g * 128 + c) = o;
            }
        }
    }
}

// ================= CSR build =================
__global__ void k_hist(const int* __restrict__ dst, int* __restrict__ deg) {
    int i = blockIdx.x * 1024 + threadIdx.x;
    if (i < EE) atomicAdd(&deg[dst[i]], 1);
}

__global__ void k_scanA(const int* __restrict__ deg, int* __restrict__ bsum) {
    __shared__ int ws[32];
    int i = blockIdx.x * 1024 + threadIdx.x;
    int v = (i < NN) ? deg[i] : 0;
    #pragma unroll
    for (int d = 16; d > 0; d >>= 1) v += __shfl_down_sync(~0u, v, d);
    int lane = threadIdx.x & 31, wid = threadIdx.x >> 5;
    if (lane == 0) ws[wid] = v;
    __syncthreads();
    if (wid == 0) {
        int t = ws[lane];
        #pragma unroll
        for (int d = 16; d > 0; d >>= 1) t += __shfl_down_sync(~0u, t, d);
        if (lane == 0) bsum[blockIdx.x] = t;
    }
}

__global__ void k_scanB(const int* __restrict__ bsum, int* __restrict__ boff) {
    __shared__ int s[128];
    int t = threadIdx.x;
    int v = (t < NBLK_SCAN) ? bsum[t] : 0;
    s[t] = v;
    __syncthreads();
    for (int d = 1; d < 128; d <<= 1) {
        int x = (t >= d) ? s[t - d] : 0;
        __syncthreads();
        s[t] += x;
        __syncthreads();
    }
    if (t < NBLK_SCAN) boff[t] = s[t] - v;   // exclusive
}

__global__ void k_scanC(const int* __restrict__ deg, const int* __restrict__ boff,
                        int* __restrict__ start, int* __restrict__ cursor) {
    __shared__ int ws[32];
    int i = blockIdx.x * 1024 + threadIdx.x;
    int lane = threadIdx.x & 31, wid = threadIdx.x >> 5;
    int v = (i < NN) ? deg[i] : 0;
    int incl = v;
    #pragma unroll
    for (int d = 1; d < 32; d <<= 1) {
        int n = __shfl_up_sync(~0u, incl, d);
        if (lane >= d) incl += n;
    }
    if (lane == 31) ws[wid] = incl;
    __syncthreads();
    if (wid == 0) {
        int wv = ws[lane];
        int wi = wv;
        #pragma unroll
        for (int d = 1; d < 32; d <<= 1) {
            int n = __shfl_up_sync(~0u, wi, d);
            if (lane >= d) wi += n;
        }
        ws[lane] = wi - wv;
    }
    __syncthreads();
    int excl = incl - v + ws[wid] + boff[blockIdx.x];
    if (i < NN) { start[i] = excl; cursor[i] = excl; }
}

__global__ void k_fill(const int* __restrict__ src, const int* __restrict__ dst,
                       const int* __restrict__ r, int* __restrict__ cursor,
                       unsigned* __restrict__ packed) {
    int i = blockIdx.x * 1024 + threadIdx.x;
    if (i >= EE) return;
    int d = dst[i];
    int pos = atomicAdd(&cursor[d], 1);
    packed[pos] = (unsigned)src[i] | ((unsigned)r[i] << 31);
}

__global__ void k_compact(const int* __restrict__ inv, int* __restrict__ list,
                          int* __restrict__ cnt) {
    int i = blockIdx.x * 1024 + threadIdx.x;
    if (i < NN && inv[i] == 1) {
        int pos = atomicAdd(cnt, 1);
        list[pos] = i;
    }
}

// ================= k_gather: warp per node, 128-wide sums =================
__global__ void k_gather(const float* __restrict__ feat, const float* __restrict__ g,
                         const unsigned* __restrict__ packed,
                         const int* __restrict__ start, const int* __restrict__ deg,
                         float* __restrict__ sum) {
    int w = (blockIdx.x * blockDim.x + threadIdx.x) >> 5;
    int lane = threadIdx.x & 31;
    if (w >= NN) return;
    int s0 = start[w];
    int e = s0 + deg[w];
    float4 acc = make_float4(0.f, 0.f, 0.f, 0.f);
    for (int j = s0; j < e; j++) {
        unsigned v = __ldg(&packed[j]);
        const float* rp = ((v >> 31) ? g : feat) + (size_t)(v & 0x7FFFFFFFu) * 128;
        float4 x = *(const float4*)(rp + 4 * lane);
        acc.x += x.x; acc.y += x.y; acc.z += x.z; acc.w += x.w;
    }
    *(float4*)(sum + (size_t)w * 128 + 4 * lane) = acc;
}

// ================= host =================
extern "C" void kernel_launch(void* const* d_in, const int* in_sizes, int n_in,
                              void* d_out, int out_size)
{
    const float* feat = (const float*)d_in[0];
    const int*   src  = (const int*)d_in[1];
    const int*   dst  = (const int*)d_in[2];
    const int*   r    = (const int*)d_in[3];
    const int*   inv  = (const int*)d_in[4];
    const float* iw1 = (const float*)d_in[5];
    const float* ib1 = (const float*)d_in[6];
    const float* iw2 = (const float*)d_in[7];
    const float* ib2 = (const float*)d_in[8];
    const float* iw3 = (const float*)d_in[9];
    const float* ib3 = (const float*)d_in[10];
    const float* aw1 = (const float*)d_in[11];
    const float* ab1 = (const float*)d_in[12];
    const float* aw2 = (const float*)d_in[13];
    const float* ab2 = (const float*)d_in[14];
    const float* aw3 = (const float*)d_in[15];
    const float* ab3 = (const float*)d_in[16];
    float* out = (float*)d_out;

    float *g, *sum;
    unsigned* packed;
    int *deg, *start, *cursor, *bsum, *boff, *list, *cnt;
    cudaGetSymbolAddress((void**)&g, g_g);
    cudaGetSymbolAddress((void**)&sum, g_sum);
    cudaGetSymbolAddress((void**)&packed, g_packed);
    cudaGetSymbolAddress((void**)&deg, g_deg);
    cudaGetSymbolAddress((void**)&start, g_start);
    cudaGetSymbolAddress((void**)&cursor, g_cursor);
    cudaGetSymbolAddress((void**)&bsum, g_bsum);
    cudaGetSymbolAddress((void**)&boff, g_boff);
    cudaGetSymbolAddress((void**)&list, g_list);
    cudaGetSymbolAddress((void**)&cnt, g_cnt);

    cudaFuncSetAttribute(mlp_mma<0>, cudaFuncAttributeMaxDynamicSharedMemorySize, SMEM_BYTES);
    cudaFuncSetAttribute(mlp_mma<1>, cudaFuncAttributeMaxDynamicSharedMemorySize, SMEM_BYTES);
    cudaFuncSetAttribute(mlp_mma<2>, cudaFuncAttributeMaxDynamicSharedMemorySize, SMEM_BYTES);

    cudaMemsetAsync(deg, 0, NN * sizeof(int));                        // launch 0
    cudaMemsetAsync(cnt, 0, sizeof(int));                             // launch 1

    k_hist<<<(EE + 1023) / 1024, 1024>>>(dst, deg);                   // 2
    k_scanA<<<NBLK_SCAN, 1024>>>(deg, bsum);                          // 3
    k_scanB<<<1, 128>>>(bsum, boff);                                  // 4
    mlp_mma<0><<<148, NTHR, SMEM_BYTES>>>(feat, g, iw1, ib1, iw2, ib2, iw3, ib3,
                                          nullptr, nullptr, nullptr); // 5  <- ncu -s 5
    k_scanC<<<NBLK_SCAN, 1024>>>(deg, boff, start, cursor);           // 6
    k_fill<<<(EE + 1023) / 1024, 1024>>>(src, dst, r, cursor, packed);// 7
    k_compact<<<NBLK_SCAN, 1024>>>(inv, list, cnt);                   // 8
    k_gather<<<(NN * 32 + 255) / 256, 256>>>(feat, g, packed, start, deg, sum); // 9
    mlp_mma<1><<<148, NTHR, SMEM_BYTES>>>(sum, out, aw1, ab1, aw2, ab2, aw3, ab3,
                                          deg, nullptr, nullptr);     // 10
    mlp_mma<2><<<148, NTHR, SMEM_BYTES>>>(out, out, iw1, ib1, iw2, ib2, iw3, ib3,
                                          nullptr, list, cnt);        // 11
}

// round 13
// speedup vs baseline: 2.1514x; 1.0089x over previous
#include <cuda_runtime.h>
#include <cuda_bf16.h>
#include <stdint.h>

#define NN 100000
#define EE 800000
#define NBLK_SCAN 98            // ceil(100000/1024)

// ---------------- scratch (device globals; no allocation) ----------------
__device__ float    g_g[(size_t)NN * 128];    // mlp_inv(feat) per node
__device__ float    g_sum[(size_t)NN * 128];  // aggregated 128-wide sums
__device__ unsigned g_packed[EE];             // CSR edge payload: src | (r<<31)
__device__ int      g_deg[NN];
__device__ int      g_start[NN];
__device__ int      g_cursor[NN];
__device__ int      g_bsum[NBLK_SCAN];
__device__ int      g_boff[NBLK_SCAN];
__device__ int      g_list[NN];
__device__ int      g_cnt[1];

__device__ __forceinline__ float lrelu(float v) { return v >= 0.0f ? v : 0.01f * v; }

__device__ __forceinline__ uint32_t smem_u32(const void* p) {
    uint32_t a;
    asm("{ .reg .u64 t; cvta.to.shared.u64 t, %1; cvt.u32.u64 %0, t; }" : "=r"(a) : "l"(p));
    return a;
}

// packed bf16x2: low 16 bits = bf16(vlo), high 16 bits = bf16(vhi)
__device__ __forceinline__ uint32_t bfpair(float vlo, float vhi) {
    uint32_t r;
    asm("cvt.rn.bf16x2.f32 %0, %1, %2;" : "=r"(r) : "f"(vhi), "f"(vlo));
    return r;
}

__device__ __forceinline__ void ldsm4(uint32_t &r0, uint32_t &r1, uint32_t &r2, uint32_t &r3,
                                      uint32_t a) {
    asm volatile("ldmatrix.sync.aligned.m8n8.x4.shared.b16 {%0,%1,%2,%3}, [%4];"
                 : "=r"(r0), "=r"(r1), "=r"(r2), "=r"(r3) : "r"(a));
}

__device__ __forceinline__ void mma_bf16(float d[4],
                                         uint32_t a0, uint32_t a1, uint32_t a2, uint32_t a3,
                                         uint32_t b0, uint32_t b1) {
    asm volatile("mma.sync.aligned.m16n8k16.row.col.f32.bf16.bf16.f32 "
                 "{%0,%1,%2,%3}, {%4,%5,%6,%7}, {%8,%9}, {%0,%1,%2,%3};"
                 : "+f"(d[0]), "+f"(d[1]), "+f"(d[2]), "+f"(d[3])
                 : "r"(a0), "r"(a1), "r"(a2), "r"(a3), "r"(b0), "r"(b1));
}

// ---------------- smem byte offsets ----------------
// pitches: X/W1 = 272 B (17x16B, odd -> conflict-free ldmatrix); 64-col tiles = 144 B (9x16B)
#define SM_RID  0          // 128 ints
#define SM_SRC  512
#define SM_SCL  1024
#define SM_B1   1536       // 64 f32
#define SM_B2   1792
#define SM_B3   2048       // 128 f32
#define SM_W1H  2560       // 64 x 272
#define SM_W1L  19968
#define SM_W2H  37376      // 64 x 144
#define SM_W2L  46592
#define SM_W3H  55808      // 128 x 144
#define SM_W3L  74240
#define SM_TH   92672      // 128 x 144
#define SM_TL   111104
#define SM_XH   129536     // 128 x 272 (U hi overlays @144 pitch)
#define SM_XL   164352
#define SMEM_BYTES 199168

#define NTHR 512

// stage fp32 weights [OUT][K] -> hi/lo bf16 pitched tiles
__device__ void stage_w(char* hi, char* lo, const float* __restrict__ w,
                        int OUT, int K, int pitch, int tid) {
    for (int i = tid; i < OUT * K; i += NTHR) {
        int o = i / K, k = i - o * K;
        float v = w[i];
        __nv_bfloat16 hb = __float2bfloat16(v);
        __nv_bfloat16 lb = __float2bfloat16(v - __bfloat162float(hb));
        *(__nv_bfloat16*)(hi + o * pitch + k * 2) = hb;
        *(__nv_bfloat16*)(lo + o * pitch + k * 2) = lb;
    }
}

// warp GEMM: A (16 rows) x B (NTILES*16 cols), hi/lo 3-pass, software-pipelined:
// A fragments double-buffered by k parity, B fragments by step parity; the ldsm
// for step i+1 issues before the MMAs of step i so LDS latency overlaps compute.
template<int KSTEPS, int NTILES>
__device__ __forceinline__ void gemmN(uint32_t aH, uint32_t aL,
                                      uint32_t bH, uint32_t bL, int bstep16,
                                      float acc[][4]) {
    uint32_t ah[2][4], al[2][4], bh[2][4], bl[2][4];
    ldsm4(ah[0][0], ah[0][1], ah[0][2], ah[0][3], aH);
    ldsm4(al[0][0], al[0][1], al[0][2], al[0][3], aL);
    ldsm4(bh[0][0], bh[0][1], bh[0][2], bh[0][3], bH);
    ldsm4(bl[0][0], bl[0][1], bl[0][2], bl[0][3], bL);
    const int total = KSTEPS * NTILES;
    #pragma unroll
    for (int idx = 0; idx < total; idx++) {
        const int k = idx / NTILES, np = idx % NTILES;
        const int ka = k & 1, ib = idx & 1;
        if (idx + 1 < total) {
            const int k2 = (idx + 1) / NTILES, np2 = (idx + 1) % NTILES;
            const int ka2 = k2 & 1, ib2 = (idx + 1) & 1;
            ldsm4(bh[ib2][0], bh[ib2][1], bh[ib2][2], bh[ib2][3],
                  bH + np2 * bstep16 + k2 * 32);
            ldsm4(bl[ib2][0], bl[ib2][1], bl[ib2][2], bl[ib2][3],
                  bL + np2 * bstep16 + k2 * 32);
            if (np2 == 0) {
                ldsm4(ah[ka2][0], ah[ka2][1], ah[ka2][2], ah[ka2][3], aH + k2 * 32);
                ldsm4(al[ka2][0], al[ka2][1], al[ka2][2], al[ka2][3], aL + k2 * 32);
            }
        }
        mma_bf16(acc[2*np],   ah[ka][0], ah[ka][1], ah[ka][2], ah[ka][3], bh[ib][0], bh[ib][1]);
        mma_bf16(acc[2*np+1], ah[ka][0], ah[ka][1], ah[ka][2], ah[ka][3], bh[ib][2], bh[ib][3]);
        mma_bf16(acc[2*np],   al[ka][0], al[ka][1], al[ka][2], al[ka][3], bh[ib][0], bh[ib][1]);
        mma_bf16(acc[2*np+1], al[ka][0], al[ka][1], al[ka][2], al[ka][3], bh[ib][2], bh[ib][3]);
        mma_bf16(acc[2*np],   ah[ka][0], ah[ka][1], ah[ka][2], ah[ka][3], bl[ib][0], bl[ib][1]);
        mma_bf16(acc[2*np+1], ah[ka][0], ah[ka][1], ah[ka][2], ah[ka][3], bl[ib][2], bl[ib][3]);
    }
}

// 32-col epilogue: acc + bias + lrelu + hi/lo bf16 store at column offset ncol0
__device__ __forceinline__ void epi32(const float acc[4][4],
                                      const float* __restrict__ bias,
                                      char* tH, char* tL, int pitch, int m0, int ncol0,
                                      int g, int t) {
    #pragma unroll
    for (int nt2 = 0; nt2 < 4; nt2++) {
        int c = ncol0 + nt2 * 8 + 2 * t;
        float v0 = lrelu(acc[nt2][0] + bias[c]);
        float v1 = lrelu(acc[nt2][1] + bias[c + 1]);
        float v2 = lrelu(acc[nt2][2] + bias[c]);
        float v3 = lrelu(acc[nt2][3] + bias[c + 1]);
        uint32_t h0 = bfpair(v0, v1);
        uint32_t l0 = bfpair(v0 - __uint_as_float(h0 << 16),
                             v1 - __uint_as_float(h0 & 0xFFFF0000u));
        uint32_t h1 = bfpair(v2, v3);
        uint32_t l1 = bfpair(v2 - __uint_as_float(h1 << 16),
                             v3 - __uint_as_float(h1 & 0xFFFF0000u));
        *(uint32_t*)(tH + (m0 + g) * pitch + c * 2)     = h0;
        *(uint32_t*)(tL + (m0 + g) * pitch + c * 2)     = l0;
        *(uint32_t*)(tH + (m0 + 8 + g) * pitch + c * 2) = h1;
        *(uint32_t*)(tL + (m0 + 8 + g) * pitch + c * 2) = l1;
    }
}

#define ZERO4(a, n) { _Pragma("unroll") for (int i = 0; i < n; i++) { (a)[i][0]=0.f; (a)[i][1]=0.f; (a)[i][2]=0.f; (a)[i][3]=0.f; } }

// ================= fused 3-layer MLP via mma.sync bf16 hi/lo, 16 warps N-split ======
// MODE 0: rows 0..NN-1. MODE 1: in scaled by 1/max(deg,1). MODE 2: rows from list.
template <int MODE>
__global__ void __launch_bounds__(NTHR, 1) mlp_mma(
    const float* __restrict__ in, float* __restrict__ outp,
    const float* __restrict__ w1, const float* __restrict__ b1,
    const float* __restrict__ w2, const float* __restrict__ b2,
    const float* __restrict__ w3, const float* __restrict__ b3,
    const int* __restrict__ deg, const int* __restrict__ list,
    const int* __restrict__ cnt)
{
    extern __shared__ char smc[];
    const uint32_t sb = smem_u32(smc);
    const int tid = threadIdx.x, wid = tid >> 5, lane = tid & 31;

    stage_w(smc + SM_W1H, smc + SM_W1L, w1, 64, 128, 272, tid);
    stage_w(smc + SM_W2H, smc + SM_W2L, w2, 64, 64, 144, tid);
    stage_w(smc + SM_W3H, smc + SM_W3L, w3, 128, 64, 144, tid);
    float* b1s = (float*)(smc + SM_B1);
    float* b2s = (float*)(smc + SM_B2);
    float* b3s = (float*)(smc + SM_B3);
    for (int i = tid; i < 64; i += NTHR) { b1s[i] = b1[i]; b2s[i] = b2[i]; }
    for (int i = tid; i < 128; i += NTHR) b3s[i] = b3[i];

    int* rid_s = (int*)(smc + SM_RID);
    int* src_s = (int*)(smc + SM_SRC);
    float* scl_s = (float*)(smc + SM_SCL);
    __syncthreads();

    const int nrows = (MODE == 2) ? *cnt : NN;
    const int ntile = (nrows + 127) >> 7;

    const int arow = (lane & 7) + ((lane >> 3) & 1) * 8;
    const int akoff = (lane >> 4) * 16;
    const int brow = (lane & 7) + ((lane >> 4) & 1) * 8;
    const int bkoff = ((lane >> 3) & 1) * 16;
    const int mwarp = wid & 7, nhalf = wid >> 3;
    const int m0 = mwarp * 16;
    const int g = lane >> 2, t = lane & 3;

    for (int tile = blockIdx.x; tile < ntile; tile += gridDim.x) {
        int base = tile << 7;
        __syncthreads();                   // prev tile fully consumed
        if (tid < 128) {
            int row = base + tid;
            int rowid, srow; float sc = 1.0f;
            if (MODE == 2) {
                rowid = (row < nrows) ? list[row] : -1;
                srow = (rowid >= 0) ? rowid : list[base];
            } else {
                rowid = (row < NN) ? row : -1;
                srow = (rowid >= 0) ? rowid : (NN - 1);
            }
            if (MODE == 1) { int dg = deg[srow]; sc = 1.0f / (float)(dg < 1 ? 1 : dg); }
            rid_s[tid] = rowid; src_s[tid] = srow; scl_s[tid] = sc;
        }
        __syncthreads();
        // ---- stage X: fp32 -> hi/lo bf16 pitched tiles ----
        for (int idx = tid; idx < 128 * 32; idx += NTHR) {
            int j = idx >> 5, q = idx & 31;
            float4 v = *(const float4*)(in + (size_t)src_s[j] * 128 + 4 * q);
            if (MODE == 1) { float sc = scl_s[j]; v.x *= sc; v.y *= sc; v.z *= sc; v.w *= sc; }
            uint32_t h0 = bfpair(v.x, v.y);
            uint32_t h1 = bfpair(v.z, v.w);
            uint32_t l0 = bfpair(v.x - __uint_as_float(h0 << 16),
                                 v.y - __uint_as_float(h0 & 0xFFFF0000u));
            uint32_t l1 = bfpair(v.z - __uint_as_float(h1 << 16),
                                 v.w - __uint_as_float(h1 & 0xFFFF0000u));
            *(uint2*)(smc + SM_XH + j * 272 + 8 * q) = make_uint2(h0, h1);
            *(uint2*)(smc + SM_XL + j * 272 + 8 * q) = make_uint2(l0, l1);
        }
        __syncthreads();

        // ---- layer 1: [16x128] @ W1^T cols [nhalf*32, +32) ----
        float acc1[4][4];
        ZERO4(acc1, 4);
        gemmN<8, 2>(sb + SM_XH + (m0 + arow) * 272 + akoff,
                    sb + SM_XL + (m0 + arow) * 272 + akoff,
                    sb + SM_W1H + (nhalf * 32 + brow) * 272 + bkoff,
                    sb + SM_W1L + (nhalf * 32 + brow) * 272 + bkoff, 16 * 272, acc1);
        epi32(acc1, b1s, smc + SM_TH, smc + SM_TL, 144, m0, nhalf * 32, g, t);
        __syncthreads();   // T complete across n-halves AND all X reads done (U overlay safe)

        // ---- layer 2: [16x64] @ W2^T cols [nhalf*32, +32) ----
        float acc2[4][4];
        ZERO4(acc2, 4);
        gemmN<4, 2>(sb + SM_TH + (m0 + arow) * 144 + akoff,
                    sb + SM_TL + (m0 + arow) * 144 + akoff,
                    sb + SM_W2H + (nhalf * 32 + brow) * 144 + bkoff,
                    sb + SM_W2L + (nhalf * 32 + brow) * 144 + bkoff, 16 * 144, acc2);
        // U tiles overlay X region at pitch 144 (X dead for all warps since last barrier)
        epi32(acc2, b2s, smc + SM_XH, smc + SM_XL, 144, m0, nhalf * 32, g, t);
        // U rows m0..m0+16 produced/consumed only by warp pair {mwarp, mwarp+8}
        asm volatile("bar.sync %0, 64;" :: "r"(mwarp + 1) : "memory");

        // ---- layer 3: [16x64] @ W3^T cols [nhalf*64, +64) -> gmem ----
        float acc3[8][4];
        ZERO4(acc3, 8);
        gemmN<4, 4>(sb + SM_XH + (m0 + arow) * 144 + akoff,
                    sb + SM_XL + (m0 + arow) * 144 + akoff,
                    sb + SM_W3H + (nhalf * 64 + brow) * 144 + bkoff,
                    sb + SM_W3L + (nhalf * 64 + brow) * 144 + bkoff, 16 * 144, acc3);
        int r0g = rid_s[m0 + g], r1g = rid_s[m0 + 8 + g];
        #pragma unroll
        for (int nt2 = 0; nt2 < 8; nt2++) {
            int c = nhalf * 64 + nt2 * 8 + 2 * t;
            if (r0g >= 0) {
                float2 o;
                o.x = acc3[nt2][0] + b3s[c];
                o.y = acc3[nt2][1] + b3s[c + 1];
                *(float2*)(outp + (size_t)r0g * 128 + c) = o;
            }
            if (r1g >= 0) {
                float2 o;
                o.x = acc3[nt2][2] + b3s[c];
                o.y = acc3[nt2][3] + b3s[c + 1];
                *(float2*)(outp + (size_t)r1g * 128 + c) = o;
            }
        }
    }
}

// ================= CSR build =================
__global__ void k_hist(const int* __restrict__ dst, int* __restrict__ deg) {
    int i = blockIdx.x * 1024 + threadIdx.x;
    if (i < EE) atomicAdd(&deg[dst[i]], 1);
}

__global__ void k_scanA(const int* __restrict__ deg, int* __restrict__ bsum) {
    __shared__ int ws[32];
    int i = blockIdx.x * 1024 + threadIdx.x;
    int v = (i < NN) ? deg[i] : 0;
    #pragma unroll
    for (int d = 16; d > 0; d >>= 1) v += __shfl_down_sync(~0u, v, d);
    int lane = threadIdx.x & 31, wid = threadIdx.x >> 5;
    if (lane == 0) ws[wid] = v;
    __syncthreads();
    if (wid == 0) {
        int t = ws[lane];
        #pragma unroll
        for (int d = 16; d > 0; d >>= 1) t += __shfl_down_sync(~0u, t, d);
        if (lane == 0) bsum[blockIdx.x] = t;
    }
}

__global__ void k_scanB(const int* __restrict__ bsum, int* __restrict__ boff) {
    __shared__ int s[128];
    int t = threadIdx.x;
    int v = (t < NBLK_SCAN) ? bsum[t] : 0;
    s[t] = v;
    __syncthreads();
    for (int d = 1; d < 128; d <<= 1) {
        int x = (t >= d) ? s[t - d] : 0;
        __syncthreads();
        s[t] += x;
        __syncthreads();
    }
    if (t < NBLK_SCAN) boff[t] = s[t] - v;   // exclusive
}

__global__ void k_scanC(const int* __restrict__ deg, const int* __restrict__ boff,
                        int* __restrict__ start, int* __restrict__ cursor) {
    __shared__ int ws[32];
    int i = blockIdx.x * 1024 + threadIdx.x;
    int lane = threadIdx.x & 31, wid = threadIdx.x >> 5;
    int v = (i < NN) ? deg[i] : 0;
    int incl = v;
    #pragma unroll
    for (int d = 1; d < 32; d <<= 1) {
        int n = __shfl_up_sync(~0u, incl, d);
        if (lane >= d) incl += n;
    }
    if (lane == 31) ws[wid] = incl;
    __syncthreads();
    if (wid == 0) {
        int wv = ws[lane];
        int wi = wv;
        #pragma unroll
        for (int d = 1; d < 32; d <<= 1) {
            int n = __shfl_up_sync(~0u, wi, d);
            if (lane >= d) wi += n;
        }
        ws[lane] = wi - wv;
    }
    __syncthreads();
    int excl = incl - v + ws[wid] + boff[blockIdx.x];
    if (i < NN) { start[i] = excl; cursor[i] = excl; }
}

__global__ void k_fill(const int* __restrict__ src, const int* __restrict__ dst,
                       const int* __restrict__ r, int* __restrict__ cursor,
                       unsigned* __restrict__ packed) {
    int i = blockIdx.x * 1024 + threadIdx.x;
    if (i >= EE) return;
    int d = dst[i];
    int pos = atomicAdd(&cursor[d], 1);
    packed[pos] = (unsigned)src[i] | ((unsigned)r[i] << 31);
}

__global__ void k_compact(const int* __restrict__ inv, int* __restrict__ list,
                          int* __restrict__ cnt) {
    int i = blockIdx.x * 1024 + threadIdx.x;
    if (i < NN && inv[i] == 1) {
        int pos = atomicAdd(cnt, 1);
        list[pos] = i;
    }
}

// ================= k_gather: warp per node, 128-wide sums =================
__global__ void k_gather(const float* __restrict__ feat, const float* __restrict__ g,
                         const unsigned* __restrict__ packed,
                         const int* __restrict__ start, const int* __restrict__ deg,
                         float* __restrict__ sum) {
    int w = (blockIdx.x * blockDim.x + threadIdx.x) >> 5;
    int lane = threadIdx.x & 31;
    if (w >= NN) return;
    int s0 = start[w];
    int e = s0 + deg[w];
    float4 acc = make_float4(0.f, 0.f, 0.f, 0.f);
    for (int j = s0; j < e; j++) {
        unsigned v = __ldg(&packed[j]);
        const float* rp = ((v >> 31) ? g : feat) + (size_t)(v & 0x7FFFFFFFu) * 128;
        float4 x = *(const float4*)(rp + 4 * lane);
        acc.x += x.x; acc.y += x.y; acc.z += x.z; acc.w += x.w;
    }
    *(float4*)(sum + (size_t)w * 128 + 4 * lane) = acc;
}

// ================= host =================
extern "C" void kernel_launch(void* const* d_in, const int* in_sizes, int n_in,
                              void* d_out, int out_size)
{
    const float* feat = (const float*)d_in[0];
    const int*   src  = (const int*)d_in[1];
    const int*   dst  = (const int*)d_in[2];
    const int*   r    = (const int*)d_in[3];
    const int*   inv  = (const int*)d_in[4];
    const float* iw1 = (const float*)d_in[5];
    const float* ib1 = (const float*)d_in[6];
    const float* iw2 = (const float*)d_in[7];
    const float* ib2 = (const float*)d_in[8];
    const float* iw3 = (const float*)d_in[9];
    const float* ib3 = (const float*)d_in[10];
    const float* aw1 = (const float*)d_in[11];
    const float* ab1 = (const float*)d_in[12];
    const float* aw2 = (const float*)d_in[13];
    const float* ab2 = (const float*)d_in[14];
    const float* aw3 = (const float*)d_in[15];
    const float* ab3 = (const float*)d_in[16];
    float* out = (float*)d_out;

    float *g, *sum;
    unsigned* packed;
    int *deg, *start, *cursor, *bsum, *boff, *list, *cnt;
    cudaGetSymbolAddress((void**)&g, g_g);
    cudaGetSymbolAddress((void**)&sum, g_sum);
    cudaGetSymbolAddress((void**)&packed, g_packed);
    cudaGetSymbolAddress((void**)&deg, g_deg);
    cudaGetSymbolAddress((void**)&start, g_start);
    cudaGetSymbolAddress((void**)&cursor, g_cursor);
    cudaGetSymbolAddress((void**)&bsum, g_bsum);
    cudaGetSymbolAddress((void**)&boff, g_boff);
    cudaGetSymbolAddress((void**)&list, g_list);
    cudaGetSymbolAddress((void**)&cnt, g_cnt);

    cudaFuncSetAttribute(mlp_mma<0>, cudaFuncAttributeMaxDynamicSharedMemorySize, SMEM_BYTES);
    cudaFuncSetAttribute(mlp_mma<1>, cudaFuncAttributeMaxDynamicSharedMemorySize, SMEM_BYTES);
    cudaFuncSetAttribute(mlp_mma<2>, cudaFuncAttributeMaxDynamicSharedMemorySize, SMEM_BYTES);

    cudaMemsetAsync(deg, 0, NN * sizeof(int));                        // launch 0
    cudaMemsetAsync(cnt, 0, sizeof(int));                             // launch 1

    k_hist<<<(EE + 1023) / 1024, 1024>>>(dst, deg);                   // 2
    k_scanA<<<NBLK_SCAN, 1024>>>(deg, bsum);                          // 3
    k_scanB<<<1, 128>>>(bsum, boff);                                  // 4
    mlp_mma<0><<<148, NTHR, SMEM_BYTES>>>(feat, g, iw1, ib1, iw2, ib2, iw3, ib3,
                                          nullptr, nullptr, nullptr); // 5  <- ncu -s 5
    k_scanC<<<NBLK_SCAN, 1024>>>(deg, boff, start, cursor);           // 6
    k_fill<<<(EE + 1023) / 1024, 1024>>>(src, dst, r, cursor, packed);// 7
    k_compact<<<NBLK_SCAN, 1024>>>(inv, list, cnt);                   // 8
    k_gather<<<(NN * 32 + 255) / 256, 256>>>(feat, g, packed, start, deg, sum); // 9
    mlp_mma<1><<<148, NTHR, SMEM_BYTES>>>(sum, out, aw1, ab1, aw2, ab2, aw3, ab3,
                                          deg, nullptr, nullptr);     // 10
    mlp_mma<2><<<148, NTHR, SMEM_BYTES>>>(out, out, iw1, ib1, iw2, ib2, iw3, ib3,
                                          nullptr, list, cnt);        // 11
}

// round 14
// speedup vs baseline: 2.3249x; 1.0806x over previous
#include <cuda_runtime.h>
#include <cuda_fp16.h>
#include <stdint.h>

#define NN 100000
#define EE 800000
#define NBLK_SCAN 98            // ceil(100000/1024)

// ---------------- scratch (device globals; no allocation) ----------------
__device__ float    g_g[(size_t)NN * 128];    // mlp_inv(feat) per node
__device__ float    g_sum[(size_t)NN * 128];  // aggregated 128-wide sums
__device__ unsigned g_packed[EE];             // CSR edge payload: src | (r<<31)
__device__ int      g_deg[NN];
__device__ int      g_start[NN];
__device__ int      g_cursor[NN];
__device__ int      g_bsum[NBLK_SCAN];
__device__ int      g_boff[NBLK_SCAN];
__device__ int      g_list[NN];
__device__ int      g_cnt[1];

__device__ __forceinline__ float lrelu(float v) { return v >= 0.0f ? v : 0.01f * v; }

__device__ __forceinline__ uint32_t smem_u32(const void* p) {
    uint32_t a;
    asm("{ .reg .u64 t; cvta.to.shared.u64 t, %1; cvt.u32.u64 %0, t; }" : "=r"(a) : "l"(p));
    return a;
}

__device__ __forceinline__ uint32_t h2u(__half2 h) {
    return *reinterpret_cast<uint32_t*>(&h);
}

__device__ __forceinline__ void ldsm4(uint32_t &r0, uint32_t &r1, uint32_t &r2, uint32_t &r3,
                                      uint32_t a) {
    asm volatile("ldmatrix.sync.aligned.m8n8.x4.shared.b16 {%0,%1,%2,%3}, [%4];"
                 : "=r"(r0), "=r"(r1), "=r"(r2), "=r"(r3) : "r"(a));
}

__device__ __forceinline__ void mma_f16(float d[4],
                                        uint32_t a0, uint32_t a1, uint32_t a2, uint32_t a3,
                                        uint32_t b0, uint32_t b1) {
    asm volatile("mma.sync.aligned.m16n8k16.row.col.f32.f16.f16.f32 "
                 "{%0,%1,%2,%3}, {%4,%5,%6,%7}, {%8,%9}, {%0,%1,%2,%3};"
                 : "+f"(d[0]), "+f"(d[1]), "+f"(d[2]), "+f"(d[3])
                 : "r"(a0), "r"(a1), "r"(a2), "r"(a3), "r"(b0), "r"(b1));
}

// ---------------- smem byte offsets ----------------
// pitches: X/W1 = 272 B (17x16B, odd -> conflict-free ldmatrix); 64-col tiles = 144 B
// fp16 2-pass: weights stored HI ONLY; activations stored hi+lo.
#define SM_RID  0          // 128 ints
#define SM_SRC  512
#define SM_SCL  1024
#define SM_B1   1536       // 64 f32
#define SM_B2   1792
#define SM_B3   2048       // 128 f32
#define SM_W1H  2560       // 64 x 272
#define SM_W2H  19968      // 64 x 144
#define SM_W3H  29184      // 128 x 144
#define SM_TH   47616      // 128 x 144
#define SM_TL   66048
#define SM_XH   84480      // 128 x 272 (U hi overlays @144 pitch)
#define SM_XL   119296
#define SMEM_BYTES 154112

#define NTHR 512

// stage fp32 weights [OUT][K] -> fp16 hi pitched tile
__device__ void stage_w(char* hi, const float* __restrict__ w,
                        int OUT, int K, int pitch, int tid) {
    for (int i = tid; i < OUT * K; i += NTHR) {
        int o = i / K, k = i - o * K;
        *(__half*)(hi + o * pitch + k * 2) = __float2half_rn(w[i]);
    }
}

// warp GEMM: A (16 rows, hi+lo fp16) x B (NTILES*16 cols, hi fp16), 2-pass,
// software-pipelined (A frags by k parity, B frags by step parity).
template<int KSTEPS, int NTILES>
__device__ __forceinline__ void gemmN(uint32_t aH, uint32_t aL,
                                      uint32_t bH, int bstep16,
                                      float acc[][4]) {
    uint32_t ah[2][4], al[2][4], bh[2][4];
    ldsm4(ah[0][0], ah[0][1], ah[0][2], ah[0][3], aH);
    ldsm4(al[0][0], al[0][1], al[0][2], al[0][3], aL);
    ldsm4(bh[0][0], bh[0][1], bh[0][2], bh[0][3], bH);
    const int total = KSTEPS * NTILES;
    #pragma unroll
    for (int idx = 0; idx < total; idx++) {
        const int k = idx / NTILES, np = idx % NTILES;
        const int ka = k & 1, ib = idx & 1;
        if (idx + 1 < total) {
            const int k2 = (idx + 1) / NTILES, np2 = (idx + 1) % NTILES;
            const int ka2 = k2 & 1, ib2 = (idx + 1) & 1;
            ldsm4(bh[ib2][0], bh[ib2][1], bh[ib2][2], bh[ib2][3],
                  bH + np2 * bstep16 + k2 * 32);
            if (np2 == 0) {
                ldsm4(ah[ka2][0], ah[ka2][1], ah[ka2][2], ah[ka2][3], aH + k2 * 32);
                ldsm4(al[ka2][0], al[ka2][1], al[ka2][2], al[ka2][3], aL + k2 * 32);
            }
        }
        mma_f16(acc[2*np],   ah[ka][0], ah[ka][1], ah[ka][2], ah[ka][3], bh[ib][0], bh[ib][1]);
        mma_f16(acc[2*np+1], ah[ka][0], ah[ka][1], ah[ka][2], ah[ka][3], bh[ib][2], bh[ib][3]);
        mma_f16(acc[2*np],   al[ka][0], al[ka][1], al[ka][2], al[ka][3], bh[ib][0], bh[ib][1]);
        mma_f16(acc[2*np+1], al[ka][0], al[ka][1], al[ka][2], al[ka][3], bh[ib][2], bh[ib][3]);
    }
}

// 32-col epilogue: acc + bias + lrelu -> fp16 hi/lo tiles at column offset ncol0
__device__ __forceinline__ void epi32(const float acc[4][4],
                                      const float* __restrict__ bias,
                                      char* tH, char* tL, int pitch, int m0, int ncol0,
                                      int g, int t) {
    #pragma unroll
    for (int nt2 = 0; nt2 < 4; nt2++) {
        int c = ncol0 + nt2 * 8 + 2 * t;
        float v0 = lrelu(acc[nt2][0] + bias[c]);
        float v1 = lrelu(acc[nt2][1] + bias[c + 1]);
        float v2 = lrelu(acc[nt2][2] + bias[c]);
        float v3 = lrelu(acc[nt2][3] + bias[c + 1]);
        __half2 H0 = __floats2half2_rn(v0, v1);
        float2  F0 = __half22float2(H0);
        __half2 L0 = __floats2half2_rn(v0 - F0.x, v1 - F0.y);
        __half2 H1 = __floats2half2_rn(v2, v3);
        float2  F1 = __half22float2(H1);
        __half2 L1 = __floats2half2_rn(v2 - F1.x, v3 - F1.y);
        *(uint32_t*)(tH + (m0 + g) * pitch + c * 2)     = h2u(H0);
        *(uint32_t*)(tL + (m0 + g) * pitch + c * 2)     = h2u(L0);
        *(uint32_t*)(tH + (m0 + 8 + g) * pitch + c * 2) = h2u(H1);
        *(uint32_t*)(tL + (m0 + 8 + g) * pitch + c * 2) = h2u(L1);
    }
}

#define ZERO4(a, n) { _Pragma("unroll") for (int i = 0; i < n; i++) { (a)[i][0]=0.f; (a)[i][1]=0.f; (a)[i][2]=0.f; (a)[i][3]=0.f; } }

// ================= fused 3-layer MLP via mma.sync fp16 2-pass, 16 warps N-split ====
// MODE 0: rows 0..NN-1. MODE 1: in scaled by 1/max(deg,1). MODE 2: rows from list.
template <int MODE>
__global__ void __launch_bounds__(NTHR, 1) mlp_mma(
    const float* __restrict__ in, float* __restrict__ outp,
    const float* __restrict__ w1, const float* __restrict__ b1,
    const float* __restrict__ w2, const float* __restrict__ b2,
    const float* __restrict__ w3, const float* __restrict__ b3,
    const int* __restrict__ deg, const int* __restrict__ list,
    const int* __restrict__ cnt)
{
    extern __shared__ char smc[];
    const uint32_t sb = smem_u32(smc);
    const int tid = threadIdx.x, wid = tid >> 5, lane = tid & 31;

    stage_w(smc + SM_W1H, w1, 64, 128, 272, tid);
    stage_w(smc + SM_W2H, w2, 64, 64, 144, tid);
    stage_w(smc + SM_W3H, w3, 128, 64, 144, tid);
    float* b1s = (float*)(smc + SM_B1);
    float* b2s = (float*)(smc + SM_B2);
    float* b3s = (float*)(smc + SM_B3);
    for (int i = tid; i < 64; i += NTHR) { b1s[i] = b1[i]; b2s[i] = b2[i]; }
    for (int i = tid; i < 128; i += NTHR) b3s[i] = b3[i];

    int* rid_s = (int*)(smc + SM_RID);
    int* src_s = (int*)(smc + SM_SRC);
    float* scl_s = (float*)(smc + SM_SCL);
    __syncthreads();

    const int nrows = (MODE == 2) ? *cnt : NN;
    const int ntile = (nrows + 127) >> 7;

    const int arow = (lane & 7) + ((lane >> 3) & 1) * 8;
    const int akoff = (lane >> 4) * 16;
    const int brow = (lane & 7) + ((lane >> 4) & 1) * 8;
    const int bkoff = ((lane >> 3) & 1) * 16;
    const int mwarp = wid & 7, nhalf = wid >> 3;
    const int m0 = mwarp * 16;
    const int g = lane >> 2, t = lane & 3;

    for (int tile = blockIdx.x; tile < ntile; tile += gridDim.x) {
        int base = tile << 7;
        __syncthreads();                   // prev tile fully consumed
        if (tid < 128) {
            int row = base + tid;
            int rowid, srow; float sc = 1.0f;
            if (MODE == 2) {
                rowid = (row < nrows) ? list[row] : -1;
                srow = (rowid >= 0) ? rowid : list[base];
            } else {
                rowid = (row < NN) ? row : -1;
                srow = (rowid >= 0) ? rowid : (NN - 1);
            }
            if (MODE == 1) { int dg = deg[srow]; sc = 1.0f / (float)(dg < 1 ? 1 : dg); }
            rid_s[tid] = rowid; src_s[tid] = srow; scl_s[tid] = sc;
        }
        __syncthreads();
        // ---- stage X: fp32 -> fp16 hi/lo pitched tiles ----
        for (int idx = tid; idx < 128 * 32; idx += NTHR) {
            int j = idx >> 5, q = idx & 31;
            float4 v = *(const float4*)(in + (size_t)src_s[j] * 128 + 4 * q);
            if (MODE == 1) { float sc = scl_s[j]; v.x *= sc; v.y *= sc; v.z *= sc; v.w *= sc; }
            __half2 Ha = __floats2half2_rn(v.x, v.y);
            float2  Fa = __half22float2(Ha);
            __half2 La = __floats2half2_rn(v.x - Fa.x, v.y - Fa.y);
            __half2 Hb = __floats2half2_rn(v.z, v.w);
            float2  Fb = __half22float2(Hb);
            __half2 Lb = __floats2half2_rn(v.z - Fb.x, v.w - Fb.y);
            *(uint2*)(smc + SM_XH + j * 272 + 8 * q) = make_uint2(h2u(Ha), h2u(Hb));
            *(uint2*)(smc + SM_XL + j * 272 + 8 * q) = make_uint2(h2u(La), h2u(Lb));
        }
        __syncthreads();

        // ---- layer 1: [16x128] @ W1^T cols [nhalf*32, +32) ----
        float acc1[4][4];
        ZERO4(acc1, 4);
        gemmN<8, 2>(sb + SM_XH + (m0 + arow) * 272 + akoff,
                    sb + SM_XL + (m0 + arow) * 272 + akoff,
                    sb + SM_W1H + (nhalf * 32 + brow) * 272 + bkoff, 16 * 272, acc1);
        epi32(acc1, b1s, smc + SM_TH, smc + SM_TL, 144, m0, nhalf * 32, g, t);
        __syncthreads();   // T complete across n-halves AND all X reads done (U overlay safe)

        // ---- layer 2: [16x64] @ W2^T cols [nhalf*32, +32) ----
        float acc2[4][4];
        ZERO4(acc2, 4);
        gemmN<4, 2>(sb + SM_TH + (m0 + arow) * 144 + akoff,
                    sb + SM_TL + (m0 + arow) * 144 + akoff,
                    sb + SM_W2H + (nhalf * 32 + brow) * 144 + bkoff, 16 * 144, acc2);
        // U tiles overlay X region at pitch 144 (X dead for all warps since last barrier)
        epi32(acc2, b2s, smc + SM_XH, smc + SM_XL, 144, m0, nhalf * 32, g, t);
        // U rows m0..m0+16 produced/consumed only by warp pair {mwarp, mwarp+8}
        asm volatile("bar.sync %0, 64;" :: "r"(mwarp + 1) : "memory");

        // ---- layer 3: [16x64] @ W3^T cols [nhalf*64, +64) -> gmem ----
        float acc3[8][4];
        ZERO4(acc3, 8);
        gemmN<4, 4>(sb + SM_XH + (m0 + arow) * 144 + akoff,
                    sb + SM_XL + (m0 + arow) * 144 + akoff,
                    sb + SM_W3H + (nhalf * 64 + brow) * 144 + bkoff, 16 * 144, acc3);
        int r0g = rid_s[m0 + g], r1g = rid_s[m0 + 8 + g];
        #pragma unroll
        for (int nt2 = 0; nt2 < 8; nt2++) {
            int c = nhalf * 64 + nt2 * 8 + 2 * t;
            if (r0g >= 0) {
                float2 o;
                o.x = acc3[nt2][0] + b3s[c];
                o.y = acc3[nt2][1] + b3s[c + 1];
                *(float2*)(outp + (size_t)r0g * 128 + c) = o;
            }
            if (r1g >= 0) {
                float2 o;
                o.x = acc3[nt2][2] + b3s[c];
                o.y = acc3[nt2][3] + b3s[c + 1];
                *(float2*)(outp + (size_t)r1g * 128 + c) = o;
            }
        }
    }
}

// ================= CSR build =================
__global__ void k_hist(const int* __restrict__ dst, int* __restrict__ deg) {
    int i = blockIdx.x * 1024 + threadIdx.x;
    if (i < EE) atomicAdd(&deg[dst[i]], 1);
}

__global__ void k_scanA(const int* __restrict__ deg, int* __restrict__ bsum) {
    __shared__ int ws[32];
    int i = blockIdx.x * 1024 + threadIdx.x;
    int v = (i < NN) ? deg[i] : 0;
    #pragma unroll
    for (int d = 16; d > 0; d >>= 1) v += __shfl_down_sync(~0u, v, d);
    int lane = threadIdx.x & 31, wid = threadIdx.x >> 5;
    if (lane == 0) ws[wid] = v;
    __syncthreads();
    if (wid == 0) {
        int t = ws[lane];
        #pragma unroll
        for (int d = 16; d > 0; d >>= 1) t += __shfl_down_sync(~0u, t, d);
        if (lane == 0) bsum[blockIdx.x] = t;
    }
}

__global__ void k_scanB(const int* __restrict__ bsum, int* __restrict__ boff) {
    __shared__ int s[128];
    int t = threadIdx.x;
    int v = (t < NBLK_SCAN) ? bsum[t] : 0;
    s[t] = v;
    __syncthreads();
    for (int d = 1; d < 128; d <<= 1) {
        int x = (t >= d) ? s[t - d] : 0;
        __syncthreads();
        s[t] += x;
        __syncthreads();
    }
    if (t < NBLK_SCAN) boff[t] = s[t] - v;   // exclusive
}

__global__ void k_scanC(const int* __restrict__ deg, const int* __restrict__ boff,
                        int* __restrict__ start, int* __restrict__ cursor) {
    __shared__ int ws[32];
    int i = blockIdx.x * 1024 + threadIdx.x;
    int lane = threadIdx.x & 31, wid = threadIdx.x >> 5;
    int v = (i < NN) ? deg[i] : 0;
    int incl = v;
    #pragma unroll
    for (int d = 1; d < 32; d <<= 1) {
        int n = __shfl_up_sync(~0u, incl, d);
        if (lane >= d) incl += n;
    }
    if (lane == 31) ws[wid] = incl;
    __syncthreads();
    if (wid == 0) {
        int wv = ws[lane];
        int wi = wv;
        #pragma unroll
        for (int d = 1; d < 32; d <<= 1) {
            int n = __shfl_up_sync(~0u, wi, d);
            if (lane >= d) wi += n;
        }
        ws[lane] = wi - wv;
    }
    __syncthreads();
    int excl = incl - v + ws[wid] + boff[blockIdx.x];
    if (i < NN) { start[i] = excl; cursor[i] = excl; }
}

__global__ void k_fill(const int* __restrict__ src, const int* __restrict__ dst,
                       const int* __restrict__ r, int* __restrict__ cursor,
                       unsigned* __restrict__ packed) {
    int i = blockIdx.x * 1024 + threadIdx.x;
    if (i >= EE) return;
    int d = dst[i];
    int pos = atomicAdd(&cursor[d], 1);
    packed[pos] = (unsigned)src[i] | ((unsigned)r[i] << 31);
}

__global__ void k_compact(const int* __restrict__ inv, int* __restrict__ list,
                          int* __restrict__ cnt) {
    int i = blockIdx.x * 1024 + threadIdx.x;
    if (i < NN && inv[i] == 1) {
        int pos = atomicAdd(cnt, 1);
        list[pos] = i;
    }
}

// ================= k_gather: warp per node, 128-wide sums =================
__global__ void k_gather(const float* __restrict__ feat, const float* __restrict__ g,
                         const unsigned* __restrict__ packed,
                         const int* __restrict__ start, const int* __restrict__ deg,
                         float* __restrict__ sum) {
    int w = (blockIdx.x * blockDim.x + threadIdx.x) >> 5;
    int lane = threadIdx.x & 31;
    if (w >= NN) return;
    int s0 = start[w];
    int e = s0 + deg[w];
    float4 acc = make_float4(0.f, 0.f, 0.f, 0.f);
    for (int j = s0; j < e; j++) {
        unsigned v = __ldg(&packed[j]);
        const float* rp = ((v >> 31) ? g : feat) + (size_t)(v & 0x7FFFFFFFu) * 128;
        float4 x = *(const float4*)(rp + 4 * lane);
        acc.x += x.x; acc.y += x.y; acc.z += x.z; acc.w += x.w;
    }
    *(float4*)(sum + (size_t)w * 128 + 4 * lane) = acc;
}

// ================= host =================
extern "C" void kernel_launch(void* const* d_in, const int* in_sizes, int n_in,
                              void* d_out, int out_size)
{
    const float* feat = (const float*)d_in[0];
    const int*   src  = (const int*)d_in[1];
    const int*   dst  = (const int*)d_in[2];
    const int*   r    = (const int*)d_in[3];
    const int*   inv  = (const int*)d_in[4];
    const float* iw1 = (const float*)d_in[5];
    const float* ib1 = (const float*)d_in[6];
    const float* iw2 = (const float*)d_in[7];
    const float* ib2 = (const float*)d_in[8];
    const float* iw3 = (const float*)d_in[9];
    const float* ib3 = (const float*)d_in[10];
    const float* aw1 = (const float*)d_in[11];
    const float* ab1 = (const float*)d_in[12];
    const float* aw2 = (const float*)d_in[13];
    const float* ab2 = (const float*)d_in[14];
    const float* aw3 = (const float*)d_in[15];
    const float* ab3 = (const float*)d_in[16];
    float* out = (float*)d_out;

    float *g, *sum;
    unsigned* packed;
    int *deg, *start, *cursor, *bsum, *boff, *list, *cnt;
    cudaGetSymbolAddress((void**)&g, g_g);
    cudaGetSymbolAddress((void**)&sum, g_sum);
    cudaGetSymbolAddress((void**)&packed, g_packed);
    cudaGetSymbolAddress((void**)&deg, g_deg);
    cudaGetSymbolAddress((void**)&start, g_start);
    cudaGetSymbolAddress((void**)&cursor, g_cursor);
    cudaGetSymbolAddress((void**)&bsum, g_bsum);
    cudaGetSymbolAddress((void**)&boff, g_boff);
    cudaGetSymbolAddress((void**)&list, g_list);
    cudaGetSymbolAddress((void**)&cnt, g_cnt);

    cudaFuncSetAttribute(mlp_mma<0>, cudaFuncAttributeMaxDynamicSharedMemorySize, SMEM_BYTES);
    cudaFuncSetAttribute(mlp_mma<1>, cudaFuncAttributeMaxDynamicSharedMemorySize, SMEM_BYTES);
    cudaFuncSetAttribute(mlp_mma<2>, cudaFuncAttributeMaxDynamicSharedMemorySize, SMEM_BYTES);

    cudaMemsetAsync(deg, 0, NN * sizeof(int));                        // launch 0
    cudaMemsetAsync(cnt, 0, sizeof(int));                             // launch 1

    k_hist<<<(EE + 1023) / 1024, 1024>>>(dst, deg);                   // 2
    k_scanA<<<NBLK_SCAN, 1024>>>(deg, bsum);                          // 3
    k_scanB<<<1, 128>>>(bsum, boff);                                  // 4
    mlp_mma<0><<<148, NTHR, SMEM_BYTES>>>(feat, g, iw1, ib1, iw2, ib2, iw3, ib3,
                                          nullptr, nullptr, nullptr); // 5  <- ncu -s 5
    k_scanC<<<NBLK_SCAN, 1024>>>(deg, boff, start, cursor);           // 6
    k_fill<<<(EE + 1023) / 1024, 1024>>>(src, dst, r, cursor, packed);// 7
    k_compact<<<NBLK_SCAN, 1024>>>(inv, list, cnt);                   // 8
    k_gather<<<(NN * 32 + 255) / 256, 256>>>(feat, g, packed, start, deg, sum); // 9
    mlp_mma<1><<<148, NTHR, SMEM_BYTES>>>(sum, out, aw1, ab1, aw2, ab2, aw3, ab3,
                                          deg, nullptr, nullptr);     // 10
    mlp_mma<2><<<148, NTHR, SMEM_BYTES>>>(out, out, iw1, ib1, iw2, ib2, iw3, ib3,
                                          nullptr, list, cnt);        // 11
}

// round 15
// speedup vs baseline: 2.4018x; 1.0330x over previous
#include <cuda_runtime.h>
#include <cuda_fp16.h>
#include <stdint.h>

#define NN 100000
#define EE 800000
#define NBLK_SCAN 98            // ceil(100000/1024)

// ---------------- scratch (device globals; no allocation) ----------------
__device__ float    g_g[(size_t)NN * 128];    // mlp_inv(feat) per node
__device__ float    g_sum[(size_t)NN * 128];  // aggregated 128-wide sums
__device__ unsigned g_packed[EE];             // CSR edge payload: src | (r<<31)
__device__ int      g_deg[NN];
__device__ int      g_start[NN];
__device__ int      g_cursor[NN];
__device__ int      g_bsum[NBLK_SCAN];
__device__ int      g_boff[NBLK_SCAN];
__device__ int      g_list[NN];
__device__ int      g_cnt[1];

__device__ __forceinline__ float lrelu(float v) { return v >= 0.0f ? v : 0.01f * v; }

__device__ __forceinline__ uint32_t smem_u32(const void* p) {
    uint32_t a;
    asm("{ .reg .u64 t; cvta.to.shared.u64 t, %1; cvt.u32.u64 %0, t; }" : "=r"(a) : "l"(p));
    return a;
}

__device__ __forceinline__ uint32_t h2u(__half2 h) {
    return *reinterpret_cast<uint32_t*>(&h);
}

__device__ __forceinline__ void ldsm4(uint32_t &r0, uint32_t &r1, uint32_t &r2, uint32_t &r3,
                                      uint32_t a) {
    asm volatile("ldmatrix.sync.aligned.m8n8.x4.shared.b16 {%0,%1,%2,%3}, [%4];"
                 : "=r"(r0), "=r"(r1), "=r"(r2), "=r"(r3) : "r"(a));
}

__device__ __forceinline__ void mma_f16(float d[4],
                                        uint32_t a0, uint32_t a1, uint32_t a2, uint32_t a3,
                                        uint32_t b0, uint32_t b1) {
    asm volatile("mma.sync.aligned.m16n8k16.row.col.f32.f16.f16.f32 "
                 "{%0,%1,%2,%3}, {%4,%5,%6,%7}, {%8,%9}, {%0,%1,%2,%3};"
                 : "+f"(d[0]), "+f"(d[1]), "+f"(d[2]), "+f"(d[3])
                 : "r"(a0), "r"(a1), "r"(a2), "r"(a3), "r"(b0), "r"(b1));
}

// ---------------- smem byte offsets ----------------
// pitches: X/W1 = 272 B (17x16B, odd -> conflict-free ldmatrix); 64-col tiles = 144 B
// fp16: weights HI only; X = hi+lo (exact); T/U = hi only (single-pass L2/L3).
#define SM_RID  0          // 128 ints
#define SM_SRC  512
#define SM_SCL  1024
#define SM_B1   1536       // 64 f32
#define SM_B2   1792
#define SM_B3   2048       // 128 f32
#define SM_W1H  2560       // 64 x 272
#define SM_W2H  19968      // 64 x 144
#define SM_W3H  29184      // 128 x 144
#define SM_TH   47616      // 128 x 144
#define SM_XH   66048      // 128 x 272 (U hi overlays @144 pitch)
#define SM_XL   100864     // 128 x 272
#define SMEM_BYTES 135680

#define NTHR 512

// stage fp32 weights [OUT][K] -> fp16 hi pitched tile
__device__ void stage_w(char* hi, const float* __restrict__ w,
                        int OUT, int K, int pitch, int tid) {
    for (int i = tid; i < OUT * K; i += NTHR) {
        int o = i / K, k = i - o * K;
        *(__half*)(hi + o * pitch + k * 2) = __float2half_rn(w[i]);
    }
}

// warp GEMM, 2-pass A (hi+lo): A (16 rows) x B (NTILES*16 cols), pipelined.
template<int KSTEPS, int NTILES>
__device__ __forceinline__ void gemm2(uint32_t aH, uint32_t aL,
                                      uint32_t bH, int bstep16,
                                      float acc[][4]) {
    uint32_t ah[2][4], al[2][4], bh[2][4];
    ldsm4(ah[0][0], ah[0][1], ah[0][2], ah[0][3], aH);
    ldsm4(al[0][0], al[0][1], al[0][2], al[0][3], aL);
    ldsm4(bh[0][0], bh[0][1], bh[0][2], bh[0][3], bH);
    const int total = KSTEPS * NTILES;
    #pragma unroll
    for (int idx = 0; idx < total; idx++) {
        const int k = idx / NTILES, np = idx % NTILES;
        const int ka = k & 1, ib = idx & 1;
        if (idx + 1 < total) {
            const int k2 = (idx + 1) / NTILES, np2 = (idx + 1) % NTILES;
            const int ka2 = k2 & 1, ib2 = (idx + 1) & 1;
            ldsm4(bh[ib2][0], bh[ib2][1], bh[ib2][2], bh[ib2][3],
                  bH + np2 * bstep16 + k2 * 32);
            if (np2 == 0) {
                ldsm4(ah[ka2][0], ah[ka2][1], ah[ka2][2], ah[ka2][3], aH + k2 * 32);
                ldsm4(al[ka2][0], al[ka2][1], al[ka2][2], al[ka2][3], aL + k2 * 32);
            }
        }
        mma_f16(acc[2*np],   ah[ka][0], ah[ka][1], ah[ka][2], ah[ka][3], bh[ib][0], bh[ib][1]);
        mma_f16(acc[2*np+1], ah[ka][0], ah[ka][1], ah[ka][2], ah[ka][3], bh[ib][2], bh[ib][3]);
        mma_f16(acc[2*np],   al[ka][0], al[ka][1], al[ka][2], al[ka][3], bh[ib][0], bh[ib][1]);
        mma_f16(acc[2*np+1], al[ka][0], al[ka][1], al[ka][2], al[ka][3], bh[ib][2], bh[ib][3]);
    }
}

// warp GEMM, 1-pass A (hi only), pipelined.
template<int KSTEPS, int NTILES>
__device__ __forceinline__ void gemm1(uint32_t aH,
                                      uint32_t bH, int bstep16,
                                      float acc[][4]) {
    uint32_t ah[2][4], bh[2][4];
    ldsm4(ah[0][0], ah[0][1], ah[0][2], ah[0][3], aH);
    ldsm4(bh[0][0], bh[0][1], bh[0][2], bh[0][3], bH);
    const int total = KSTEPS * NTILES;
    #pragma unroll
    for (int idx = 0; idx < total; idx++) {
        const int k = idx / NTILES, np = idx % NTILES;
        const int ka = k & 1, ib = idx & 1;
        if (idx + 1 < total) {
            const int k2 = (idx + 1) / NTILES, np2 = (idx + 1) % NTILES;
            const int ka2 = k2 & 1, ib2 = (idx + 1) & 1;
            ldsm4(bh[ib2][0], bh[ib2][1], bh[ib2][2], bh[ib2][3],
                  bH + np2 * bstep16 + k2 * 32);
            if (np2 == 0) {
                ldsm4(ah[ka2][0], ah[ka2][1], ah[ka2][2], ah[ka2][3], aH + k2 * 32);
            }
        }
        mma_f16(acc[2*np],   ah[ka][0], ah[ka][1], ah[ka][2], ah[ka][3], bh[ib][0], bh[ib][1]);
        mma_f16(acc[2*np+1], ah[ka][0], ah[ka][1], ah[ka][2], ah[ka][3], bh[ib][2], bh[ib][3]);
    }
}

// 32-col epilogue: acc + bias + lrelu -> fp16 HI tile at column offset ncol0
__device__ __forceinline__ void epi32h(const float acc[4][4],
                                       const float* __restrict__ bias,
                                       char* tH, int pitch, int m0, int ncol0,
                                       int g, int t) {
    #pragma unroll
    for (int nt2 = 0; nt2 < 4; nt2++) {
        int c = ncol0 + nt2 * 8 + 2 * t;
        float v0 = lrelu(acc[nt2][0] + bias[c]);
        float v1 = lrelu(acc[nt2][1] + bias[c + 1]);
        float v2 = lrelu(acc[nt2][2] + bias[c]);
        float v3 = lrelu(acc[nt2][3] + bias[c + 1]);
        *(uint32_t*)(tH + (m0 + g) * pitch + c * 2)     = h2u(__floats2half2_rn(v0, v1));
        *(uint32_t*)(tH + (m0 + 8 + g) * pitch + c * 2) = h2u(__floats2half2_rn(v2, v3));
    }
}

#define ZERO4(a, n) { _Pragma("unroll") for (int i = 0; i < n; i++) { (a)[i][0]=0.f; (a)[i][1]=0.f; (a)[i][2]=0.f; (a)[i][3]=0.f; } }

// ====== fused 3-layer MLP: L1 fp16 2-pass (exact x), L2/L3 single-pass fp16 ======
// MODE 0: rows 0..NN-1. MODE 1: in scaled by 1/max(deg,1). MODE 2: rows from list.
template <int MODE>
__global__ void __launch_bounds__(NTHR, 1) mlp_mma(
    const float* __restrict__ in, float* __restrict__ outp,
    const float* __restrict__ w1, const float* __restrict__ b1,
    const float* __restrict__ w2, const float* __restrict__ b2,
    const float* __restrict__ w3, const float* __restrict__ b3,
    const int* __restrict__ deg, const int* __restrict__ list,
    const int* __restrict__ cnt)
{
    extern __shared__ char smc[];
    const uint32_t sb = smem_u32(smc);
    const int tid = threadIdx.x, wid = tid >> 5, lane = tid & 31;

    stage_w(smc + SM_W1H, w1, 64, 128, 272, tid);
    stage_w(smc + SM_W2H, w2, 64, 64, 144, tid);
    stage_w(smc + SM_W3H, w3, 128, 64, 144, tid);
    float* b1s = (float*)(smc + SM_B1);
    float* b2s = (float*)(smc + SM_B2);
    float* b3s = (float*)(smc + SM_B3);
    for (int i = tid; i < 64; i += NTHR) { b1s[i] = b1[i]; b2s[i] = b2[i]; }
    for (int i = tid; i < 128; i += NTHR) b3s[i] = b3[i];

    int* rid_s = (int*)(smc + SM_RID);
    int* src_s = (int*)(smc + SM_SRC);
    float* scl_s = (float*)(smc + SM_SCL);
    __syncthreads();

    const int nrows = (MODE == 2) ? *cnt : NN;
    const int ntile = (nrows + 127) >> 7;

    const int arow = (lane & 7) + ((lane >> 3) & 1) * 8;
    const int akoff = (lane >> 4) * 16;
    const int brow = (lane & 7) + ((lane >> 4) & 1) * 8;
    const int bkoff = ((lane >> 3) & 1) * 16;
    const int mwarp = wid & 7, nhalf = wid >> 3;
    const int m0 = mwarp * 16;
    const int g = lane >> 2, t = lane & 3;

    for (int tile = blockIdx.x; tile < ntile; tile += gridDim.x) {
        int base = tile << 7;
        __syncthreads();                   // prev tile fully consumed
        if (tid < 128) {
            int row = base + tid;
            int rowid, srow; float sc = 1.0f;
            if (MODE == 2) {
                rowid = (row < nrows) ? list[row] : -1;
                srow = (rowid >= 0) ? rowid : list[base];
            } else {
                rowid = (row < NN) ? row : -1;
                srow = (rowid >= 0) ? rowid : (NN - 1);
            }
            if (MODE == 1) { int dg = deg[srow]; sc = 1.0f / (float)(dg < 1 ? 1 : dg); }
            rid_s[tid] = rowid; src_s[tid] = srow; scl_s[tid] = sc;
        }
        __syncthreads();
        // ---- stage X: fp32 -> fp16 hi/lo pitched tiles (exact split) ----
        for (int idx = tid; idx < 128 * 32; idx += NTHR) {
            int j = idx >> 5, q = idx & 31;
            float4 v = *(const float4*)(in + (size_t)src_s[j] * 128 + 4 * q);
            if (MODE == 1) { float sc = scl_s[j]; v.x *= sc; v.y *= sc; v.z *= sc; v.w *= sc; }
            __half2 Ha = __floats2half2_rn(v.x, v.y);
            float2  Fa = __half22float2(Ha);
            __half2 La = __floats2half2_rn(v.x - Fa.x, v.y - Fa.y);
            __half2 Hb = __floats2half2_rn(v.z, v.w);
            float2  Fb = __half22float2(Hb);
            __half2 Lb = __floats2half2_rn(v.z - Fb.x, v.w - Fb.y);
            *(uint2*)(smc + SM_XH + j * 272 + 8 * q) = make_uint2(h2u(Ha), h2u(Hb));
            *(uint2*)(smc + SM_XL + j * 272 + 8 * q) = make_uint2(h2u(La), h2u(Lb));
        }
        __syncthreads();

        // ---- layer 1 (2-pass): [16x128] @ W1^T cols [nhalf*32, +32) ----
        float acc1[4][4];
        ZERO4(acc1, 4);
        gemm2<8, 2>(sb + SM_XH + (m0 + arow) * 272 + akoff,
                    sb + SM_XL + (m0 + arow) * 272 + akoff,
                    sb + SM_W1H + (nhalf * 32 + brow) * 272 + bkoff, 16 * 272, acc1);
        epi32h(acc1, b1s, smc + SM_TH, 144, m0, nhalf * 32, g, t);
        __syncthreads();   // T complete across n-halves AND all X reads done (U overlay safe)

        // ---- layer 2 (1-pass): [16x64] @ W2^T cols [nhalf*32, +32) ----
        float acc2[4][4];
        ZERO4(acc2, 4);
        gemm1<4, 2>(sb + SM_TH + (m0 + arow) * 144 + akoff,
                    sb + SM_W2H + (nhalf * 32 + brow) * 144 + bkoff, 16 * 144, acc2);
        // U hi tiles overlay X region at pitch 144 (X dead for all warps since last barrier)
        epi32h(acc2, b2s, smc + SM_XH, 144, m0, nhalf * 32, g, t);
        // U rows m0..m0+16 produced/consumed only by warp pair {mwarp, mwarp+8}
        asm volatile("bar.sync %0, 64;" :: "r"(mwarp + 1) : "memory");

        // ---- layer 3 (1-pass): [16x64] @ W3^T cols [nhalf*64, +64) -> gmem ----
        float acc3[8][4];
        ZERO4(acc3, 8);
        gemm1<4, 4>(sb + SM_XH + (m0 + arow) * 144 + akoff,
                    sb + SM_W3H + (nhalf * 64 + brow) * 144 + bkoff, 16 * 144, acc3);
        int r0g = rid_s[m0 + g], r1g = rid_s[m0 + 8 + g];
        #pragma unroll
        for (int nt2 = 0; nt2 < 8; nt2++) {
            int c = nhalf * 64 + nt2 * 8 + 2 * t;
            if (r0g >= 0) {
                float2 o;
                o.x = acc3[nt2][0] + b3s[c];
                o.y = acc3[nt2][1] + b3s[c + 1];
                *(float2*)(outp + (size_t)r0g * 128 + c) = o;
            }
            if (r1g >= 0) {
                float2 o;
                o.x = acc3[nt2][2] + b3s[c];
                o.y = acc3[nt2][3] + b3s[c + 1];
                *(float2*)(outp + (size_t)r1g * 128 + c) = o;
            }
        }
    }
}

// ================= CSR build =================
__global__ void k_hist(const int* __restrict__ dst, int* __restrict__ deg) {
    int i = blockIdx.x * 1024 + threadIdx.x;
    if (i < EE) atomicAdd(&deg[dst[i]], 1);
}

__global__ void k_scanA(const int* __restrict__ deg, int* __restrict__ bsum) {
    __shared__ int ws[32];
    int i = blockIdx.x * 1024 + threadIdx.x;
    int v = (i < NN) ? deg[i] : 0;
    #pragma unroll
    for (int d = 16; d > 0; d >>= 1) v += __shfl_down_sync(~0u, v, d);
    int lane = threadIdx.x & 31, wid = threadIdx.x >> 5;
    if (lane == 0) ws[wid] = v;
    __syncthreads();
    if (wid == 0) {
        int t = ws[lane];
        #pragma unroll
        for (int d = 16; d > 0; d >>= 1) t += __shfl_down_sync(~0u, t, d);
        if (lane == 0) bsum[blockIdx.x] = t;
    }
}

__global__ void k_scanB(const int* __restrict__ bsum, int* __restrict__ boff) {
    __shared__ int s[128];
    int t = threadIdx.x;
    int v = (t < NBLK_SCAN) ? bsum[t] : 0;
    s[t] = v;
    __syncthreads();
    for (int d = 1; d < 128; d <<= 1) {
        int x = (t >= d) ? s[t - d] : 0;
        __syncthreads();
        s[t] += x;
        __syncthreads();
    }
    if (t < NBLK_SCAN) boff[t] = s[t] - v;   // exclusive
}

__global__ void k_scanC(const int* __restrict__ deg, const int* __restrict__ boff,
                        int* __restrict__ start, int* __restrict__ cursor) {
    __shared__ int ws[32];
    int i = blockIdx.x * 1024 + threadIdx.x;
    int lane = threadIdx.x & 31, wid = threadIdx.x >> 5;
    int v = (i < NN) ? deg[i] : 0;
    int incl = v;
    #pragma unroll
    for (int d = 1; d < 32; d <<= 1) {
        int n = __shfl_up_sync(~0u, incl, d);
        if (lane >= d) incl += n;
    }
    if (lane == 31) ws[wid] = incl;
    __syncthreads();
    if (wid == 0) {
        int wv = ws[lane];
        int wi = wv;
        #pragma unroll
        for (int d = 1; d < 32; d <<= 1) {
            int n = __shfl_up_sync(~0u, wi, d);
            if (lane >= d) wi += n;
        }
        ws[lane] = wi - wv;
    }
    __syncthreads();
    int excl = incl - v + ws[wid] + boff[blockIdx.x];
    if (i < NN) { start[i] = excl; cursor[i] = excl; }
}

__global__ void k_fill(const int* __restrict__ src, const int* __restrict__ dst,
                       const int* __restrict__ r, int* __restrict__ cursor,
                       unsigned* __restrict__ packed) {
    int i = blockIdx.x * 1024 + threadIdx.x;
    if (i >= EE) return;
    int d = dst[i];
    int pos = atomicAdd(&cursor[d], 1);
    packed[pos] = (unsigned)src[i] | ((unsigned)r[i] << 31);
}

__global__ void k_compact(const int* __restrict__ inv, int* __restrict__ list,
                          int* __restrict__ cnt) {
    int i = blockIdx.x * 1024 + threadIdx.x;
    if (i < NN && inv[i] == 1) {
        int pos = atomicAdd(cnt, 1);
        list[pos] = i;
    }
}

// ================= k_gather: warp per node, 128-wide sums =================
__global__ void k_gather(const float* __restrict__ feat, const float* __restrict__ g,
                         const unsigned* __restrict__ packed,
                         const int* __restrict__ start, const int* __restrict__ deg,
                         float* __restrict__ sum) {
    int w = (blockIdx.x * blockDim.x + threadIdx.x) >> 5;
    int lane = threadIdx.x & 31;
    if (w >= NN) return;
    int s0 = start[w];
    int e = s0 + deg[w];
    float4 acc = make_float4(0.f, 0.f, 0.f, 0.f);
    for (int j = s0; j < e; j++) {
        unsigned v = __ldg(&packed[j]);
        const float* rp = ((v >> 31) ? g : feat) + (size_t)(v & 0x7FFFFFFFu) * 128;
        float4 x = *(const float4*)(rp + 4 * lane);
        acc.x += x.x; acc.y += x.y; acc.z += x.z; acc.w += x.w;
    }
    *(float4*)(sum + (size_t)w * 128 + 4 * lane) = acc;
}

// ================= host =================
extern "C" void kernel_launch(void* const* d_in, const int* in_sizes, int n_in,
                              void* d_out, int out_size)
{
    const float* feat = (const float*)d_in[0];
    const int*   src  = (const int*)d_in[1];
    const int*   dst  = (const int*)d_in[2];
    const int*   r    = (const int*)d_in[3];
    const int*   inv  = (const int*)d_in[4];
    const float* iw1 = (const float*)d_in[5];
    const float* ib1 = (const float*)d_in[6];
    const float* iw2 = (const float*)d_in[7];
    const float* ib2 = (const float*)d_in[8];
    const float* iw3 = (const float*)d_in[9];
    const float* ib3 = (const float*)d_in[10];
    const float* aw1 = (const float*)d_in[11];
    const float* ab1 = (const float*)d_in[12];
    const float* aw2 = (const float*)d_in[13];
    const float* ab2 = (const float*)d_in[14];
    const float* aw3 = (const float*)d_in[15];
    const float* ab3 = (const float*)d_in[16];
    float* out = (float*)d_out;

    float *g, *sum;
    unsigned* packed;
    int *deg, *start, *cursor, *bsum, *boff, *list, *cnt;
    cudaGetSymbolAddress((void**)&g, g_g);
    cudaGetSymbolAddress((void**)&sum, g_sum);
    cudaGetSymbolAddress((void**)&packed, g_packed);
    cudaGetSymbolAddress((void**)&deg, g_deg);
    cudaGetSymbolAddress((void**)&start, g_start);
    cudaGetSymbolAddress((void**)&cursor, g_cursor);
    cudaGetSymbolAddress((void**)&bsum, g_bsum);
    cudaGetSymbolAddress((void**)&boff, g_boff);
    cudaGetSymbolAddress((void**)&list, g_list);
    cudaGetSymbolAddress((void**)&cnt, g_cnt);

    cudaFuncSetAttribute(mlp_mma<0>, cudaFuncAttributeMaxDynamicSharedMemorySize, SMEM_BYTES);
    cudaFuncSetAttribute(mlp_mma<1>, cudaFuncAttributeMaxDynamicSharedMemorySize, SMEM_BYTES);
    cudaFuncSetAttribute(mlp_mma<2>, cudaFuncAttributeMaxDynamicSharedMemorySize, SMEM_BYTES);

    cudaMemsetAsync(deg, 0, NN * sizeof(int));                        // launch 0
    cudaMemsetAsync(cnt, 0, sizeof(int));                             // launch 1

    k_hist<<<(EE + 1023) / 1024, 1024>>>(dst, deg);                   // 2
    k_scanA<<<NBLK_SCAN, 1024>>>(deg, bsum);                          // 3
    k_scanB<<<1, 128>>>(bsum, boff);                                  // 4
    mlp_mma<0><<<148, NTHR, SMEM_BYTES>>>(feat, g, iw1, ib1, iw2, ib2, iw3, ib3,
                                          nullptr, nullptr, nullptr); // 5  <- ncu -s 5
    k_scanC<<<NBLK_SCAN, 1024>>>(deg, boff, start, cursor);           // 6
    k_fill<<<(EE + 1023) / 1024, 1024>>>(src, dst, r, cursor, packed);// 7
    k_compact<<<NBLK_SCAN, 1024>>>(inv, list, cnt);                   // 8
    k_gather<<<(NN * 32 + 255) / 256, 256>>>(feat, g, packed, start, deg, sum); // 9
    mlp_mma<1><<<148, NTHR, SMEM_BYTES>>>(sum, out, aw1, ab1, aw2, ab2, aw3, ab3,
                                          deg, nullptr, nullptr);     // 10
    mlp_mma<2><<<148, NTHR, SMEM_BYTES>>>(out, out, iw1, ib1, iw2, ib2, iw3, ib3,
                                          nullptr, list, cnt);        // 11
}

// round 17
// speedup vs baseline: 2.5876x; 1.0774x over previous
#include <cuda_runtime.h>
#include <cuda_fp16.h>
#include <stdint.h>

#define NN 100000
#define EE 800000
#define NBLK_SCAN 98            // ceil(100000/1024)

// ---------------- scratch (device globals; no allocation) ----------------
__device__ __half   g_g16[(size_t)NN * 128];  // mlp_inv(feat) per node, fp16
__device__ float    g_sum[(size_t)NN * 128];  // aggregated 128-wide sums
__device__ unsigned g_packed[EE];             // CSR edge payload: src | (r<<31)
__device__ int      g_deg[NN];
__device__ int      g_start[NN];
__device__ int      g_cursor[NN];
__device__ int      g_bsum[NBLK_SCAN];
__device__ int      g_boff[NBLK_SCAN];
__device__ int      g_list[NN];
__device__ int      g_cnt[1];

__device__ __forceinline__ float lrelu(float v) { return v >= 0.0f ? v : 0.01f * v; }

__device__ __forceinline__ uint32_t smem_u32(const void* p) {
    uint32_t a;
    asm("{ .reg .u64 t; cvta.to.shared.u64 t, %1; cvt.u32.u64 %0, t; }" : "=r"(a) : "l"(p));
    return a;
}

__device__ __forceinline__ uint32_t h2u(__half2 h) {
    return *reinterpret_cast<uint32_t*>(&h);
}

__device__ __forceinline__ void ldsm4(uint32_t &r0, uint32_t &r1, uint32_t &r2, uint32_t &r3,
                                      uint32_t a) {
    asm volatile("ldmatrix.sync.aligned.m8n8.x4.shared.b16 {%0,%1,%2,%3}, [%4];"
                 : "=r"(r0), "=r"(r1), "=r"(r2), "=r"(r3) : "r"(a));
}

__device__ __forceinline__ void mma_f16(float d[4],
                                        uint32_t a0, uint32_t a1, uint32_t a2, uint32_t a3,
                                        uint32_t b0, uint32_t b1) {
    asm volatile("mma.sync.aligned.m16n8k16.row.col.f32.f16.f16.f32 "
                 "{%0,%1,%2,%3}, {%4,%5,%6,%7}, {%8,%9}, {%0,%1,%2,%3};"
                 : "+f"(d[0]), "+f"(d[1]), "+f"(d[2]), "+f"(d[3])
                 : "r"(a0), "r"(a1), "r"(a2), "r"(a3), "r"(b0), "r"(b1));
}

// ---------------- smem byte offsets ----------------
// pitches: X/W1 = 272 B (17x16B, odd -> conflict-free ldmatrix); 64-col tiles = 144 B
// All-fp16 single-precision path: weights hi, X hi, T/U hi.
#define SM_RID  0          // 128 ints
#define SM_SRC  512
#define SM_SCL  1024
#define SM_B1   1536       // 64 f32
#define SM_B2   1792
#define SM_B3   2048       // 128 f32
#define SM_W1H  2560       // 64 x 272
#define SM_W2H  19968      // 64 x 144
#define SM_W3H  29184      // 128 x 144
#define SM_TH   47616      // 128 x 144
#define SM_XH   66048      // 128 x 272 (U hi overlays @144 pitch)
#define SMEM_BYTES 100864

#define NTHR 512

// stage fp32 weights [OUT][K] -> fp16 pitched tile
__device__ void stage_w(char* hi, const float* __restrict__ w,
                        int OUT, int K, int pitch, int tid) {
    for (int i = tid; i < OUT * K; i += NTHR) {
        int o = i / K, k = i - o * K;
        *(__half*)(hi + o * pitch + k * 2) = __float2half_rn(w[i]);
    }
}

// warp GEMM, single-pass fp16: A (16 rows) x B (NTILES*16 cols), pipelined.
template<int KSTEPS, int NTILES>
__device__ __forceinline__ void gemm1(uint32_t aH,
                                      uint32_t bH, int bstep16,
                                      float acc[][4]) {
    uint32_t ah[2][4], bh[2][4];
    ldsm4(ah[0][0], ah[0][1], ah[0][2], ah[0][3], aH);
    ldsm4(bh[0][0], bh[0][1], bh[0][2], bh[0][3], bH);
    const int total = KSTEPS * NTILES;
    #pragma unroll
    for (int idx = 0; idx < total; idx++) {
        const int k = idx / NTILES, np = idx % NTILES;
        const int ka = k & 1, ib = idx & 1;
        if (idx + 1 < total) {
            const int k2 = (idx + 1) / NTILES, np2 = (idx + 1) % NTILES;
            const int ka2 = k2 & 1, ib2 = (idx + 1) & 1;
            ldsm4(bh[ib2][0], bh[ib2][1], bh[ib2][2], bh[ib2][3],
                  bH + np2 * bstep16 + k2 * 32);
            if (np2 == 0) {
                ldsm4(ah[ka2][0], ah[ka2][1], ah[ka2][2], ah[ka2][3], aH + k2 * 32);
            }
        }
        mma_f16(acc[2*np],   ah[ka][0], ah[ka][1], ah[ka][2], ah[ka][3], bh[ib][0], bh[ib][1]);
        mma_f16(acc[2*np+1], ah[ka][0], ah[ka][1], ah[ka][2], ah[ka][3], bh[ib][2], bh[ib][3]);
    }
}

// 32-col epilogue: acc + bias + lrelu -> fp16 tile at column offset ncol0
__device__ __forceinline__ void epi32h(const float acc[4][4],
                                       const float* __restrict__ bias,
                                       char* tH, int pitch, int m0, int ncol0,
                                       int g, int t) {
    #pragma unroll
    for (int nt2 = 0; nt2 < 4; nt2++) {
        int c = ncol0 + nt2 * 8 + 2 * t;
        float v0 = lrelu(acc[nt2][0] + bias[c]);
        float v1 = lrelu(acc[nt2][1] + bias[c + 1]);
        float v2 = lrelu(acc[nt2][2] + bias[c]);
        float v3 = lrelu(acc[nt2][3] + bias[c + 1]);
        *(uint32_t*)(tH + (m0 + g) * pitch + c * 2)     = h2u(__floats2half2_rn(v0, v1));
        *(uint32_t*)(tH + (m0 + 8 + g) * pitch + c * 2) = h2u(__floats2half2_rn(v2, v3));
    }
}

#define ZERO4(a, n) { _Pragma("unroll") for (int i = 0; i < n; i++) { (a)[i][0]=0.f; (a)[i][1]=0.f; (a)[i][2]=0.f; (a)[i][3]=0.f; } }

// ====== fused 3-layer MLP, single-pass fp16 throughout ======
// MODE 0: rows 0..NN-1, fp32 in, write fp16 out16.
// MODE 1: in scaled by 1/max(deg,1), write fp32 outp.
// MODE 2: rows from list, fp32 in/out in-place (outp).
template <int MODE>
__global__ void __launch_bounds__(NTHR, 1) mlp_mma(
    const float* __restrict__ in, float* __restrict__ outp, __half* __restrict__ out16,
    const float* __restrict__ w1, const float* __restrict__ b1,
    const float* __restrict__ w2, const float* __restrict__ b2,
    const float* __restrict__ w3, const float* __restrict__ b3,
    const int* __restrict__ deg, const int* __restrict__ list,
    const int* __restrict__ cnt)
{
    extern __shared__ char smc[];
    const uint32_t sb = smem_u32(smc);
    const int tid = threadIdx.x, wid = tid >> 5, lane = tid & 31;

    stage_w(smc + SM_W1H, w1, 64, 128, 272, tid);
    stage_w(smc + SM_W2H, w2, 64, 64, 144, tid);
    stage_w(smc + SM_W3H, w3, 128, 64, 144, tid);
    float* b1s = (float*)(smc + SM_B1);
    float* b2s = (float*)(smc + SM_B2);
    float* b3s = (float*)(smc + SM_B3);
    for (int i = tid; i < 64; i += NTHR) { b1s[i] = b1[i]; b2s[i] = b2[i]; }
    for (int i = tid; i < 128; i += NTHR) b3s[i] = b3[i];

    int* rid_s = (int*)(smc + SM_RID);
    int* src_s = (int*)(smc + SM_SRC);
    float* scl_s = (float*)(smc + SM_SCL);
    __syncthreads();

    const int nrows = (MODE == 2) ? *cnt : NN;
    const int ntile = (nrows + 127) >> 7;

    const int arow = (lane & 7) + ((lane >> 3) & 1) * 8;
    const int akoff = (lane >> 4) * 16;
    const int brow = (lane & 7) + ((lane >> 4) & 1) * 8;
    const int bkoff = ((lane >> 3) & 1) * 16;
    const int mwarp = wid & 7, nhalf = wid >> 3;
    const int m0 = mwarp * 16;
    const int g = lane >> 2, t = lane & 3;

    for (int tile = blockIdx.x; tile < ntile; tile += gridDim.x) {
        int base = tile << 7;
        __syncthreads();                   // prev tile fully consumed
        if (tid < 128) {
            int row = base + tid;
            int rowid, srow; float sc = 1.0f;
            if (MODE == 2) {
                rowid = (row < nrows) ? list[row] : -1;
                srow = (rowid >= 0) ? rowid : list[base];
            } else {
                rowid = (row < NN) ? row : -1;
                srow = (rowid >= 0) ? rowid : (NN - 1);
            }
            if (MODE == 1) { int dg = deg[srow]; sc = 1.0f / (float)(dg < 1 ? 1 : dg); }
            rid_s[tid] = rowid; src_s[tid] = srow; scl_s[tid] = sc;
        }
        __syncthreads();
        // ---- stage X: fp32 -> fp16 pitched tile ----
        for (int idx = tid; idx < 128 * 32; idx += NTHR) {
            int j = idx >> 5, q = idx & 31;
            float4 v = *(const float4*)(in + (size_t)src_s[j] * 128 + 4 * q);
            if (MODE == 1) { float sc = scl_s[j]; v.x *= sc; v.y *= sc; v.z *= sc; v.w *= sc; }
            *(uint2*)(smc + SM_XH + j * 272 + 8 * q) =
                make_uint2(h2u(__floats2half2_rn(v.x, v.y)),
                           h2u(__floats2half2_rn(v.z, v.w)));
        }
        __syncthreads();

        // ---- layer 1: [16x128] @ W1^T cols [nhalf*32, +32) ----
        float acc1[4][4];
        ZERO4(acc1, 4);
        gemm1<8, 2>(sb + SM_XH + (m0 + arow) * 272 + akoff,
                    sb + SM_W1H + (nhalf * 32 + brow) * 272 + bkoff, 16 * 272, acc1);
        epi32h(acc1, b1s, smc + SM_TH, 144, m0, nhalf * 32, g, t);
        __syncthreads();   // T complete across n-halves AND all X reads done (U overlay safe)

        // ---- layer 2: [16x64] @ W2^T cols [nhalf*32, +32) ----
        float acc2[4][4];
        ZERO4(acc2, 4);
        gemm1<4, 2>(sb + SM_TH + (m0 + arow) * 144 + akoff,
                    sb + SM_W2H + (nhalf * 32 + brow) * 144 + bkoff, 16 * 144, acc2);
        // U tiles overlay X region at pitch 144 (X dead for all warps since last barrier)
        epi32h(acc2, b2s, smc + SM_XH, 144, m0, nhalf * 32, g, t);
        // U rows m0..m0+16 produced/consumed only by warp pair {mwarp, mwarp+8}
        asm volatile("bar.sync %0, 64;" :: "r"(mwarp + 1) : "memory");

        // ---- layer 3: [16x64] @ W3^T cols [nhalf*64, +64) -> gmem ----
        float acc3[8][4];
        ZERO4(acc3, 8);
        gemm1<4, 4>(sb + SM_XH + (m0 + arow) * 144 + akoff,
                    sb + SM_W3H + (nhalf * 64 + brow) * 144 + bkoff, 16 * 144, acc3);
        int r0g = rid_s[m0 + g], r1g = rid_s[m0 + 8 + g];
        #pragma unroll
        for (int nt2 = 0; nt2 < 8; nt2++) {
            int c = nhalf * 64 + nt2 * 8 + 2 * t;
            float o0 = acc3[nt2][0] + b3s[c];
            float o1 = acc3[nt2][1] + b3s[c + 1];
            float o2 = acc3[nt2][2] + b3s[c];
            float o3 = acc3[nt2][3] + b3s[c + 1];
            if (MODE == 0) {
                if (r0g >= 0)
                    *(uint32_t*)(out16 + (size_t)r0g * 128 + c) = h2u(__floats2half2_rn(o0, o1));
                if (r1g >= 0)
                    *(uint32_t*)(out16 + (size_t)r1g * 128 + c) = h2u(__floats2half2_rn(o2, o3));
            } else {
                if (r0g >= 0) { float2 o; o.x = o0; o.y = o1;
                    *(float2*)(outp + (size_t)r0g * 128 + c) = o; }
                if (r1g >= 0) { float2 o; o.x = o2; o.y = o3;
                    *(float2*)(outp + (size_t)r1g * 128 + c) = o; }
            }
        }
    }
}

// ================= CSR build =================
__global__ void k_hist(const int* __restrict__ dst, int* __restrict__ deg) {
    int i = blockIdx.x * 1024 + threadIdx.x;
    if (i < EE) atomicAdd(&deg[dst[i]], 1);
}

__global__ void k_scanA(const int* __restrict__ deg, int* __restrict__ bsum) {
    __shared__ int ws[32];
    int i = blockIdx.x * 1024 + threadIdx.x;
    int v = (i < NN) ? deg[i] : 0;
    #pragma unroll
    for (int d = 16; d > 0; d >>= 1) v += __shfl_down_sync(~0u, v, d);
    int lane = threadIdx.x & 31, wid = threadIdx.x >> 5;
    if (lane == 0) ws[wid] = v;
    __syncthreads();
    if (wid == 0) {
        int t = ws[lane];
        #pragma unroll
        for (int d = 16; d > 0; d >>= 1) t += __shfl_down_sync(~0u, t, d);
        if (lane == 0) bsum[blockIdx.x] = t;
    }
}

__global__ void k_scanB(const int* __restrict__ bsum, int* __restrict__ boff) {
    __shared__ int s[128];
    int t = threadIdx.x;
    int v = (t < NBLK_SCAN) ? bsum[t] : 0;
    s[t] = v;
    __syncthreads();
    for (int d = 1; d < 128; d <<= 1) {
        int x = (t >= d) ? s[t - d] : 0;
        __syncthreads();
        s[t] += x;
        __syncthreads();
    }
    if (t < NBLK_SCAN) boff[t] = s[t] - v;   // exclusive
}

__global__ void k_scanC(const int* __restrict__ deg, const int* __restrict__ boff,
                        int* __restrict__ start, int* __restrict__ cursor) {
    __shared__ int ws[32];
    int i = blockIdx.x * 1024 + threadIdx.x;
    int lane = threadIdx.x & 31, wid = threadIdx.x >> 5;
    int v = (i < NN) ? deg[i] : 0;
    int incl = v;
    #pragma unroll
    for (int d = 1; d < 32; d <<= 1) {
        int n = __shfl_up_sync(~0u, incl, d);
        if (lane >= d) incl += n;
    }
    if (lane == 31) ws[wid] = incl;
    __syncthreads();
    if (wid == 0) {
        int wv = ws[lane];
        int wi = wv;
        #pragma unroll
        for (int d = 1; d < 32; d <<= 1) {
            int n = __shfl_up_sync(~0u, wi, d);
            if (lane >= d) wi += n;
        }
        ws[lane] = wi - wv;
    }
    __syncthreads();
    int excl = incl - v + ws[wid] + boff[blockIdx.x];
    if (i < NN) { start[i] = excl; cursor[i] = excl; }
}

__global__ void k_fill(const int* __restrict__ src, const int* __restrict__ dst,
                       const int* __restrict__ r, int* __restrict__ cursor,
                       unsigned* __restrict__ packed) {
    int i = blockIdx.x * 1024 + threadIdx.x;
    if (i >= EE) return;
    int d = dst[i];
    int pos = atomicAdd(&cursor[d], 1);
    packed[pos] = (unsigned)src[i] | ((unsigned)r[i] << 31);
}

__global__ void k_compact(const int* __restrict__ inv, int* __restrict__ list,
                          int* __restrict__ cnt) {
    int i = blockIdx.x * 1024 + threadIdx.x;
    if (i < NN && inv[i] == 1) {
        int pos = atomicAdd(cnt, 1);
        list[pos] = i;
    }
}

// ================= k_gather: warp per node; g in fp16, feat in fp32 ============
__global__ void k_gather(const float* __restrict__ feat, const __half* __restrict__ g16,
                         const unsigned* __restrict__ packed,
                         const int* __restrict__ start, const int* __restrict__ deg,
                         float* __restrict__ sum) {
    int w = (blockIdx.x * blockDim.x + threadIdx.x) >> 5;
    int lane = threadIdx.x & 31;
    if (w >= NN) return;
    int s0 = start[w];
    int e = s0 + deg[w];
    float4 acc = make_float4(0.f, 0.f, 0.f, 0.f);
    for (int j = s0; j < e; j++) {
        unsigned v = __ldg(&packed[j]);
        unsigned node = v & 0x7FFFFFFFu;
        if (v >> 31) {
            uint2 hraw = *(const uint2*)(g16 + (size_t)node * 128 + 4 * lane);
            float2 a = __half22float2(*reinterpret_cast<__half2*>(&hraw.x));
            float2 b = __half22float2(*reinterpret_cast<__half2*>(&hraw.y));
            acc.x += a.x; acc.y += a.y; acc.z += b.x; acc.w += b.y;
        } else {
            float4 x = *(const float4*)(feat + (size_t)node * 128 + 4 * lane);
            acc.x += x.x; acc.y += x.y; acc.z += x.z; acc.w += x.w;
        }
    }
    *(float4*)(sum + (size_t)w * 128 + 4 * lane) = acc;
}

// ================= host =================
extern "C" void kernel_launch(void* const* d_in, const int* in_sizes, int n_in,
                              void* d_out, int out_size)
{
    const float* feat = (const float*)d_in[0];
    const int*   src  = (const int*)d_in[1];
    const int*   dst  = (const int*)d_in[2];
    const int*   r    = (const int*)d_in[3];
    const int*   inv  = (const int*)d_in[4];
    const float* iw1 = (const float*)d_in[5];
    const float* ib1 = (const float*)d_in[6];
    const float* iw2 = (const float*)d_in[7];
    const float* ib2 = (const float*)d_in[8];
    const float* iw3 = (const float*)d_in[9];
    const float* ib3 = (const float*)d_in[10];
    const float* aw1 = (const float*)d_in[11];
    const float* ab1 = (const float*)d_in[12];
    const float* aw2 = (const float*)d_in[13];
    const float* ab2 = (const float*)d_in[14];
    const float* aw3 = (const float*)d_in[15];
    const float* ab3 = (const float*)d_in[16];
    float* out = (float*)d_out;

    __half* g16;
    float* sum;
    unsigned* packed;
    int *deg, *start, *cursor, *bsum, *boff, *list, *cnt;
    cudaGetSymbolAddress((void**)&g16, g_g16);
    cudaGetSymbolAddress((void**)&sum, g_sum);
    cudaGetSymbolAddress((void**)&packed, g_packed);
    cudaGetSymbolAddress((void**)&deg, g_deg);
    cudaGetSymbolAddress((void**)&start, g_start);
    cudaGetSymbolAddress((void**)&cursor, g_cursor);
    cudaGetSymbolAddress((void**)&bsum, g_bsum);
    cudaGetSymbolAddress((void**)&boff, g_boff);
    cudaGetSymbolAddress((void**)&list, g_list);
    cudaGetSymbolAddress((void**)&cnt, g_cnt);

    cudaFuncSetAttribute(mlp_mma<0>, cudaFuncAttributeMaxDynamicSharedMemorySize, SMEM_BYTES);
    cudaFuncSetAttribute(mlp_mma<1>, cudaFuncAttributeMaxDynamicSharedMemorySize, SMEM_BYTES);
    cudaFuncSetAttribute(mlp_mma<2>, cudaFuncAttributeMaxDynamicSharedMemorySize, SMEM_BYTES);

    cudaMemsetAsync(deg, 0, NN * sizeof(int));                        // launch 0
    cudaMemsetAsync(cnt, 0, sizeof(int));                             // launch 1

    k_hist<<<(EE + 1023) / 1024, 1024>>>(dst, deg);                   // 2
    k_scanA<<<NBLK_SCAN, 1024>>>(deg, bsum);                          // 3
    k_scanB<<<1, 128>>>(bsum, boff);                                  // 4
    mlp_mma<0><<<148, NTHR, SMEM_BYTES>>>(feat, nullptr, g16,
                                          iw1, ib1, iw2, ib2, iw3, ib3,
                                          nullptr, nullptr, nullptr); // 5  <- ncu -s 5
    k_scanC<<<NBLK_SCAN, 1024>>>(deg, boff, start, cursor);           // 6
    k_fill<<<(EE + 1023) / 1024, 1024>>>(src, dst, r, cursor, packed);// 7
    k_compact<<<NBLK_SCAN, 1024>>>(inv, list, cnt);                   // 8
    k_gather<<<(NN * 32 + 255) / 256, 256>>>(feat, g16, packed, start, deg, sum); // 9
    mlp_mma<1><<<148, NTHR, SMEM_BYTES>>>(sum, out, nullptr,
                                          aw1, ab1, aw2, ab2, aw3, ab3,
                                          deg, nullptr, nullptr);     // 10
    mlp_mma<2><<<148, NTHR, SMEM_BYTES>>>(out, out, nullptr,
                                          iw1, ib1, iw2, ib2, iw3, ib3,
                                          nullptr, list, cnt);        // 11
}